// round 3
// baseline (speedup 1.0000x reference)
#include <cuda_runtime.h>

typedef unsigned long long u64;

#define B_  16
#define V_  16
#define C_  64
#define M_  32
#define CM_ 16
#define D_  128
#define OUT_ 600
#define BV  256
#define BVM 8192

// ---------------- scratch ----------------
__device__ __align__(16) float g_vis[3][BV][D_];
__device__ __align__(16) float g_mon[2][BVM][D_];
__device__ __align__(16) float g_wc[2][D_ * 512];        // gnn combined weights [d][512]
__device__ __align__(16) float g_bias[2][BV][512];       // visit-level gnn bias
__device__ __align__(16) float g_outs[2][BVM][512];      // gnn outputs (relu)
__device__ __align__(16) float g_wihT[5][D_ * 384];      // mgru Wih transposed
__device__ __align__(16) float g_vwihT[4][D_ * 384];     // vgru Wih transposed
__device__ __align__(16) float g_gi[8][BVM][384];        // monitor gi
__device__ __align__(16) float g_seq[10][BV][D_];        // visit-level sequences (8 chan + weight + age)
__device__ __align__(16) float g_vgi[10][BV][384];       // visit gi
__device__ __align__(16) float g_hbuf[10][B_][D_];       // final hidden per run

// ---------------- f32x2 helpers ----------------
__device__ __forceinline__ u64 f2u(float x, float y) {
    u64 r; asm("mov.b64 %0, {%1, %2};" : "=l"(r) : "f"(x), "f"(y)); return r;
}
__device__ __forceinline__ void fma2(u64& c, u64 a, u64 b) {
    asm("fma.rn.f32x2 %0, %1, %2, %0;" : "+l"(c) : "l"(a), "l"(b));
}
__device__ __forceinline__ float sum2(u64 v) {
    float x, y; asm("mov.b64 {%0, %1}, %2;" : "=f"(x), "=f"(y) : "l"(v)); return x + y;
}
__device__ __forceinline__ float sigm_(float x) { return 1.f / (1.f + __expf(-x)); }
__device__ __forceinline__ float tanh_(float x) { float e = __expf(2.f * x); return 1.f - 2.f / (e + 1.f); }

// ---------------- K1: visit sum-pool embeddings ----------------
__global__ void k_vis(const int* __restrict__ cc, const int* __restrict__ cp, const int* __restrict__ cd,
                      const float* __restrict__ ec, const float* __restrict__ ep, const float* __restrict__ ed) {
    int bv = blockIdx.x, ty = blockIdx.y, d = threadIdx.x;
    const int* codes = (ty == 0) ? cc : ((ty == 1) ? cp : cd);
    const float* emb = (ty == 0) ? ec : ((ty == 1) ? ep : ed);
    codes += bv * C_;
    float s = 0.f;
#pragma unroll 8
    for (int c = 0; c < C_; c++) s += emb[codes[c] * D_ + d];
    g_vis[ty][bv][d] = s;
}

// ---------------- K2: monitor pair embeddings ----------------
__global__ void k_mon(const int* __restrict__ li, const int* __restrict__ lv,
                      const int* __restrict__ ii, const int* __restrict__ iv,
                      const float* __restrict__ eli, const float* __restrict__ elv,
                      const float* __restrict__ eii, const float* __restrict__ eiv) {
    int row = blockIdx.x, p = blockIdx.y, d = threadIdx.x;
    const int* ci = ((p == 0) ? li : ii) + row * CM_;
    const int* cv = ((p == 0) ? lv : iv) + row * CM_;
    const float* ei = (p == 0) ? eli : eii;
    const float* ev = (p == 0) ? elv : eiv;
    float s = 0.f;
#pragma unroll
    for (int c = 0; c < CM_; c++) s += ei[ci[c] * D_ + d] * ev[cv[c] * D_ + d];
    g_mon[p][row][d] = s;
}

// ---------------- K3: combined gnn weights  g_wc[p][d][t*128+j] ----------------
__global__ void k_wt(const float* __restrict__ Ws, const float* __restrict__ Wm) {
    int bx = blockIdx.x, p = bx >> 7, d = bx & 127;
    int j5 = threadIdx.x, t = j5 >> 7, j = j5 & 127;
    float v = (t == 0) ? Ws[(p * 4) * 16384 + d * 128 + j]
                       : Wm[(p * 4 + t) * 16384 + d * 128 + j] * (1.f / 3.f);
    g_wc[p][d * 512 + j5] = v;
}

// ---------------- K4: transpose GRU input weights ----------------
__global__ void k_trans(const float* __restrict__ mW, const float* __restrict__ vW) {
    int bx = blockIdx.x, j = threadIdx.x;
    if (bx < 640) {
        int g = bx >> 7, d = bx & 127;
        g_wihT[g][d * 384 + j] = mW[g * 49152 + j * 128 + d];
    } else {
        int g = (bx - 640) >> 7, d = bx & 127;
        g_vwihT[g][d * 384 + j] = vW[g * 49152 + j * 128 + d];
    }
}

// ---------------- K5: visit-level gnn bias ----------------
__global__ void k_bias(const float* __restrict__ Ws, const float* __restrict__ Wm) {
    __shared__ float sv[3][32][128];
    int pt = blockIdx.x, p = pt >> 2, t = pt & 3;
    int bv0 = blockIdx.y * 32, j = threadIdx.x;
    for (int i = j; i < 3 * 32 * 128; i += 128) {
        int ty = i >> 12, c = (i >> 7) & 31, d = i & 127;
        sv[ty][c][d] = g_vis[ty][bv0 + c][d];
    }
    __syncthreads();
    const float* Wsp = Ws + (p * 4 + t) * 16384;
    const float* Wmp = Wm + (p * 4 + t) * 16384;
    float acc[32];
#pragma unroll
    for (int c = 0; c < 32; c++) acc[c] = 0.f;
    for (int d = 0; d < 128; d++) {
        float w2 = Wmp[d * 128 + j] * (1.f / 3.f);
        float w1 = (t == 0) ? 0.f : (Wsp[d * 128 + j] - w2);
#pragma unroll
        for (int c = 0; c < 32; c++) {
            float v0 = sv[0][c][d], v1 = sv[1][c][d], v2 = sv[2][c][d];
            float vs = v0 + v1 + v2;
            float vt = (t == 1) ? v0 : ((t == 2) ? v1 : ((t == 3) ? v2 : 0.f));
            acc[c] = fmaf(w2, vs, fmaf(w1, vt, acc[c]));
        }
    }
    for (int c = 0; c < 32; c++) g_bias[p][bv0 + c][t * 128 + j] = acc[c];
}

// ---------------- K6: scalar features -> g_seq[8+i] ----------------
__global__ void k_xe(const float* __restrict__ w, const float* __restrict__ a,
                     const float* __restrict__ fwW, const float* __restrict__ fwb,
                     const float* __restrict__ faW, const float* __restrict__ fab) {
    int bv = blockIdx.x, i = blockIdx.y, d = threadIdx.x;
    float x = (i == 0) ? w[bv] : a[bv];
    const float* Wp = (i == 0) ? fwW : faW;
    const float* bp = (i == 0) ? fwb : fab;
    g_seq[8 + i][bv][d] = (x != 0.f) ? (x * Wp[d] + bp[d]) : 0.f;
}

// ---------------- GEMM: out[n,j] = act(sum_d A[n,d]*W[d,j] + bias) ----------------
// 64x64 tile, 256 threads, f32x2. mode 1: gnn; mode 2: monitor gi; mode 3: visit gi.
__global__ __launch_bounds__(256) void k_gemm(int mode, const float* __restrict__ bih_all,
                                              const float* __restrict__ vbih_all) {
    __shared__ float As[64 * 66];
    __shared__ float Wsm[64 * 66];
    const float *A, *W, *bias; float* out;
    int lda, K, bshift, relu;
    int n0 = blockIdx.x * 64, j0 = blockIdx.y * 64;
    if (mode == 1) {
        int p = blockIdx.z;
        A = &g_mon[p][0][0]; lda = 128;
        W = g_wc[p]; bias = &g_bias[p][0][0]; bshift = 5; K = 512; relu = 1;
        out = &g_outs[p][0][0];
    } else if (mode == 2) {
        int z = blockIdx.z, p = z >> 2, t = z & 3, g = (t == 0) ? p : (t + 1);
        A = &g_outs[p][0][0] + t * 128; lda = 512;
        W = g_wihT[g]; bias = bih_all + g * 384; bshift = 30; K = 384; relu = 0;
        out = &g_gi[z][0][0];
    } else {
        int run = n0 >> 8;
        int vi = (run < 8) ? (run >> 2) : (run - 6);
        A = &g_seq[0][0][0]; lda = 128;
        W = g_vwihT[vi]; bias = vbih_all + vi * 384; bshift = 30; K = 384; relu = 0;
        out = &g_vgi[0][0][0];
    }
    int tid = threadIdx.x, tx = tid & 15, ty = tid >> 4;
    u64 acc[4][4];
#pragma unroll
    for (int i = 0; i < 4; i++)
#pragma unroll
        for (int j = 0; j < 4; j++) acc[i][j] = 0ull;

    for (int kc = 0; kc < 2; kc++) {
#pragma unroll
        for (int k = 0; k < 4; k++) {
            int f4 = tid + 256 * k;
            int r = f4 >> 4, d4 = f4 & 15;
            float4 v = *(const float4*)(A + (n0 + r) * lda + kc * 64 + d4 * 4);
            float* dst = As + r * 66 + d4 * 4;
            dst[0] = v.x; dst[1] = v.y; dst[2] = v.z; dst[3] = v.w;
        }
#pragma unroll
        for (int k = 0; k < 4; k++) {
            int f4 = tid + 256 * k;
            int dr = f4 >> 4, j4 = f4 & 15;
            float4 v = *(const float4*)(W + (kc * 64 + dr) * K + j0 + j4 * 4);
            Wsm[(j4 * 4 + 0) * 66 + dr] = v.x;
            Wsm[(j4 * 4 + 1) * 66 + dr] = v.y;
            Wsm[(j4 * 4 + 2) * 66 + dr] = v.z;
            Wsm[(j4 * 4 + 3) * 66 + dr] = v.w;
        }
        __syncthreads();
        const u64* A2 = (const u64*)As;
        const u64* W2 = (const u64*)Wsm;
#pragma unroll 8
        for (int d2 = 0; d2 < 32; d2++) {
            u64 a2[4], w2[4];
#pragma unroll
            for (int i = 0; i < 4; i++) a2[i] = A2[(ty + 16 * i) * 33 + d2];
#pragma unroll
            for (int j = 0; j < 4; j++) w2[j] = W2[(tx + 16 * j) * 33 + d2];
#pragma unroll
            for (int i = 0; i < 4; i++)
#pragma unroll
                for (int j = 0; j < 4; j++) fma2(acc[i][j], a2[i], w2[j]);
        }
        __syncthreads();
    }
#pragma unroll
    for (int i = 0; i < 4; i++) {
        int n = n0 + ty + 16 * i;
#pragma unroll
        for (int j = 0; j < 4; j++) {
            int jj = j0 + tx + 16 * j;
            float v = sum2(acc[i][j]) + bias[(n >> bshift) * K + jj];
            if (relu) v = fmaxf(v, 0.f);
            out[n * K + jj] = v;
        }
    }
}

// ---------------- GRU recurrence: 16 sequences/block, Whh in smem ----------------
// mode 0: monitor (grid 128 = 8 chan x 8 groups... actually 8x16), T=32.
// mode 1: visit (grid 10 runs), T=16.
__global__ __launch_bounds__(384, 1) void k_rec(int mode,
                                                const float* __restrict__ mWhh, const float* __restrict__ mbhh,
                                                const float* __restrict__ vWhh, const float* __restrict__ vbhh) {
    extern __shared__ float sm[];
    float* ws = sm;                   // [384][129]
    float* hs = sm + 384 * 129;       // [16][128]
    float* gsm = hs + 16 * 128;       // [16][384]
    int tid = threadIdx.x;

    const float *Whh, *bhh, *gip; float* outp;
    int T, s0;
    if (mode == 0) {
        int chan = blockIdx.x >> 4, sgrp = blockIdx.x & 15;
        int p = chan >> 2, t = chan & 3, g = (t == 0) ? p : (t + 1);
        Whh = mWhh + g * 49152; bhh = mbhh + g * 384;
        gip = &g_gi[chan][0][0]; outp = &g_seq[chan][0][0];
        T = 32; s0 = sgrp * 16;
    } else {
        int run = blockIdx.x;
        int vi = (run < 8) ? (run >> 2) : (run - 6);
        Whh = vWhh + vi * 49152; bhh = vbhh + vi * 384;
        gip = &g_vgi[run][0][0]; outp = &g_hbuf[run][0][0];
        T = 16; s0 = 0;
    }
    for (int i = tid; i < 49152; i += 384) ws[(i >> 7) * 129 + (i & 127)] = Whh[i];
    for (int i = tid; i < 2048; i += 384) hs[i] = 0.f;
    __syncthreads();

    int j = tid;
    float bj = bhh[j];
    const float* wr = ws + j * 129;

    for (int t = 0; t < T; t++) {
        u64 acc[16];
#pragma unroll
        for (int s = 0; s < 16; s++) acc[s] = 0ull;
#pragma unroll 2
        for (int d4 = 0; d4 < 32; d4++) {
            float w0 = wr[4 * d4], w1 = wr[4 * d4 + 1], w2v = wr[4 * d4 + 2], w3 = wr[4 * d4 + 3];
            u64 wlo = f2u(w0, w1), whi = f2u(w2v, w3);
#pragma unroll
            for (int s = 0; s < 16; s++) {
                float4 h = ((const float4*)hs)[s * 32 + d4];
                fma2(acc[s], f2u(h.x, h.y), wlo);
                fma2(acc[s], f2u(h.z, h.w), whi);
            }
        }
#pragma unroll
        for (int s = 0; s < 16; s++) gsm[s * 384 + j] = sum2(acc[s]) + bj;
        __syncthreads();
        for (int idx = tid; idx < 2048; idx += 384) {
            int s = idx >> 7, d = idx & 127;
            int row = (s0 + s) * T + t;
            const float* gr = gip + row * 384;
            float rg = sigm_(gr[d] + gsm[s * 384 + d]);
            float zg = sigm_(gr[128 + d] + gsm[s * 384 + 128 + d]);
            float nn = tanh_(fmaf(rg, gsm[s * 384 + 256 + d], gr[256 + d]));
            hs[idx] = (1.f - zg) * nn + zg * hs[idx];
        }
        __syncthreads();
    }
    for (int idx = tid; idx < 2048; idx += 384) {
        int s = idx >> 7, d = idx & 127;
        outp[(s0 + s) * 128 + d] = hs[idx];
    }
}

// ---------------- head: out = relu(pe) @ W.T + b ----------------
__global__ void k_head(const float* __restrict__ fW, const float* __restrict__ fb,
                       float* __restrict__ out) {
    __shared__ float pe[896];
    int b = blockIdx.x / 10, og0 = (blockIdx.x % 10) * 60;
    int tid = threadIdx.x, lane = tid & 31, wp = tid >> 5;
    const float* H = &g_hbuf[0][0][0];  // [10][16][128]
    for (int i = tid; i < 896; i += 256) {
        int slot = i >> 7, d = i & 127;
        float v;
        if (slot == 0) v = H[0 * 2048 + b * 128 + d];
        else if (slot == 1) v = H[1 * 2048 + b * 128 + d] + H[5 * 2048 + b * 128 + d];
        else if (slot == 2) v = H[2 * 2048 + b * 128 + d] + H[6 * 2048 + b * 128 + d];
        else if (slot == 3) v = H[3 * 2048 + b * 128 + d] + H[7 * 2048 + b * 128 + d];
        else if (slot == 4) v = H[4 * 2048 + b * 128 + d];
        else if (slot == 5) v = H[8 * 2048 + b * 128 + d];
        else v = H[9 * 2048 + b * 128 + d];
        pe[i] = fmaxf(v, 0.f);
    }
    __syncthreads();
    for (int oi = wp; oi < 60; oi += 8) {
        int o = og0 + oi;
        u64 acc = 0ull;
#pragma unroll
        for (int i = 0; i < 7; i++) {
            int k4 = lane + 32 * i;
            float4 w = __ldg((const float4*)(fW + o * 896) + k4);
            float4 x = ((const float4*)pe)[k4];
            fma2(acc, f2u(x.x, x.y), f2u(w.x, w.y));
            fma2(acc, f2u(x.z, x.w), f2u(w.z, w.w));
        }
        float v = sum2(acc);
#pragma unroll
        for (int m = 16; m > 0; m >>= 1) v += __shfl_xor_sync(0xffffffffu, v, m);
        if (lane == 0) out[b * 600 + o] = v + fb[o];
    }
}

// ---------------- launch ----------------
extern "C" void kernel_launch(void* const* d_in, const int* in_sizes, int n_in,
                              void* d_out, int out_size) {
    const int* cc = (const int*)d_in[0];
    const int* cp = (const int*)d_in[1];
    const int* cd = (const int*)d_in[2];
    const int* cli = (const int*)d_in[3];
    const int* clv = (const int*)d_in[4];
    const int* cii = (const int*)d_in[5];
    const int* civ = (const int*)d_in[6];
    const float* wgt = (const float*)d_in[7];
    const float* age = (const float*)d_in[8];
    const float* ec = (const float*)d_in[9];
    const float* ep = (const float*)d_in[10];
    const float* ed = (const float*)d_in[11];
    const float* eli = (const float*)d_in[12];
    const float* elv = (const float*)d_in[13];
    const float* eii = (const float*)d_in[14];
    const float* eiv = (const float*)d_in[15];
    const float* mWih = (const float*)d_in[16];
    const float* mWhh = (const float*)d_in[17];
    const float* mbih = (const float*)d_in[18];
    const float* mbhh = (const float*)d_in[19];
    const float* vWih = (const float*)d_in[20];
    const float* vWhh = (const float*)d_in[21];
    const float* vbih = (const float*)d_in[22];
    const float* vbhh = (const float*)d_in[23];
    const float* gWs = (const float*)d_in[24];
    const float* gWm = (const float*)d_in[25];
    const float* fwW = (const float*)d_in[26];
    const float* fwb = (const float*)d_in[27];
    const float* faW = (const float*)d_in[28];
    const float* fab = (const float*)d_in[29];
    const float* fpW = (const float*)d_in[30];
    const float* fpb = (const float*)d_in[31];
    float* out = (float*)d_out;

    static int attr_set = 0;
    if (!attr_set) {
        cudaFuncSetAttribute(k_rec, cudaFuncAttributeMaxDynamicSharedMemorySize, 230912);
        attr_set = 1;
    }

    k_vis<<<dim3(256, 3), 128>>>(cc, cp, cd, ec, ep, ed);
    k_mon<<<dim3(8192, 2), 128>>>(cli, clv, cii, civ, eli, elv, eii, eiv);
    k_wt<<<256, 512>>>(gWs, gWm);
    k_trans<<<1152, 384>>>(mWih, vWih);
    k_bias<<<dim3(8, 8), 128>>>(gWs, gWm);
    k_xe<<<dim3(256, 2), 128>>>(wgt, age, fwW, fwb, faW, fab);
    k_gemm<<<dim3(128, 8, 2), 256>>>(1, mbih, vbih);
    k_gemm<<<dim3(128, 6, 8), 256>>>(2, mbih, vbih);
    k_rec<<<128, 384, 230912>>>(0, mWhh, mbhh, vWhh, vbhh);
    k_gemm<<<dim3(40, 6, 1), 256>>>(3, mbih, vbih);
    k_rec<<<10, 384, 230912>>>(1, mWhh, mbhh, vWhh, vbhh);
    k_head<<<160, 256>>>(fpW, fpb, out);
}

// round 4
// speedup vs baseline: 1.3292x; 1.3292x over previous
#include <cuda_runtime.h>

typedef unsigned long long u64;

#define B_  16
#define V_  16
#define C_  64
#define M_  32
#define CM_ 16
#define D_  128
#define OUT_ 600
#define BV  256
#define BVM 8192

// ---------------- scratch ----------------
__device__ __align__(16) float g_vis[3][BV][D_];
__device__ __align__(16) float g_mon[2][BVM][D_];
__device__ __align__(16) float g_wc[2][D_ * 512];        // gnn combined weights [d][512]
__device__ __align__(16) float g_bias[2][BV][512];       // visit-level gnn bias
__device__ __align__(16) float g_outs[2][BVM][512];      // gnn outputs (relu)
__device__ __align__(16) float g_gi[8][BVM][384];        // monitor gi
__device__ __align__(16) float g_seq[10][BV][D_];        // visit-level sequences
__device__ __align__(16) float g_vgi[10][BV][384];       // visit gi
__device__ __align__(16) float g_hbuf[10][B_][D_];       // final hidden per run

// ---------------- f32x2 helpers ----------------
__device__ __forceinline__ void fma2(u64& c, u64 a, u64 b) {
    asm("fma.rn.f32x2 %0, %1, %2, %0;" : "+l"(c) : "l"(a), "l"(b));
}
__device__ __forceinline__ float sum2(u64 v) {
    float x, y; asm("mov.b64 {%0, %1}, %2;" : "=f"(x), "=f"(y) : "l"(v)); return x + y;
}
__device__ __forceinline__ float sigm_(float x) { return 1.f / (1.f + __expf(-x)); }
__device__ __forceinline__ float tanh_(float x) { float e = __expf(2.f * x); return 1.f - 2.f / (e + 1.f); }

// ---------------- K1: visit sum-pool embeddings ----------------
__global__ void k_vis(const int* __restrict__ cc, const int* __restrict__ cp, const int* __restrict__ cd,
                      const float* __restrict__ ec, const float* __restrict__ ep, const float* __restrict__ ed) {
    int bv = blockIdx.x, ty = blockIdx.y, d = threadIdx.x;
    const int* codes = (ty == 0) ? cc : ((ty == 1) ? cp : cd);
    const float* emb = (ty == 0) ? ec : ((ty == 1) ? ep : ed);
    codes += bv * C_;
    float s = 0.f;
#pragma unroll 8
    for (int c = 0; c < C_; c++) s += emb[codes[c] * D_ + d];
    g_vis[ty][bv][d] = s;
}

// ---------------- K2: monitor pair embeddings ----------------
__global__ void k_mon(const int* __restrict__ li, const int* __restrict__ lv,
                      const int* __restrict__ ii, const int* __restrict__ iv,
                      const float* __restrict__ eli, const float* __restrict__ elv,
                      const float* __restrict__ eii, const float* __restrict__ eiv) {
    int row = blockIdx.x, p = blockIdx.y, d = threadIdx.x;
    const int* ci = ((p == 0) ? li : ii) + row * CM_;
    const int* cv = ((p == 0) ? lv : iv) + row * CM_;
    const float* ei = (p == 0) ? eli : eii;
    const float* ev = (p == 0) ? elv : eiv;
    float s = 0.f;
#pragma unroll
    for (int c = 0; c < CM_; c++) s += ei[ci[c] * D_ + d] * ev[cv[c] * D_ + d];
    g_mon[p][row][d] = s;
}

// ---------------- K_prep: gnn combined weights + visit bias + scalar feats ----------------
// grid 322 x 512 threads.
//   bx <  256: g_wc build
//   bx <  320: visit-level gnn bias (64 blocks)
//   else     : weight/age features (2 blocks)
__global__ __launch_bounds__(512) void k_prep(const float* __restrict__ Ws, const float* __restrict__ Wm,
                                              const float* __restrict__ w, const float* __restrict__ a,
                                              const float* __restrict__ fwW, const float* __restrict__ fwb,
                                              const float* __restrict__ faW, const float* __restrict__ fab) {
    __shared__ float sv[3][32][128];
    int bx = blockIdx.x, tid = threadIdx.x;
    if (bx < 256) {
        int p = bx >> 7, d = bx & 127;
        int t = tid >> 7, j = tid & 127;
        float v = (t == 0) ? Ws[(p * 4) * 16384 + d * 128 + j]
                           : Wm[(p * 4 + t) * 16384 + d * 128 + j] * (1.f / 3.f);
        g_wc[p][d * 512 + tid] = v;
    } else if (bx < 320) {
        int blk = bx - 256;
        int pt = blk >> 3, p = pt >> 2, t = pt & 3;
        int bv0 = (blk & 7) * 32;
        for (int i = tid; i < 3 * 32 * 128; i += 512) {
            int ty = i >> 12, c = (i >> 7) & 31, d = i & 127;
            sv[ty][c][d] = g_vis[ty][bv0 + c][d];
        }
        __syncthreads();
        if (tid < 128) {
            int j = tid;
            const float* Wsp = Ws + (p * 4 + t) * 16384;
            const float* Wmp = Wm + (p * 4 + t) * 16384;
            float acc[32];
#pragma unroll
            for (int c = 0; c < 32; c++) acc[c] = 0.f;
            for (int d = 0; d < 128; d++) {
                float w2 = Wmp[d * 128 + j] * (1.f / 3.f);
                float w1 = (t == 0) ? 0.f : (Wsp[d * 128 + j] - w2);
#pragma unroll
                for (int c = 0; c < 32; c++) {
                    float v0 = sv[0][c][d], v1 = sv[1][c][d], v2 = sv[2][c][d];
                    float vs = v0 + v1 + v2;
                    float vt = (t == 1) ? v0 : ((t == 2) ? v1 : ((t == 3) ? v2 : 0.f));
                    acc[c] = fmaf(w2, vs, fmaf(w1, vt, acc[c]));
                }
            }
            for (int c = 0; c < 32; c++) g_bias[p][bv0 + c][t * 128 + j] = acc[c];
        }
    } else {
        int i = bx - 320;
        const float* Wp = (i == 0) ? fwW : faW;
        const float* bp = (i == 0) ? fwb : fab;
        const float* xp = (i == 0) ? w : a;
        for (int idx = tid; idx < 32768; idx += 512) {
            int bv = idx >> 7, d = idx & 127;
            float x = xp[bv];
            g_seq[8 + i][bv][d] = (x != 0.f) ? (x * Wp[d] + bp[d]) : 0.f;
        }
    }
}

// ---------------- GEMM: out[n,j] = act(sum_d A[n,d]*W[.,.] + bias) ----------------
// 64x64 tile, 256 threads, f32x2.
// mode 1: gnn (W [d][512] col layout); mode 2: monitor gi (W row-major [j][128]);
// mode 3: visit gi (W row-major [j][128]).
__global__ __launch_bounds__(256) void k_gemm(int mode,
                                              const float* __restrict__ mWih, const float* __restrict__ vWih,
                                              const float* __restrict__ bih_all, const float* __restrict__ vbih_all) {
    __shared__ float As[64 * 66];
    __shared__ float Wsm[64 * 66];
    const float *A, *W, *bias; float* out;
    int lda, K, bshift, relu, wrow;
    int n0 = blockIdx.x * 64, j0 = blockIdx.y * 64;
    if (mode == 1) {
        int p = blockIdx.z;
        A = &g_mon[p][0][0]; lda = 128;
        W = g_wc[p]; wrow = 0; bias = &g_bias[p][0][0]; bshift = 5; K = 512; relu = 1;
        out = &g_outs[p][0][0];
    } else if (mode == 2) {
        int z = blockIdx.z, p = z >> 2, t = z & 3, g = (t == 0) ? p : (t + 1);
        A = &g_outs[p][0][0] + t * 128; lda = 512;
        W = mWih + g * 49152; wrow = 1; bias = bih_all + g * 384; bshift = 30; K = 384; relu = 0;
        out = &g_gi[z][0][0];
    } else {
        int run = n0 >> 8;
        int vi = (run < 8) ? (run >> 2) : (run - 6);
        A = &g_seq[0][0][0]; lda = 128;
        W = vWih + vi * 49152; wrow = 1; bias = vbih_all + vi * 384; bshift = 30; K = 384; relu = 0;
        out = &g_vgi[0][0][0];
    }
    int tid = threadIdx.x, tx = tid & 15, ty = tid >> 4;
    u64 acc[4][4];
#pragma unroll
    for (int i = 0; i < 4; i++)
#pragma unroll
        for (int j = 0; j < 4; j++) acc[i][j] = 0ull;

    for (int kc = 0; kc < 2; kc++) {
#pragma unroll
        for (int k = 0; k < 4; k++) {
            int f4 = tid + 256 * k;
            int r = f4 >> 4, d4 = f4 & 15;
            float4 v = *(const float4*)(A + (n0 + r) * lda + kc * 64 + d4 * 4);
            float* dst = As + r * 66 + d4 * 4;
            dst[0] = v.x; dst[1] = v.y; dst[2] = v.z; dst[3] = v.w;
        }
        if (wrow) {
#pragma unroll
            for (int k = 0; k < 4; k++) {
                int f4 = tid + 256 * k;
                int r = f4 >> 4, d4 = f4 & 15;
                float4 v = *(const float4*)(W + (j0 + r) * 128 + kc * 64 + d4 * 4);
                float* dst = Wsm + r * 66 + d4 * 4;
                dst[0] = v.x; dst[1] = v.y; dst[2] = v.z; dst[3] = v.w;
            }
        } else {
#pragma unroll
            for (int k = 0; k < 4; k++) {
                int f4 = tid + 256 * k;
                int dr = f4 >> 4, j4 = f4 & 15;
                float4 v = *(const float4*)(W + (kc * 64 + dr) * K + j0 + j4 * 4);
                Wsm[(j4 * 4 + 0) * 66 + dr] = v.x;
                Wsm[(j4 * 4 + 1) * 66 + dr] = v.y;
                Wsm[(j4 * 4 + 2) * 66 + dr] = v.z;
                Wsm[(j4 * 4 + 3) * 66 + dr] = v.w;
            }
        }
        __syncthreads();
        const u64* A2 = (const u64*)As;
        const u64* W2 = (const u64*)Wsm;
#pragma unroll 8
        for (int d2 = 0; d2 < 32; d2++) {
            u64 a2[4], w2[4];
#pragma unroll
            for (int i = 0; i < 4; i++) a2[i] = A2[(ty + 16 * i) * 33 + d2];
#pragma unroll
            for (int j = 0; j < 4; j++) w2[j] = W2[(tx + 16 * j) * 33 + d2];
#pragma unroll
            for (int i = 0; i < 4; i++)
#pragma unroll
                for (int j = 0; j < 4; j++) fma2(acc[i][j], a2[i], w2[j]);
        }
        __syncthreads();
    }
#pragma unroll
    for (int i = 0; i < 4; i++) {
        int n = n0 + ty + 16 * i;
#pragma unroll
        for (int j = 0; j < 4; j++) {
            int jj = j0 + tx + 16 * j;
            float v = sum2(acc[i][j]) + bias[(n >> bshift) * K + jj];
            if (relu) v = fmaxf(v, 0.f);
            out[n * K + jj] = v;
        }
    }
}

// ---------------- GRU recurrence: 16 sequences/block ----------------
// Whh in smem, transposed + pre-paired: ws2[d2][j] = (W[j][2d2], W[j][2d2+1]) as u64.
// mode 0: monitor (grid 128 = 8 chan x 16 groups), T=32.
// mode 1: visit   (grid 10 runs), T=16.
__global__ __launch_bounds__(384, 1) void k_rec(int mode,
                                                const float* __restrict__ mWhh, const float* __restrict__ mbhh,
                                                const float* __restrict__ vWhh, const float* __restrict__ vbhh) {
    extern __shared__ float sm[];
    float* wsf = sm;                  // 64*384 u64 = 49152 floats
    float* hs = sm + 49152;           // [16][128]
    float* gsm = hs + 2048;           // [16][384]
    const u64* ws2 = (const u64*)sm;
    int tid = threadIdx.x;

    const float *Whh, *bhh, *gip; float* outp;
    int T, s0;
    if (mode == 0) {
        int chan = blockIdx.x >> 4, sgrp = blockIdx.x & 15;
        int p = chan >> 2, t = chan & 3, g = (t == 0) ? p : (t + 1);
        Whh = mWhh + g * 49152; bhh = mbhh + g * 384;
        gip = &g_gi[chan][0][0]; outp = &g_seq[chan][0][0];
        T = 32; s0 = sgrp * 16;
    } else {
        int run = blockIdx.x;
        int vi = (run < 8) ? (run >> 2) : (run - 6);
        Whh = vWhh + vi * 49152; bhh = vbhh + vi * 384;
        gip = &g_vgi[run][0][0]; outp = &g_hbuf[run][0][0];
        T = 16; s0 = 0;
    }
    // build transposed pair layout: wsf[d2*768 + 2j + lo] = Whh[j*128 + 2d2 + lo]
    for (int i = tid; i < 49152; i += 384) {
        int j = i >> 7, d = i & 127;
        wsf[(d >> 1) * 768 + 2 * j + (d & 1)] = Whh[i];
    }
    for (int i = tid; i < 2048; i += 384) hs[i] = 0.f;
    __syncthreads();

    int j = tid;
    float bj = bhh[j];

    for (int t = 0; t < T; t++) {
        // prefetch gi for the gate phase (gmem, overlaps dot phase)
        float pr[6], pz[6], pn[6];
#pragma unroll
        for (int k = 0; k < 6; k++) {
            int idx = tid + k * 384;
            if (idx < 2048) {
                int s = idx >> 7, d = idx & 127;
                const float* gr = gip + ((s0 + s) * T + t) * 384;
                pr[k] = gr[d]; pz[k] = gr[128 + d]; pn[k] = gr[256 + d];
            }
        }
        // dot phase: gate_j = sum_d h[s][d] * Whh[j][d]
        u64 acc[16];
#pragma unroll
        for (int s = 0; s < 16; s++) acc[s] = 0ull;
#pragma unroll 2
        for (int d4 = 0; d4 < 32; d4++) {
            u64 wA = ws2[(2 * d4) * 384 + j];
            u64 wB = ws2[(2 * d4 + 1) * 384 + j];
#pragma unroll
            for (int s = 0; s < 16; s++) {
                double2 hd = ((const double2*)(hs + s * 128))[d4];
                fma2(acc[s], __double_as_longlong(hd.x), wA);
                fma2(acc[s], __double_as_longlong(hd.y), wB);
            }
        }
#pragma unroll
        for (int s = 0; s < 16; s++) gsm[s * 384 + j] = sum2(acc[s]) + bj;
        __syncthreads();
        // gate phase
#pragma unroll
        for (int k = 0; k < 6; k++) {
            int idx = tid + k * 384;
            if (idx < 2048) {
                int s = idx >> 7, d = idx & 127;
                float rg = sigm_(pr[k] + gsm[s * 384 + d]);
                float zg = sigm_(pz[k] + gsm[s * 384 + 128 + d]);
                float nn = tanh_(fmaf(rg, gsm[s * 384 + 256 + d], pn[k]));
                hs[idx] = (1.f - zg) * nn + zg * hs[idx];
            }
        }
        __syncthreads();
    }
    for (int idx = tid; idx < 2048; idx += 384) {
        int s = idx >> 7, d = idx & 127;
        outp[(s0 + s) * 128 + d] = hs[idx];
    }
}

// ---------------- head: out = relu(pe) @ W.T + b ----------------
__global__ void k_head(const float* __restrict__ fW, const float* __restrict__ fb,
                       float* __restrict__ out) {
    __shared__ float pe[896];
    int b = blockIdx.x / 10, og0 = (blockIdx.x % 10) * 60;
    int tid = threadIdx.x, lane = tid & 31, wp = tid >> 5;
    const float* H = &g_hbuf[0][0][0];  // [10][16][128]
    for (int i = tid; i < 896; i += 256) {
        int slot = i >> 7, d = i & 127;
        float v;
        if (slot == 0) v = H[0 * 2048 + b * 128 + d];
        else if (slot == 1) v = H[1 * 2048 + b * 128 + d] + H[5 * 2048 + b * 128 + d];
        else if (slot == 2) v = H[2 * 2048 + b * 128 + d] + H[6 * 2048 + b * 128 + d];
        else if (slot == 3) v = H[3 * 2048 + b * 128 + d] + H[7 * 2048 + b * 128 + d];
        else if (slot == 4) v = H[4 * 2048 + b * 128 + d];
        else if (slot == 5) v = H[8 * 2048 + b * 128 + d];
        else v = H[9 * 2048 + b * 128 + d];
        pe[i] = fmaxf(v, 0.f);
    }
    __syncthreads();
    for (int oi = wp; oi < 60; oi += 8) {
        int o = og0 + oi;
        u64 acc = 0ull;
#pragma unroll
        for (int i = 0; i < 7; i++) {
            int k4 = lane + 32 * i;
            float4 wv = __ldg((const float4*)(fW + o * 896) + k4);
            double2 xv = ((const double2*)pe)[k4 * 2 / 2];
            float2 x01 = make_float2(((const float*)pe)[k4 * 4], ((const float*)pe)[k4 * 4 + 1]);
            float2 x23 = make_float2(((const float*)pe)[k4 * 4 + 2], ((const float*)pe)[k4 * 4 + 3]);
            (void)xv;
            u64 a01, a23, w01, w23;
            asm("mov.b64 %0, {%1, %2};" : "=l"(a01) : "f"(x01.x), "f"(x01.y));
            asm("mov.b64 %0, {%1, %2};" : "=l"(a23) : "f"(x23.x), "f"(x23.y));
            asm("mov.b64 %0, {%1, %2};" : "=l"(w01) : "f"(wv.x), "f"(wv.y));
            asm("mov.b64 %0, {%1, %2};" : "=l"(w23) : "f"(wv.z), "f"(wv.w));
            fma2(acc, a01, w01);
            fma2(acc, a23, w23);
        }
        float v = sum2(acc);
#pragma unroll
        for (int m = 16; m > 0; m >>= 1) v += __shfl_xor_sync(0xffffffffu, v, m);
        if (lane == 0) out[b * 600 + o] = v + fb[o];
    }
}

// ---------------- launch ----------------
extern "C" void kernel_launch(void* const* d_in, const int* in_sizes, int n_in,
                              void* d_out, int out_size) {
    const int* cc = (const int*)d_in[0];
    const int* cp = (const int*)d_in[1];
    const int* cd = (const int*)d_in[2];
    const int* cli = (const int*)d_in[3];
    const int* clv = (const int*)d_in[4];
    const int* cii = (const int*)d_in[5];
    const int* civ = (const int*)d_in[6];
    const float* wgt = (const float*)d_in[7];
    const float* age = (const float*)d_in[8];
    const float* ec = (const float*)d_in[9];
    const float* ep = (const float*)d_in[10];
    const float* ed = (const float*)d_in[11];
    const float* eli = (const float*)d_in[12];
    const float* elv = (const float*)d_in[13];
    const float* eii = (const float*)d_in[14];
    const float* eiv = (const float*)d_in[15];
    const float* mWih = (const float*)d_in[16];
    const float* mWhh = (const float*)d_in[17];
    const float* mbih = (const float*)d_in[18];
    const float* mbhh = (const float*)d_in[19];
    const float* vWih = (const float*)d_in[20];
    const float* vWhh = (const float*)d_in[21];
    const float* vbih = (const float*)d_in[22];
    const float* vbhh = (const float*)d_in[23];
    const float* gWs = (const float*)d_in[24];
    const float* gWm = (const float*)d_in[25];
    const float* fwW = (const float*)d_in[26];
    const float* fwb = (const float*)d_in[27];
    const float* faW = (const float*)d_in[28];
    const float* fab = (const float*)d_in[29];
    const float* fpW = (const float*)d_in[30];
    const float* fpb = (const float*)d_in[31];
    float* out = (float*)d_out;

    cudaFuncSetAttribute(k_rec, cudaFuncAttributeMaxDynamicSharedMemorySize, 229376);

    k_vis<<<dim3(256, 3), 128>>>(cc, cp, cd, ec, ep, ed);
    k_mon<<<dim3(8192, 2), 128>>>(cli, clv, cii, civ, eli, elv, eii, eiv);
    k_prep<<<322, 512>>>(gWs, gWm, wgt, age, fwW, fwb, faW, fab);
    k_gemm<<<dim3(128, 8, 2), 256>>>(1, mWih, vWih, mbih, vbih);
    k_gemm<<<dim3(128, 6, 8), 256>>>(2, mWih, vWih, mbih, vbih);
    k_rec<<<128, 384, 229376>>>(0, mWhh, mbhh, vWhh, vbhh);
    k_gemm<<<dim3(40, 6, 1), 256>>>(3, mWih, vWih, mbih, vbih);
    k_rec<<<10, 384, 229376>>>(1, mWhh, mbhh, vWhh, vbhh);
    k_head<<<160, 256>>>(fpW, fpb, out);
}

// round 5
// speedup vs baseline: 1.4924x; 1.1228x over previous
#include <cuda_runtime.h>

typedef unsigned long long u64;

#define B_  16
#define V_  16
#define C_  64
#define M_  32
#define CM_ 16
#define D_  128
#define OUT_ 600
#define BV  256
#define BVM 8192

// ---------------- scratch ----------------
__device__ __align__(16) float g_vis[3][BV][D_];
__device__ __align__(16) float g_mon[2][BVM][D_];
__device__ __align__(16) float g_wc[2][D_ * 512];        // gnn combined weights [d][512]
__device__ __align__(16) float g_bias[2][BV][512];       // visit-level gnn bias
__device__ __align__(16) float g_outs[2][BVM][512];      // gnn outputs (relu)
__device__ __align__(16) float g_gi[8][BVM][384];        // monitor gi
__device__ __align__(16) float g_seq[10][BV][D_];        // visit-level sequences
__device__ __align__(16) float g_vgi[10][BV][384];       // visit gi
__device__ __align__(16) float g_hbuf[10][B_][D_];       // final hidden per run

// ---------------- f32x2 helpers ----------------
__device__ __forceinline__ void fma2(u64& c, u64 a, u64 b) {
    asm("fma.rn.f32x2 %0, %1, %2, %0;" : "+l"(c) : "l"(a), "l"(b));
}
__device__ __forceinline__ float sum2(u64 v) {
    float x, y; asm("mov.b64 {%0, %1}, %2;" : "=f"(x), "=f"(y) : "l"(v)); return x + y;
}
__device__ __forceinline__ float sigm_(float x) { return 1.f / (1.f + __expf(-x)); }
__device__ __forceinline__ float tanh_(float x) { float e = __expf(2.f * x); return 1.f - 2.f / (e + 1.f); }

// ---------------- K_pre: all gathers + weight prep + scalar feats ----------------
// bx <   768 : visit sum-pool embeddings
// bx < 17152 : monitor pair embeddings
// bx < 18176 : gnn combined weight build
// else (2)   : weight/age features
__global__ __launch_bounds__(128) void k_pre(
    const int* __restrict__ cc, const int* __restrict__ cp, const int* __restrict__ cd,
    const float* __restrict__ ec, const float* __restrict__ ep, const float* __restrict__ ed,
    const int* __restrict__ li, const int* __restrict__ lv,
    const int* __restrict__ ii, const int* __restrict__ iv,
    const float* __restrict__ eli, const float* __restrict__ elv,
    const float* __restrict__ eii, const float* __restrict__ eiv,
    const float* __restrict__ Ws, const float* __restrict__ Wm,
    const float* __restrict__ w, const float* __restrict__ a,
    const float* __restrict__ fwW, const float* __restrict__ fwb,
    const float* __restrict__ faW, const float* __restrict__ fab) {
    int bx = blockIdx.x, tid = threadIdx.x;
    if (bx < 768) {
        int bv = bx & 255, ty = bx >> 8, d = tid;
        const int* codes = ((ty == 0) ? cc : ((ty == 1) ? cp : cd)) + bv * C_;
        const float* emb = (ty == 0) ? ec : ((ty == 1) ? ep : ed);
        float s = 0.f;
#pragma unroll 8
        for (int c = 0; c < C_; c++) s += emb[codes[c] * D_ + d];
        g_vis[ty][bv][d] = s;
    } else if (bx < 17152) {
        int i = bx - 768, p = i >> 13, row = i & 8191, d = tid;
        const int* ci = ((p == 0) ? li : ii) + row * CM_;
        const int* cv = ((p == 0) ? lv : iv) + row * CM_;
        const float* ei = (p == 0) ? eli : eii;
        const float* ev = (p == 0) ? elv : eiv;
        float s = 0.f;
#pragma unroll
        for (int c = 0; c < CM_; c++) s += ei[ci[c] * D_ + d] * ev[cv[c] * D_ + d];
        g_mon[p][row][d] = s;
    } else if (bx < 18176) {
        int i = (bx - 17152) * 128 + tid;
        int p = i >> 16, d = (i >> 9) & 127, j5 = i & 511;
        int t = j5 >> 7, j = j5 & 127;
        float v = (t == 0) ? Ws[(p * 4) * 16384 + d * 128 + j]
                           : Wm[(p * 4 + t) * 16384 + d * 128 + j] * (1.f / 3.f);
        g_wc[p][d * 512 + j5] = v;
    } else {
        int i = bx - 18176;
        const float* Wp = (i == 0) ? fwW : faW;
        const float* bp = (i == 0) ? fwb : fab;
        const float* xp = (i == 0) ? w : a;
        for (int idx = tid; idx < 32768; idx += 128) {
            int bv = idx >> 7, d = idx & 127;
            float x = xp[bv];
            g_seq[8 + i][bv][d] = (x != 0.f) ? (x * Wp[d] + bp[d]) : 0.f;
        }
    }
}

// ---------------- K_bias: visit-level gnn bias ----------------
__global__ __launch_bounds__(128) void k_bias(const float* __restrict__ Ws, const float* __restrict__ Wm) {
    __shared__ float sv[3][32][128];
    int blk = blockIdx.x, tid = threadIdx.x;
    int pt = blk >> 3, p = pt >> 2, t = pt & 3;
    int bv0 = (blk & 7) * 32;
    for (int i = tid; i < 3 * 32 * 128; i += 128) {
        int ty = i >> 12, c = (i >> 7) & 31, d = i & 127;
        sv[ty][c][d] = g_vis[ty][bv0 + c][d];
    }
    __syncthreads();
    int j = tid;
    const float* Wsp = Ws + (p * 4 + t) * 16384;
    const float* Wmp = Wm + (p * 4 + t) * 16384;
    float acc[32];
#pragma unroll
    for (int c = 0; c < 32; c++) acc[c] = 0.f;
    for (int d = 0; d < 128; d++) {
        float w2 = Wmp[d * 128 + j] * (1.f / 3.f);
        float w1 = (t == 0) ? 0.f : (Wsp[d * 128 + j] - w2);
#pragma unroll
        for (int c = 0; c < 32; c++) {
            float v0 = sv[0][c][d], v1 = sv[1][c][d], v2 = sv[2][c][d];
            float vs = v0 + v1 + v2;
            float vt = (t == 1) ? v0 : ((t == 2) ? v1 : ((t == 3) ? v2 : 0.f));
            acc[c] = fmaf(w2, vs, fmaf(w1, vt, acc[c]));
        }
    }
    for (int c = 0; c < 32; c++) g_bias[p][bv0 + c][t * 128 + j] = acc[c];
}

// ---------------- GEMM: 128x64 block tile, 8x4 register tile, f32x2 ----------------
// mode 1: gnn (W [d][512] col layout); mode 2: monitor gi; mode 3: visit gi (both row-major [j][128]).
__global__ __launch_bounds__(256, 2) void k_gemm(int mode,
                                                 const float* __restrict__ mWih, const float* __restrict__ vWih,
                                                 const float* __restrict__ bih_all, const float* __restrict__ vbih_all) {
    __shared__ float As[128 * 66];
    __shared__ float Wsm[64 * 66];
    const float *A, *W, *bias; float* out;
    int lda, K, bshift, relu, wrow;
    int n0 = blockIdx.x * 128, j0 = blockIdx.y * 64;
    if (mode == 1) {
        int p = blockIdx.z;
        A = &g_mon[p][0][0]; lda = 128;
        W = g_wc[p]; wrow = 0; bias = &g_bias[p][0][0]; bshift = 5; K = 512; relu = 1;
        out = &g_outs[p][0][0];
    } else if (mode == 2) {
        int z = blockIdx.z, p = z >> 2, t = z & 3, g = (t == 0) ? p : (t + 1);
        A = &g_outs[p][0][0] + t * 128; lda = 512;
        W = mWih + g * 49152; wrow = 1; bias = bih_all + g * 384; bshift = 30; K = 384; relu = 0;
        out = &g_gi[z][0][0];
    } else {
        int run = n0 >> 8;
        int vi = (run < 8) ? (run >> 2) : (run - 6);
        A = &g_seq[0][0][0]; lda = 128;
        W = vWih + vi * 49152; wrow = 1; bias = vbih_all + vi * 384; bshift = 30; K = 384; relu = 0;
        out = &g_vgi[0][0][0];
    }
    int tid = threadIdx.x, tx = tid & 15, ty = tid >> 4;
    u64 acc[8][4];
#pragma unroll
    for (int i = 0; i < 8; i++)
#pragma unroll
        for (int j = 0; j < 4; j++) acc[i][j] = 0ull;

    for (int kc = 0; kc < 2; kc++) {
#pragma unroll
        for (int k = 0; k < 8; k++) {
            int f4 = tid + 256 * k;
            int r = f4 >> 4, d4 = f4 & 15;
            float4 v = *(const float4*)(A + (n0 + r) * lda + kc * 64 + d4 * 4);
            float* dst = As + r * 66 + d4 * 4;
            dst[0] = v.x; dst[1] = v.y; dst[2] = v.z; dst[3] = v.w;
        }
        if (wrow) {
#pragma unroll
            for (int k = 0; k < 4; k++) {
                int f4 = tid + 256 * k;
                int r = f4 >> 4, d4 = f4 & 15;
                float4 v = *(const float4*)(W + (j0 + r) * 128 + kc * 64 + d4 * 4);
                float* dst = Wsm + r * 66 + d4 * 4;
                dst[0] = v.x; dst[1] = v.y; dst[2] = v.z; dst[3] = v.w;
            }
        } else {
#pragma unroll
            for (int k = 0; k < 4; k++) {
                int f4 = tid + 256 * k;
                int dr = f4 >> 4, j4 = f4 & 15;
                float4 v = *(const float4*)(W + (kc * 64 + dr) * K + j0 + j4 * 4);
                Wsm[(j4 * 4 + 0) * 66 + dr] = v.x;
                Wsm[(j4 * 4 + 1) * 66 + dr] = v.y;
                Wsm[(j4 * 4 + 2) * 66 + dr] = v.z;
                Wsm[(j4 * 4 + 3) * 66 + dr] = v.w;
            }
        }
        __syncthreads();
        const u64* A2 = (const u64*)As;
        const u64* W2 = (const u64*)Wsm;
#pragma unroll 4
        for (int d2 = 0; d2 < 32; d2++) {
            u64 a2[8], w2[4];
#pragma unroll
            for (int j = 0; j < 4; j++) w2[j] = W2[(tx + 16 * j) * 33 + d2];
#pragma unroll
            for (int i = 0; i < 8; i++) a2[i] = A2[(ty + 16 * i) * 33 + d2];
#pragma unroll
            for (int i = 0; i < 8; i++)
#pragma unroll
                for (int j = 0; j < 4; j++) fma2(acc[i][j], a2[i], w2[j]);
        }
        __syncthreads();
    }
#pragma unroll
    for (int i = 0; i < 8; i++) {
        int n = n0 + ty + 16 * i;
#pragma unroll
        for (int j = 0; j < 4; j++) {
            int jj = j0 + tx + 16 * j;
            float v = sum2(acc[i][j]) + bias[(n >> bshift) * K + jj];
            if (relu) v = fmaxf(v, 0.f);
            out[n * K + jj] = v;
        }
    }
}

// ---------------- GRU recurrence (templated on seqs/block) ----------------
// Whh in smem, transposed + pre-paired u64: ws2[d2][j].
// MON: grid 128 = 8 chan x 16 groups of 16 seqs, T=32.
// else: grid 40 = 10 runs x 4 groups of 4 seqs, T=16.
template <int NSEQ, int T, bool MON>
__global__ __launch_bounds__(384, 1) void k_rec(const float* __restrict__ Whh_all,
                                                const float* __restrict__ bhh_all) {
    extern __shared__ float sm[];
    float* wsf = sm;                     // 64*384 u64 = 49152 floats
    float* hs = sm + 49152;              // [NSEQ][128]
    float* gsm = hs + NSEQ * 128;        // [NSEQ][384]
    const u64* ws2 = (const u64*)sm;
    int tid = threadIdx.x, bx = blockIdx.x;

    const float *Whh, *bhh, *gip; float* outp;
    int s0;
    if (MON) {
        int chan = bx >> 4, sgrp = bx & 15;
        int p = chan >> 2, t = chan & 3, g = (t == 0) ? p : (t + 1);
        Whh = Whh_all + g * 49152; bhh = bhh_all + g * 384;
        gip = &g_gi[chan][0][0]; outp = &g_seq[chan][0][0];
        s0 = sgrp * NSEQ;
    } else {
        int run = bx >> 2, sgrp = bx & 3;
        int vi = (run < 8) ? (run >> 2) : (run - 6);
        Whh = Whh_all + vi * 49152; bhh = bhh_all + vi * 384;
        gip = &g_vgi[run][0][0]; outp = &g_hbuf[run][0][0];
        s0 = sgrp * NSEQ;
    }
    for (int i = tid; i < 49152; i += 384) {
        int j = i >> 7, d = i & 127;
        wsf[(d >> 1) * 768 + 2 * j + (d & 1)] = Whh[i];
    }
    for (int i = tid; i < NSEQ * 128; i += 384) hs[i] = 0.f;
    __syncthreads();

    int j = tid;
    float bj = bhh[j];
    constexpr int KP = (NSEQ * 128 + 383) / 384;

    for (int t = 0; t < T; t++) {
        float pr[KP], pz[KP], pn[KP];
#pragma unroll
        for (int k = 0; k < KP; k++) {
            int idx = tid + k * 384;
            if (idx < NSEQ * 128) {
                int s = idx >> 7, d = idx & 127;
                const float* gr = gip + ((s0 + s) * T + t) * 384;
                pr[k] = gr[d]; pz[k] = gr[128 + d]; pn[k] = gr[256 + d];
            }
        }
        u64 acc[NSEQ];
#pragma unroll
        for (int s = 0; s < NSEQ; s++) acc[s] = 0ull;
#pragma unroll 2
        for (int d4 = 0; d4 < 32; d4++) {
            u64 wA = ws2[(2 * d4) * 384 + j];
            u64 wB = ws2[(2 * d4 + 1) * 384 + j];
#pragma unroll
            for (int s = 0; s < NSEQ; s++) {
                double2 hd = ((const double2*)(hs + s * 128))[d4];
                fma2(acc[s], __double_as_longlong(hd.x), wA);
                fma2(acc[s], __double_as_longlong(hd.y), wB);
            }
        }
#pragma unroll
        for (int s = 0; s < NSEQ; s++) gsm[s * 384 + j] = sum2(acc[s]) + bj;
        __syncthreads();
#pragma unroll
        for (int k = 0; k < KP; k++) {
            int idx = tid + k * 384;
            if (idx < NSEQ * 128) {
                int s = idx >> 7, d = idx & 127;
                float rg = sigm_(pr[k] + gsm[s * 384 + d]);
                float zg = sigm_(pz[k] + gsm[s * 384 + 128 + d]);
                float nn = tanh_(fmaf(rg, gsm[s * 384 + 256 + d], pn[k]));
                hs[idx] = (1.f - zg) * nn + zg * hs[idx];
            }
        }
        __syncthreads();
    }
    for (int idx = tid; idx < NSEQ * 128; idx += 384) {
        int s = idx >> 7, d = idx & 127;
        outp[(s0 + s) * 128 + d] = hs[idx];
    }
}

// ---------------- head: out = relu(pe) @ W.T + b ----------------
__global__ void k_head(const float* __restrict__ fW, const float* __restrict__ fb,
                       float* __restrict__ out) {
    __shared__ float pe[896];
    int b = blockIdx.x / 10, og0 = (blockIdx.x % 10) * 60;
    int tid = threadIdx.x, lane = tid & 31, wp = tid >> 5;
    const float* H = &g_hbuf[0][0][0];  // [10][16][128]
    for (int i = tid; i < 896; i += 256) {
        int slot = i >> 7, d = i & 127;
        float v;
        if (slot == 0) v = H[0 * 2048 + b * 128 + d];
        else if (slot == 1) v = H[1 * 2048 + b * 128 + d] + H[5 * 2048 + b * 128 + d];
        else if (slot == 2) v = H[2 * 2048 + b * 128 + d] + H[6 * 2048 + b * 128 + d];
        else if (slot == 3) v = H[3 * 2048 + b * 128 + d] + H[7 * 2048 + b * 128 + d];
        else if (slot == 4) v = H[4 * 2048 + b * 128 + d];
        else if (slot == 5) v = H[8 * 2048 + b * 128 + d];
        else v = H[9 * 2048 + b * 128 + d];
        pe[i] = fmaxf(v, 0.f);
    }
    __syncthreads();
    for (int oi = wp; oi < 60; oi += 8) {
        int o = og0 + oi;
        u64 acc = 0ull;
#pragma unroll
        for (int i = 0; i < 7; i++) {
            int k4 = lane + 32 * i;
            float4 wv = __ldg((const float4*)(fW + o * 896) + k4);
            float4 xv = ((const float4*)pe)[k4];
            u64 a01, a23, w01, w23;
            asm("mov.b64 %0, {%1, %2};" : "=l"(a01) : "f"(xv.x), "f"(xv.y));
            asm("mov.b64 %0, {%1, %2};" : "=l"(a23) : "f"(xv.z), "f"(xv.w));
            asm("mov.b64 %0, {%1, %2};" : "=l"(w01) : "f"(wv.x), "f"(wv.y));
            asm("mov.b64 %0, {%1, %2};" : "=l"(w23) : "f"(wv.z), "f"(wv.w));
            fma2(acc, a01, w01);
            fma2(acc, a23, w23);
        }
        float v = sum2(acc);
#pragma unroll
        for (int m = 16; m > 0; m >>= 1) v += __shfl_xor_sync(0xffffffffu, v, m);
        if (lane == 0) out[b * 600 + o] = v + fb[o];
    }
}

// ---------------- launch ----------------
extern "C" void kernel_launch(void* const* d_in, const int* in_sizes, int n_in,
                              void* d_out, int out_size) {
    const int* cc = (const int*)d_in[0];
    const int* cp = (const int*)d_in[1];
    const int* cd = (const int*)d_in[2];
    const int* cli = (const int*)d_in[3];
    const int* clv = (const int*)d_in[4];
    const int* cii = (const int*)d_in[5];
    const int* civ = (const int*)d_in[6];
    const float* wgt = (const float*)d_in[7];
    const float* age = (const float*)d_in[8];
    const float* ec = (const float*)d_in[9];
    const float* ep = (const float*)d_in[10];
    const float* ed = (const float*)d_in[11];
    const float* eli = (const float*)d_in[12];
    const float* elv = (const float*)d_in[13];
    const float* eii = (const float*)d_in[14];
    const float* eiv = (const float*)d_in[15];
    const float* mWih = (const float*)d_in[16];
    const float* mWhh = (const float*)d_in[17];
    const float* mbih = (const float*)d_in[18];
    const float* mbhh = (const float*)d_in[19];
    const float* vWih = (const float*)d_in[20];
    const float* vWhh = (const float*)d_in[21];
    const float* vbih = (const float*)d_in[22];
    const float* vbhh = (const float*)d_in[23];
    const float* gWs = (const float*)d_in[24];
    const float* gWm = (const float*)d_in[25];
    const float* fwW = (const float*)d_in[26];
    const float* fwb = (const float*)d_in[27];
    const float* faW = (const float*)d_in[28];
    const float* fab = (const float*)d_in[29];
    const float* fpW = (const float*)d_in[30];
    const float* fpb = (const float*)d_in[31];
    float* out = (float*)d_out;

    cudaFuncSetAttribute((const void*)k_rec<16, 32, true>, cudaFuncAttributeMaxDynamicSharedMemorySize, 229376);
    cudaFuncSetAttribute((const void*)k_rec<4, 16, false>, cudaFuncAttributeMaxDynamicSharedMemorySize, 204800);

    k_pre<<<18178, 128>>>(cc, cp, cd, ec, ep, ed, cli, clv, cii, civ, eli, elv, eii, eiv,
                          gWs, gWm, wgt, age, fwW, fwb, faW, fab);
    k_bias<<<64, 128>>>(gWs, gWm);
    k_gemm<<<dim3(64, 8, 2), 256>>>(1, mWih, vWih, mbih, vbih);
    k_gemm<<<dim3(64, 6, 8), 256>>>(2, mWih, vWih, mbih, vbih);
    k_rec<16, 32, true><<<128, 384, 229376>>>(mWhh, mbhh);
    k_gemm<<<dim3(20, 6, 1), 256>>>(3, mWih, vWih, mbih, vbih);
    k_rec<4, 16, false><<<40, 384, 204800>>>(vWhh, vbhh);
    k_head<<<160, 256>>>(fpW, fpb, out);
}

// round 6
// speedup vs baseline: 1.5816x; 1.0598x over previous
#include <cuda_runtime.h>

typedef unsigned long long u64;

#define B_  16
#define V_  16
#define C_  64
#define M_  32
#define CM_ 16
#define D_  128
#define OUT_ 600
#define BV  256
#define BVM 8192

// ---------------- scratch ----------------
__device__ __align__(16) float g_vis[3][BV][D_];
__device__ __align__(16) float g_mon[2][BVM][D_];
__device__ __align__(16) float g_wc[2][512 * D_];        // gnn combined weights [n=512][k=128]
__device__ __align__(16) float g_bias[2][BV][512];       // visit-level gnn bias
__device__ __align__(16) float g_outs[2][BVM][512];      // gnn outputs (relu)
__device__ __align__(16) float g_gi[8][BVM][384];        // monitor gi
__device__ __align__(16) float g_seq[10][BV][D_];        // visit-level sequences
__device__ __align__(16) float g_vgi[10][BV][384];       // visit gi
__device__ __align__(16) float g_hbuf[10][B_][D_];       // final hidden per run

// ---------------- helpers ----------------
__device__ __forceinline__ void fma2(u64& c, u64 a, u64 b) {
    asm("fma.rn.f32x2 %0, %1, %2, %0;" : "+l"(c) : "l"(a), "l"(b));
}
__device__ __forceinline__ float sum2(u64 v) {
    float x, y; asm("mov.b64 {%0, %1}, %2;" : "=f"(x), "=f"(y) : "l"(v)); return x + y;
}
__device__ __forceinline__ float sigm_(float x) { return 1.f / (1.f + __expf(-x)); }
__device__ __forceinline__ float tanh_(float x) { float e = __expf(2.f * x); return 1.f - 2.f / (e + 1.f); }

__device__ __forceinline__ unsigned tf32r(float x) {
    unsigned r; asm("cvt.rna.tf32.f32 %0, %1;" : "=r"(r) : "f"(x)); return r;
}

#define MMA_TF32(c, a, b) \
    asm("mma.sync.aligned.m16n8k8.row.col.f32.tf32.tf32.f32 " \
        "{%0,%1,%2,%3},{%4,%5,%6,%7},{%8,%9},{%0,%1,%2,%3};" \
        : "+f"((c)[0]), "+f"((c)[1]), "+f"((c)[2]), "+f"((c)[3]) \
        : "r"((a)[0]), "r"((a)[1]), "r"((a)[2]), "r"((a)[3]), "r"((b)[0]), "r"((b)[1]))

// ---------------- K_pre: all gathers + weight prep + scalar feats ----------------
__global__ __launch_bounds__(128) void k_pre(
    const int* __restrict__ cc, const int* __restrict__ cp, const int* __restrict__ cd,
    const float* __restrict__ ec, const float* __restrict__ ep, const float* __restrict__ ed,
    const int* __restrict__ li, const int* __restrict__ lv,
    const int* __restrict__ ii, const int* __restrict__ iv,
    const float* __restrict__ eli, const float* __restrict__ elv,
    const float* __restrict__ eii, const float* __restrict__ eiv,
    const float* __restrict__ Ws, const float* __restrict__ Wm,
    const float* __restrict__ w, const float* __restrict__ a,
    const float* __restrict__ fwW, const float* __restrict__ fwb,
    const float* __restrict__ faW, const float* __restrict__ fab) {
    int bx = blockIdx.x, tid = threadIdx.x;
    if (bx < 768) {
        int bv = bx & 255, ty = bx >> 8, d = tid;
        const int* codes = ((ty == 0) ? cc : ((ty == 1) ? cp : cd)) + bv * C_;
        const float* emb = (ty == 0) ? ec : ((ty == 1) ? ep : ed);
        float s = 0.f;
#pragma unroll 8
        for (int c = 0; c < C_; c++) s += emb[codes[c] * D_ + d];
        g_vis[ty][bv][d] = s;
    } else if (bx < 17152) {
        int i = bx - 768, p = i >> 13, row = i & 8191, d = tid;
        const int* ci = ((p == 0) ? li : ii) + row * CM_;
        const int* cv = ((p == 0) ? lv : iv) + row * CM_;
        const float* ei = (p == 0) ? eli : eii;
        const float* ev = (p == 0) ? elv : eiv;
        float s = 0.f;
#pragma unroll
        for (int c = 0; c < CM_; c++) s += ei[ci[c] * D_ + d] * ev[cv[c] * D_ + d];
        g_mon[p][row][d] = s;
    } else if (bx < 18176) {
        int i = (bx - 17152) * 128 + tid;
        int p = i >> 16, d = (i >> 9) & 127, j5 = i & 511;
        int t = j5 >> 7, j = j5 & 127;
        float v = (t == 0) ? Ws[(p * 4) * 16384 + d * 128 + j]
                           : Wm[(p * 4 + t) * 16384 + d * 128 + j] * (1.f / 3.f);
        g_wc[p][j5 * 128 + d] = v;   // [n][k] layout
    } else {
        int i = bx - 18176;
        const float* Wp = (i == 0) ? fwW : faW;
        const float* bp = (i == 0) ? fwb : fab;
        const float* xp = (i == 0) ? w : a;
        for (int idx = tid; idx < 32768; idx += 128) {
            int bv = idx >> 7, d = idx & 127;
            float x = xp[bv];
            g_seq[8 + i][bv][d] = (x != 0.f) ? (x * Wp[d] + bp[d]) : 0.f;
        }
    }
}

// ---------------- K_bias: visit-level gnn bias ----------------
__global__ __launch_bounds__(128) void k_bias(const float* __restrict__ Ws, const float* __restrict__ Wm) {
    __shared__ float sv[3][32][128];
    int blk = blockIdx.x, tid = threadIdx.x;
    int pt = blk >> 3, p = pt >> 2, t = pt & 3;
    int bv0 = (blk & 7) * 32;
    for (int i = tid; i < 3 * 32 * 128; i += 128) {
        int ty = i >> 12, c = (i >> 7) & 31, d = i & 127;
        sv[ty][c][d] = g_vis[ty][bv0 + c][d];
    }
    __syncthreads();
    int j = tid;
    const float* Wsp = Ws + (p * 4 + t) * 16384;
    const float* Wmp = Wm + (p * 4 + t) * 16384;
    float acc[32];
#pragma unroll
    for (int c = 0; c < 32; c++) acc[c] = 0.f;
    for (int d = 0; d < 128; d++) {
        float w2 = Wmp[d * 128 + j] * (1.f / 3.f);
        float w1 = (t == 0) ? 0.f : (Wsp[d * 128 + j] - w2);
#pragma unroll
        for (int c = 0; c < 32; c++) {
            float v0 = sv[0][c][d], v1 = sv[1][c][d], v2 = sv[2][c][d];
            float vs = v0 + v1 + v2;
            float vt = (t == 1) ? v0 : ((t == 2) ? v1 : ((t == 3) ? v2 : 0.f));
            acc[c] = fmaf(w2, vs, fmaf(w1, vt, acc[c]));
        }
    }
    for (int c = 0; c < 32; c++) g_bias[p][bv0 + c][t * 128 + j] = acc[c];
}

// ---------------- Tensor-core GEMM (3xTF32): 128x128 block tile ----------------
// out[m, n] = act( sum_k A[m,k] * W[n,k] + bias )
// All W operands are row-major [n][128]. K=128 always (2 chunks of 64).
// mode 1: gnn; mode 2: monitor gi; mode 3: visit gi.
#define GSM_BYTES (4 * 128 * 68 * 4)
__global__ __launch_bounds__(256) void k_gemm(int mode,
                                              const float* __restrict__ mWih, const float* __restrict__ vWih,
                                              const float* __restrict__ bih_all, const float* __restrict__ vbih_all) {
    extern __shared__ float sm[];
    float* Ah = sm;                 // [128][68]
    float* Al = Ah + 128 * 68;
    float* Wh = Al + 128 * 68;      // [128][68]  (n rows, k cols)
    float* Wl = Wh + 128 * 68;

    const float *A, *W, *bias; float* out;
    int lda, K, bshift, relu;
    int n0 = blockIdx.x * 128, j0 = blockIdx.y * 128;
    if (mode == 1) {
        int p = blockIdx.z;
        A = &g_mon[p][0][0]; lda = 128;
        W = g_wc[p]; bias = &g_bias[p][0][0]; bshift = 5; K = 512; relu = 1;
        out = &g_outs[p][0][0];
    } else if (mode == 2) {
        int z = blockIdx.z, p = z >> 2, t = z & 3, g = (t == 0) ? p : (t + 1);
        A = &g_outs[p][0][0] + t * 128; lda = 512;
        W = mWih + g * 49152; bias = bih_all + g * 384; bshift = 30; K = 384; relu = 0;
        out = &g_gi[z][0][0];
    } else {
        int run = n0 >> 8;
        int vi = (run < 8) ? (run >> 2) : (run - 6);
        A = &g_seq[0][0][0]; lda = 128;
        W = vWih + vi * 49152; bias = vbih_all + vi * 384; bshift = 30; K = 384; relu = 0;
        out = &g_vgi[0][0][0];
    }

    int tid = threadIdx.x;
    int lane = tid & 31, wid = tid >> 5;
    int gid = lane >> 2, tig = lane & 3;
    int m0w = (wid & 1) * 64, n0w = (wid >> 1) * 32;

    float C[4][4][4];
#pragma unroll
    for (int mt = 0; mt < 4; mt++)
#pragma unroll
        for (int nt = 0; nt < 4; nt++)
#pragma unroll
            for (int q = 0; q < 4; q++) C[mt][nt][q] = 0.f;

    for (int kc = 0; kc < 2; kc++) {
        // load A tile [128][64] -> hi/lo
#pragma unroll
        for (int it = 0; it < 8; it++) {
            int f4 = tid + 256 * it;
            int r = f4 >> 4, c4 = f4 & 15;
            float4 v = *(const float4*)(A + (n0 + r) * lda + kc * 64 + c4 * 4);
            float h0 = __uint_as_float(tf32r(v.x)), h1 = __uint_as_float(tf32r(v.y));
            float h2 = __uint_as_float(tf32r(v.z)), h3 = __uint_as_float(tf32r(v.w));
            float4 hv = make_float4(h0, h1, h2, h3);
            float4 lv = make_float4(__uint_as_float(tf32r(v.x - h0)), __uint_as_float(tf32r(v.y - h1)),
                                    __uint_as_float(tf32r(v.z - h2)), __uint_as_float(tf32r(v.w - h3)));
            *(float4*)(Ah + r * 68 + c4 * 4) = hv;
            *(float4*)(Al + r * 68 + c4 * 4) = lv;
        }
        // load W tile [128 n][64 k] -> hi/lo (row-major source [n][128])
#pragma unroll
        for (int it = 0; it < 8; it++) {
            int f4 = tid + 256 * it;
            int n = f4 >> 4, k4 = f4 & 15;
            float4 v = *(const float4*)(W + (j0 + n) * 128 + kc * 64 + k4 * 4);
            float h0 = __uint_as_float(tf32r(v.x)), h1 = __uint_as_float(tf32r(v.y));
            float h2 = __uint_as_float(tf32r(v.z)), h3 = __uint_as_float(tf32r(v.w));
            float4 hv = make_float4(h0, h1, h2, h3);
            float4 lv = make_float4(__uint_as_float(tf32r(v.x - h0)), __uint_as_float(tf32r(v.y - h1)),
                                    __uint_as_float(tf32r(v.z - h2)), __uint_as_float(tf32r(v.w - h3)));
            *(float4*)(Wh + n * 68 + k4 * 4) = hv;
            *(float4*)(Wl + n * 68 + k4 * 4) = lv;
        }
        __syncthreads();

#pragma unroll 2
        for (int ks = 0; ks < 8; ks++) {
            int kk = ks * 8;
            unsigned ah[4][4], al[4][4], bh[4][2], bl[4][2];
#pragma unroll
            for (int mt = 0; mt < 4; mt++) {
                const float* ap = Ah + (m0w + 16 * mt + gid) * 68 + kk + tig;
                const float* lp = Al + (m0w + 16 * mt + gid) * 68 + kk + tig;
                ah[mt][0] = __float_as_uint(ap[0]);
                ah[mt][1] = __float_as_uint(ap[8 * 68]);
                ah[mt][2] = __float_as_uint(ap[4]);
                ah[mt][3] = __float_as_uint(ap[8 * 68 + 4]);
                al[mt][0] = __float_as_uint(lp[0]);
                al[mt][1] = __float_as_uint(lp[8 * 68]);
                al[mt][2] = __float_as_uint(lp[4]);
                al[mt][3] = __float_as_uint(lp[8 * 68 + 4]);
            }
#pragma unroll
            for (int nt = 0; nt < 4; nt++) {
                const float* bp = Wh + (n0w + 8 * nt + gid) * 68 + kk + tig;
                const float* lp = Wl + (n0w + 8 * nt + gid) * 68 + kk + tig;
                bh[nt][0] = __float_as_uint(bp[0]);
                bh[nt][1] = __float_as_uint(bp[4]);
                bl[nt][0] = __float_as_uint(lp[0]);
                bl[nt][1] = __float_as_uint(lp[4]);
            }
#pragma unroll
            for (int mt = 0; mt < 4; mt++)
#pragma unroll
                for (int nt = 0; nt < 4; nt++) {
                    MMA_TF32(C[mt][nt], ah[mt], bh[nt]);
                    MMA_TF32(C[mt][nt], ah[mt], bl[nt]);
                    MMA_TF32(C[mt][nt], al[mt], bh[nt]);
                }
        }
        __syncthreads();
    }

    // epilogue
#pragma unroll
    for (int mt = 0; mt < 4; mt++) {
        int mrow = n0 + m0w + 16 * mt + gid;
        int bgrp = (mrow >> bshift) * K;
        int bgrp2 = ((mrow + 8) >> bshift) * K;
#pragma unroll
        for (int nt = 0; nt < 4; nt++) {
            int col = j0 + n0w + 8 * nt + 2 * tig;
            float v0 = C[mt][nt][0] + bias[bgrp + col];
            float v1 = C[mt][nt][1] + bias[bgrp + col + 1];
            float v2 = C[mt][nt][2] + bias[bgrp2 + col];
            float v3 = C[mt][nt][3] + bias[bgrp2 + col + 1];
            if (relu) {
                v0 = fmaxf(v0, 0.f); v1 = fmaxf(v1, 0.f);
                v2 = fmaxf(v2, 0.f); v3 = fmaxf(v3, 0.f);
            }
            *(float2*)(out + mrow * K + col) = make_float2(v0, v1);
            *(float2*)(out + (mrow + 8) * K + col) = make_float2(v2, v3);
        }
    }
}

// ---------------- GRU recurrence (templated on seqs/block) ----------------
template <int NSEQ, int T, bool MON>
__global__ __launch_bounds__(384, 1) void k_rec(const float* __restrict__ Whh_all,
                                                const float* __restrict__ bhh_all) {
    extern __shared__ float sm[];
    float* wsf = sm;                     // 64*384 u64 = 49152 floats
    float* hs = sm + 49152;              // [NSEQ][128]
    float* gsm = hs + NSEQ * 128;        // [NSEQ][384]
    const u64* ws2 = (const u64*)sm;
    int tid = threadIdx.x, bx = blockIdx.x;

    const float *Whh, *bhh, *gip; float* outp;
    int s0;
    if (MON) {
        int chan = bx >> 4, sgrp = bx & 15;
        int p = chan >> 2, t = chan & 3, g = (t == 0) ? p : (t + 1);
        Whh = Whh_all + g * 49152; bhh = bhh_all + g * 384;
        gip = &g_gi[chan][0][0]; outp = &g_seq[chan][0][0];
        s0 = sgrp * NSEQ;
    } else {
        int run = bx >> 2, sgrp = bx & 3;
        int vi = (run < 8) ? (run >> 2) : (run - 6);
        Whh = Whh_all + vi * 49152; bhh = bhh_all + vi * 384;
        gip = &g_vgi[run][0][0]; outp = &g_hbuf[run][0][0];
        s0 = sgrp * NSEQ;
    }
    for (int i = tid; i < 49152; i += 384) {
        int j = i >> 7, d = i & 127;
        wsf[(d >> 1) * 768 + 2 * j + (d & 1)] = Whh[i];
    }
    for (int i = tid; i < NSEQ * 128; i += 384) hs[i] = 0.f;
    __syncthreads();

    int j = tid;
    float bj = bhh[j];
    constexpr int KP = (NSEQ * 128 + 383) / 384;

    for (int t = 0; t < T; t++) {
        float pr[KP], pz[KP], pn[KP];
#pragma unroll
        for (int k = 0; k < KP; k++) {
            int idx = tid + k * 384;
            if (idx < NSEQ * 128) {
                int s = idx >> 7, d = idx & 127;
                const float* gr = gip + ((s0 + s) * T + t) * 384;
                pr[k] = gr[d]; pz[k] = gr[128 + d]; pn[k] = gr[256 + d];
            }
        }
        u64 acc[NSEQ];
#pragma unroll
        for (int s = 0; s < NSEQ; s++) acc[s] = 0ull;
#pragma unroll 2
        for (int d4 = 0; d4 < 32; d4++) {
            u64 wA = ws2[(2 * d4) * 384 + j];
            u64 wB = ws2[(2 * d4 + 1) * 384 + j];
#pragma unroll
            for (int s = 0; s < NSEQ; s++) {
                double2 hd = ((const double2*)(hs + s * 128))[d4];
                fma2(acc[s], __double_as_longlong(hd.x), wA);
                fma2(acc[s], __double_as_longlong(hd.y), wB);
            }
        }
#pragma unroll
        for (int s = 0; s < NSEQ; s++) gsm[s * 384 + j] = sum2(acc[s]) + bj;
        __syncthreads();
#pragma unroll
        for (int k = 0; k < KP; k++) {
            int idx = tid + k * 384;
            if (idx < NSEQ * 128) {
                int s = idx >> 7, d = idx & 127;
                float rg = sigm_(pr[k] + gsm[s * 384 + d]);
                float zg = sigm_(pz[k] + gsm[s * 384 + 128 + d]);
                float nn = tanh_(fmaf(rg, gsm[s * 384 + 256 + d], pn[k]));
                hs[idx] = (1.f - zg) * nn + zg * hs[idx];
            }
        }
        __syncthreads();
    }
    for (int idx = tid; idx < NSEQ * 128; idx += 384) {
        int s = idx >> 7, d = idx & 127;
        outp[(s0 + s) * 128 + d] = hs[idx];
    }
}

// ---------------- head: out = relu(pe) @ W.T + b ----------------
__global__ void k_head(const float* __restrict__ fW, const float* __restrict__ fb,
                       float* __restrict__ out) {
    __shared__ float pe[896];
    int b = blockIdx.x / 10, og0 = (blockIdx.x % 10) * 60;
    int tid = threadIdx.x, lane = tid & 31, wp = tid >> 5;
    const float* H = &g_hbuf[0][0][0];  // [10][16][128]
    for (int i = tid; i < 896; i += 256) {
        int slot = i >> 7, d = i & 127;
        float v;
        if (slot == 0) v = H[0 * 2048 + b * 128 + d];
        else if (slot == 1) v = H[1 * 2048 + b * 128 + d] + H[5 * 2048 + b * 128 + d];
        else if (slot == 2) v = H[2 * 2048 + b * 128 + d] + H[6 * 2048 + b * 128 + d];
        else if (slot == 3) v = H[3 * 2048 + b * 128 + d] + H[7 * 2048 + b * 128 + d];
        else if (slot == 4) v = H[4 * 2048 + b * 128 + d];
        else if (slot == 5) v = H[8 * 2048 + b * 128 + d];
        else v = H[9 * 2048 + b * 128 + d];
        pe[i] = fmaxf(v, 0.f);
    }
    __syncthreads();
    for (int oi = wp; oi < 60; oi += 8) {
        int o = og0 + oi;
        u64 acc = 0ull;
#pragma unroll
        for (int i = 0; i < 7; i++) {
            int k4 = lane + 32 * i;
            float4 wv = __ldg((const float4*)(fW + o * 896) + k4);
            float4 xv = ((const float4*)pe)[k4];
            u64 a01, a23, w01, w23;
            asm("mov.b64 %0, {%1, %2};" : "=l"(a01) : "f"(xv.x), "f"(xv.y));
            asm("mov.b64 %0, {%1, %2};" : "=l"(a23) : "f"(xv.z), "f"(xv.w));
            asm("mov.b64 %0, {%1, %2};" : "=l"(w01) : "f"(wv.x), "f"(wv.y));
            asm("mov.b64 %0, {%1, %2};" : "=l"(w23) : "f"(wv.z), "f"(wv.w));
            fma2(acc, a01, w01);
            fma2(acc, a23, w23);
        }
        float v = sum2(acc);
#pragma unroll
        for (int m = 16; m > 0; m >>= 1) v += __shfl_xor_sync(0xffffffffu, v, m);
        if (lane == 0) out[b * 600 + o] = v + fb[o];
    }
}

// ---------------- launch ----------------
extern "C" void kernel_launch(void* const* d_in, const int* in_sizes, int n_in,
                              void* d_out, int out_size) {
    const int* cc = (const int*)d_in[0];
    const int* cp = (const int*)d_in[1];
    const int* cd = (const int*)d_in[2];
    const int* cli = (const int*)d_in[3];
    const int* clv = (const int*)d_in[4];
    const int* cii = (const int*)d_in[5];
    const int* civ = (const int*)d_in[6];
    const float* wgt = (const float*)d_in[7];
    const float* age = (const float*)d_in[8];
    const float* ec = (const float*)d_in[9];
    const float* ep = (const float*)d_in[10];
    const float* ed = (const float*)d_in[11];
    const float* eli = (const float*)d_in[12];
    const float* elv = (const float*)d_in[13];
    const float* eii = (const float*)d_in[14];
    const float* eiv = (const float*)d_in[15];
    const float* mWih = (const float*)d_in[16];
    const float* mWhh = (const float*)d_in[17];
    const float* mbih = (const float*)d_in[18];
    const float* mbhh = (const float*)d_in[19];
    const float* vWih = (const float*)d_in[20];
    const float* vWhh = (const float*)d_in[21];
    const float* vbih = (const float*)d_in[22];
    const float* vbhh = (const float*)d_in[23];
    const float* gWs = (const float*)d_in[24];
    const float* gWm = (const float*)d_in[25];
    const float* fwW = (const float*)d_in[26];
    const float* fwb = (const float*)d_in[27];
    const float* faW = (const float*)d_in[28];
    const float* fab = (const float*)d_in[29];
    const float* fpW = (const float*)d_in[30];
    const float* fpb = (const float*)d_in[31];
    float* out = (float*)d_out;

    cudaFuncSetAttribute(k_gemm, cudaFuncAttributeMaxDynamicSharedMemorySize, GSM_BYTES);
    cudaFuncSetAttribute((const void*)k_rec<16, 32, true>, cudaFuncAttributeMaxDynamicSharedMemorySize, 229376);
    cudaFuncSetAttribute((const void*)k_rec<4, 16, false>, cudaFuncAttributeMaxDynamicSharedMemorySize, 204800);

    k_pre<<<18178, 128>>>(cc, cp, cd, ec, ep, ed, cli, clv, cii, civ, eli, elv, eii, eiv,
                          gWs, gWm, wgt, age, fwW, fwb, faW, fab);
    k_bias<<<64, 128>>>(gWs, gWm);
    k_gemm<<<dim3(64, 4, 2), 256, GSM_BYTES>>>(1, mWih, vWih, mbih, vbih);
    k_gemm<<<dim3(64, 3, 8), 256, GSM_BYTES>>>(2, mWih, vWih, mbih, vbih);
    k_rec<16, 32, true><<<128, 384, 229376>>>(mWhh, mbhh);
    k_gemm<<<dim3(20, 3, 1), 256, GSM_BYTES>>>(3, mWih, vWih, mbih, vbih);
    k_rec<4, 16, false><<<40, 384, 204800>>>(vWhh, vbhh);
    k_head<<<160, 256>>>(fpW, fpb, out);
}

// round 7
// speedup vs baseline: 1.6346x; 1.0335x over previous
#include <cuda_runtime.h>

typedef unsigned long long u64;

#define B_  16
#define V_  16
#define C_  64
#define M_  32
#define CM_ 16
#define D_  128
#define OUT_ 600
#define BV  256
#define BVM 8192

// ---------------- scratch ----------------
__device__ __align__(16) float g_vis[3][BV][D_];
__device__ __align__(16) float g_mon[2][BVM][D_];
__device__ __align__(16) float g_wch[2][512 * D_];       // gnn combined weights tf32-hi [n][k]
__device__ __align__(16) float g_wcl[2][512 * D_];       // gnn combined weights tf32-lo
__device__ __align__(16) float g_mih_h[5 * 384 * D_];    // mgru Wih tf32-hi
__device__ __align__(16) float g_mih_l[5 * 384 * D_];
__device__ __align__(16) float g_vih_h[4 * 384 * D_];    // vgru Wih tf32-hi
__device__ __align__(16) float g_vih_l[4 * 384 * D_];
__device__ __align__(16) float g_bias[2][BV][512];       // visit-level gnn bias
__device__ __align__(16) float g_outs[2][BVM][512];      // gnn outputs (relu)
__device__ __align__(16) float g_gi[8][BVM][384];        // monitor gi
__device__ __align__(16) float g_seq[10][BV][D_];        // visit-level sequences
__device__ __align__(16) float g_vgi[10][BV][384];       // visit gi
__device__ __align__(16) float g_hbuf[10][B_][D_];       // final hidden per run

// ---------------- helpers ----------------
__device__ __forceinline__ void fma2(u64& c, u64 a, u64 b) {
    asm("fma.rn.f32x2 %0, %1, %2, %0;" : "+l"(c) : "l"(a), "l"(b));
}
__device__ __forceinline__ float sum2(u64 v) {
    float x, y; asm("mov.b64 {%0, %1}, %2;" : "=f"(x), "=f"(y) : "l"(v)); return x + y;
}
__device__ __forceinline__ float tanh_fast(float x) {
    float r; asm("tanh.approx.f32 %0, %1;" : "=f"(r) : "f"(x)); return r;
}
__device__ __forceinline__ float sigm_(float x) { return fmaf(0.5f, tanh_fast(0.5f * x), 0.5f); }

__device__ __forceinline__ unsigned tf32r(float x) {
    unsigned r; asm("cvt.rna.tf32.f32 %0, %1;" : "=r"(r) : "f"(x)); return r;
}

#define MMA_TF32(c, a, b) \
    asm("mma.sync.aligned.m16n8k8.row.col.f32.tf32.tf32.f32 " \
        "{%0,%1,%2,%3},{%4,%5,%6,%7},{%8,%9},{%0,%1,%2,%3};" \
        : "+f"((c)[0]), "+f"((c)[1]), "+f"((c)[2]), "+f"((c)[3]) \
        : "r"((a)[0]), "r"((a)[1]), "r"((a)[2]), "r"((a)[3]), "r"((b)[0]), "r"((b)[1]))

// ---------------- K_pre: gathers + weight prep (incl. tf32 hi/lo) + scalar feats ----------------
__global__ __launch_bounds__(128) void k_pre(
    const int* __restrict__ cc, const int* __restrict__ cp, const int* __restrict__ cd,
    const float* __restrict__ ec, const float* __restrict__ ep, const float* __restrict__ ed,
    const int* __restrict__ li, const int* __restrict__ lv,
    const int* __restrict__ ii, const int* __restrict__ iv,
    const float* __restrict__ eli, const float* __restrict__ elv,
    const float* __restrict__ eii, const float* __restrict__ eiv,
    const float* __restrict__ Ws, const float* __restrict__ Wm,
    const float* __restrict__ mWih, const float* __restrict__ vWih,
    const float* __restrict__ w, const float* __restrict__ a,
    const float* __restrict__ fwW, const float* __restrict__ fwb,
    const float* __restrict__ faW, const float* __restrict__ fab) {
    int bx = blockIdx.x, tid = threadIdx.x;
    if (bx < 768) {
        int bv = bx & 255, ty = bx >> 8, d = tid;
        const int* codes = ((ty == 0) ? cc : ((ty == 1) ? cp : cd)) + bv * C_;
        const float* emb = (ty == 0) ? ec : ((ty == 1) ? ep : ed);
        float s = 0.f;
#pragma unroll 8
        for (int c = 0; c < C_; c++) s += emb[codes[c] * D_ + d];
        g_vis[ty][bv][d] = s;
    } else if (bx < 17152) {
        int i = bx - 768, p = i >> 13, row = i & 8191, d = tid;
        const int* ci = ((p == 0) ? li : ii) + row * CM_;
        const int* cv = ((p == 0) ? lv : iv) + row * CM_;
        const float* ei = (p == 0) ? eli : eii;
        const float* ev = (p == 0) ? elv : eiv;
        float s = 0.f;
#pragma unroll
        for (int c = 0; c < CM_; c++) s += ei[ci[c] * D_ + d] * ev[cv[c] * D_ + d];
        g_mon[p][row][d] = s;
    } else if (bx < 18176) {
        int i = (bx - 17152) * 128 + tid;
        int p = i >> 16, d = (i >> 9) & 127, j5 = i & 511;
        int t = j5 >> 7, j = j5 & 127;
        float v = (t == 0) ? Ws[(p * 4) * 16384 + d * 128 + j]
                           : Wm[(p * 4 + t) * 16384 + d * 128 + j] * (1.f / 3.f);
        float h = __uint_as_float(tf32r(v));
        g_wch[p][j5 * 128 + d] = h;
        g_wcl[p][j5 * 128 + d] = __uint_as_float(tf32r(v - h));
    } else if (bx < 20096) {
        int idx = (bx - 18176) * 128 + tid;   // < 245760
        float v = mWih[idx];
        float h = __uint_as_float(tf32r(v));
        g_mih_h[idx] = h;
        g_mih_l[idx] = __uint_as_float(tf32r(v - h));
    } else if (bx < 21632) {
        int idx = (bx - 20096) * 128 + tid;   // < 196608
        float v = vWih[idx];
        float h = __uint_as_float(tf32r(v));
        g_vih_h[idx] = h;
        g_vih_l[idx] = __uint_as_float(tf32r(v - h));
    } else {
        int i = bx - 21632;
        const float* Wp = (i == 0) ? fwW : faW;
        const float* bp = (i == 0) ? fwb : fab;
        const float* xp = (i == 0) ? w : a;
        for (int idx = tid; idx < 32768; idx += 128) {
            int bv = idx >> 7, d = idx & 127;
            float x = xp[bv];
            g_seq[8 + i][bv][d] = (x != 0.f) ? (x * Wp[d] + bp[d]) : 0.f;
        }
    }
}

// ---------------- K_bias: visit-level gnn bias ----------------
__global__ __launch_bounds__(128) void k_bias(const float* __restrict__ Ws, const float* __restrict__ Wm) {
    __shared__ float sv[3][32][128];
    int blk = blockIdx.x, tid = threadIdx.x;
    int pt = blk >> 3, p = pt >> 2, t = pt & 3;
    int bv0 = (blk & 7) * 32;
    for (int i = tid; i < 3 * 32 * 128; i += 128) {
        int ty = i >> 12, c = (i >> 7) & 31, d = i & 127;
        sv[ty][c][d] = g_vis[ty][bv0 + c][d];
    }
    __syncthreads();
    int j = tid;
    const float* Wsp = Ws + (p * 4 + t) * 16384;
    const float* Wmp = Wm + (p * 4 + t) * 16384;
    float acc[32];
#pragma unroll
    for (int c = 0; c < 32; c++) acc[c] = 0.f;
    for (int d = 0; d < 128; d++) {
        float w2 = Wmp[d * 128 + j] * (1.f / 3.f);
        float w1 = (t == 0) ? 0.f : (Wsp[d * 128 + j] - w2);
#pragma unroll
        for (int c = 0; c < 32; c++) {
            float v0 = sv[0][c][d], v1 = sv[1][c][d], v2 = sv[2][c][d];
            float vs = v0 + v1 + v2;
            float vt = (t == 1) ? v0 : ((t == 2) ? v1 : ((t == 3) ? v2 : 0.f));
            acc[c] = fmaf(w2, vs, fmaf(w1, vt, acc[c]));
        }
    }
    for (int c = 0; c < 32; c++) g_bias[p][bv0 + c][t * 128 + j] = acc[c];
}

// ---------------- Tensor-core GEMM (3xTF32): 128x128 block tile ----------------
#define GSM_BYTES (4 * 128 * 68 * 4)
__global__ __launch_bounds__(256) void k_gemm(int mode,
                                              const float* __restrict__ bih_all, const float* __restrict__ vbih_all) {
    extern __shared__ float sm[];
    float* Ah = sm;                 // [128][68]
    float* Al = Ah + 128 * 68;
    float* Wh = Al + 128 * 68;      // [128][68]  (n rows, k cols)
    float* Wl = Wh + 128 * 68;

    const float *A, *Whp, *Wlp, *bias; float* out;
    int lda, K, bshift, relu;
    int n0 = blockIdx.x * 128, j0 = blockIdx.y * 128;
    if (mode == 1) {
        int p = blockIdx.z;
        A = &g_mon[p][0][0]; lda = 128;
        Whp = g_wch[p]; Wlp = g_wcl[p];
        bias = &g_bias[p][0][0]; bshift = 5; K = 512; relu = 1;
        out = &g_outs[p][0][0];
    } else if (mode == 2) {
        int z = blockIdx.z, p = z >> 2, t = z & 3, g = (t == 0) ? p : (t + 1);
        A = &g_outs[p][0][0] + t * 128; lda = 512;
        Whp = g_mih_h + g * 49152; Wlp = g_mih_l + g * 49152;
        bias = bih_all + g * 384; bshift = 30; K = 384; relu = 0;
        out = &g_gi[z][0][0];
    } else {
        int run = n0 >> 8;
        int vi = (run < 8) ? (run >> 2) : (run - 6);
        A = &g_seq[0][0][0]; lda = 128;
        Whp = g_vih_h + vi * 49152; Wlp = g_vih_l + vi * 49152;
        bias = vbih_all + vi * 384; bshift = 30; K = 384; relu = 0;
        out = &g_vgi[0][0][0];
    }

    int tid = threadIdx.x;
    int lane = tid & 31, wid = tid >> 5;
    int gid = lane >> 2, tig = lane & 3;
    int m0w = (wid & 1) * 64, n0w = (wid >> 1) * 32;

    float C[4][4][4];
#pragma unroll
    for (int mt = 0; mt < 4; mt++)
#pragma unroll
        for (int nt = 0; nt < 4; nt++)
#pragma unroll
            for (int q = 0; q < 4; q++) C[mt][nt][q] = 0.f;

    for (int kc = 0; kc < 2; kc++) {
        // load A tile [128][64] -> hi/lo (with on-the-fly split)
#pragma unroll
        for (int it = 0; it < 8; it++) {
            int f4 = tid + 256 * it;
            int r = f4 >> 4, c4 = f4 & 15;
            float4 v = *(const float4*)(A + (n0 + r) * lda + kc * 64 + c4 * 4);
            float h0 = __uint_as_float(tf32r(v.x)), h1 = __uint_as_float(tf32r(v.y));
            float h2 = __uint_as_float(tf32r(v.z)), h3 = __uint_as_float(tf32r(v.w));
            *(float4*)(Ah + r * 68 + c4 * 4) = make_float4(h0, h1, h2, h3);
            *(float4*)(Al + r * 68 + c4 * 4) =
                make_float4(__uint_as_float(tf32r(v.x - h0)), __uint_as_float(tf32r(v.y - h1)),
                            __uint_as_float(tf32r(v.z - h2)), __uint_as_float(tf32r(v.w - h3)));
        }
        // load W tile [128 n][64 k] hi/lo (precomputed)
#pragma unroll
        for (int it = 0; it < 8; it++) {
            int f4 = tid + 256 * it;
            int n = f4 >> 4, k4 = f4 & 15;
            *(float4*)(Wh + n * 68 + k4 * 4) = *(const float4*)(Whp + (j0 + n) * 128 + kc * 64 + k4 * 4);
            *(float4*)(Wl + n * 68 + k4 * 4) = *(const float4*)(Wlp + (j0 + n) * 128 + kc * 64 + k4 * 4);
        }
        __syncthreads();

#pragma unroll 2
        for (int ks = 0; ks < 8; ks++) {
            int kk = ks * 8;
            unsigned ah[4][4], al[4][4], bh[4][2], bl[4][2];
#pragma unroll
            for (int mt = 0; mt < 4; mt++) {
                const float* ap = Ah + (m0w + 16 * mt + gid) * 68 + kk + tig;
                const float* lp = Al + (m0w + 16 * mt + gid) * 68 + kk + tig;
                ah[mt][0] = __float_as_uint(ap[0]);
                ah[mt][1] = __float_as_uint(ap[8 * 68]);
                ah[mt][2] = __float_as_uint(ap[4]);
                ah[mt][3] = __float_as_uint(ap[8 * 68 + 4]);
                al[mt][0] = __float_as_uint(lp[0]);
                al[mt][1] = __float_as_uint(lp[8 * 68]);
                al[mt][2] = __float_as_uint(lp[4]);
                al[mt][3] = __float_as_uint(lp[8 * 68 + 4]);
            }
#pragma unroll
            for (int nt = 0; nt < 4; nt++) {
                const float* bp = Wh + (n0w + 8 * nt + gid) * 68 + kk + tig;
                const float* lp = Wl + (n0w + 8 * nt + gid) * 68 + kk + tig;
                bh[nt][0] = __float_as_uint(bp[0]);
                bh[nt][1] = __float_as_uint(bp[4]);
                bl[nt][0] = __float_as_uint(lp[0]);
                bl[nt][1] = __float_as_uint(lp[4]);
            }
#pragma unroll
            for (int mt = 0; mt < 4; mt++)
#pragma unroll
                for (int nt = 0; nt < 4; nt++) {
                    MMA_TF32(C[mt][nt], ah[mt], bh[nt]);
                    MMA_TF32(C[mt][nt], ah[mt], bl[nt]);
                    MMA_TF32(C[mt][nt], al[mt], bh[nt]);
                }
        }
        __syncthreads();
    }

#pragma unroll
    for (int mt = 0; mt < 4; mt++) {
        int mrow = n0 + m0w + 16 * mt + gid;
        int bgrp = (mrow >> bshift) * K;
        int bgrp2 = ((mrow + 8) >> bshift) * K;
#pragma unroll
        for (int nt = 0; nt < 4; nt++) {
            int col = j0 + n0w + 8 * nt + 2 * tig;
            float v0 = C[mt][nt][0] + bias[bgrp + col];
            float v1 = C[mt][nt][1] + bias[bgrp + col + 1];
            float v2 = C[mt][nt][2] + bias[bgrp2 + col];
            float v3 = C[mt][nt][3] + bias[bgrp2 + col + 1];
            if (relu) {
                v0 = fmaxf(v0, 0.f); v1 = fmaxf(v1, 0.f);
                v2 = fmaxf(v2, 0.f); v3 = fmaxf(v3, 0.f);
            }
            *(float2*)(out + mrow * K + col) = make_float2(v0, v1);
            *(float2*)(out + (mrow + 8) * K + col) = make_float2(v2, v3);
        }
    }
}

// ---------------- GRU recurrence (templated on seqs/block) ----------------
template <int NSEQ, int T, bool MON>
__global__ __launch_bounds__(384, 1) void k_rec(const float* __restrict__ Whh_all,
                                                const float* __restrict__ bhh_all) {
    extern __shared__ float sm[];
    float* wsf = sm;                     // 64*384 u64 = 49152 floats
    float* hs = sm + 49152;              // [NSEQ][128]
    float* gsm = hs + NSEQ * 128;        // [NSEQ][384]
    const u64* ws2 = (const u64*)sm;
    int tid = threadIdx.x, bx = blockIdx.x;

    const float *Whh, *bhh, *gip; float* outp;
    int s0;
    if (MON) {
        int chan = bx >> 4, sgrp = bx & 15;
        int p = chan >> 2, t = chan & 3, g = (t == 0) ? p : (t + 1);
        Whh = Whh_all + g * 49152; bhh = bhh_all + g * 384;
        gip = &g_gi[chan][0][0]; outp = &g_seq[chan][0][0];
        s0 = sgrp * NSEQ;
    } else {
        int run = bx >> 2, sgrp = bx & 3;
        int vi = (run < 8) ? (run >> 2) : (run - 6);
        Whh = Whh_all + vi * 49152; bhh = bhh_all + vi * 384;
        gip = &g_vgi[run][0][0]; outp = &g_hbuf[run][0][0];
        s0 = sgrp * NSEQ;
    }
    for (int i = tid; i < 49152; i += 384) {
        int j = i >> 7, d = i & 127;
        wsf[(d >> 1) * 768 + 2 * j + (d & 1)] = Whh[i];
    }
    for (int i = tid; i < NSEQ * 128; i += 384) hs[i] = 0.f;
    __syncthreads();

    int j = tid;
    float bj = bhh[j];
    constexpr int KP = (NSEQ * 128 + 383) / 384;

    for (int t = 0; t < T; t++) {
        float pr[KP], pz[KP], pn[KP];
#pragma unroll
        for (int k = 0; k < KP; k++) {
            int idx = tid + k * 384;
            if (idx < NSEQ * 128) {
                int s = idx >> 7, d = idx & 127;
                const float* gr = gip + ((s0 + s) * T + t) * 384;
                pr[k] = gr[d]; pz[k] = gr[128 + d]; pn[k] = gr[256 + d];
            }
        }
        u64 acc[NSEQ];
#pragma unroll
        for (int s = 0; s < NSEQ; s++) acc[s] = 0ull;
#pragma unroll 2
        for (int d4 = 0; d4 < 32; d4++) {
            u64 wA = ws2[(2 * d4) * 384 + j];
            u64 wB = ws2[(2 * d4 + 1) * 384 + j];
#pragma unroll
            for (int s = 0; s < NSEQ; s++) {
                double2 hd = ((const double2*)(hs + s * 128))[d4];
                fma2(acc[s], __double_as_longlong(hd.x), wA);
                fma2(acc[s], __double_as_longlong(hd.y), wB);
            }
        }
#pragma unroll
        for (int s = 0; s < NSEQ; s++) gsm[s * 384 + j] = sum2(acc[s]) + bj;
        __syncthreads();
#pragma unroll
        for (int k = 0; k < KP; k++) {
            int idx = tid + k * 384;
            if (idx < NSEQ * 128) {
                int s = idx >> 7, d = idx & 127;
                float rg = sigm_(pr[k] + gsm[s * 384 + d]);
                float zg = sigm_(pz[k] + gsm[s * 384 + 128 + d]);
                float nn = tanh_fast(fmaf(rg, gsm[s * 384 + 256 + d], pn[k]));
                hs[idx] = (1.f - zg) * nn + zg * hs[idx];
            }
        }
        __syncthreads();
    }
    for (int idx = tid; idx < NSEQ * 128; idx += 384) {
        int s = idx >> 7, d = idx & 127;
        outp[(s0 + s) * 128 + d] = hs[idx];
    }
}

// ---------------- head: out = relu(pe) @ W.T + b ----------------
__global__ void k_head(const float* __restrict__ fW, const float* __restrict__ fb,
                       float* __restrict__ out) {
    __shared__ float pe[896];
    int b = blockIdx.x / 10, og0 = (blockIdx.x % 10) * 60;
    int tid = threadIdx.x, lane = tid & 31, wp = tid >> 5;
    const float* H = &g_hbuf[0][0][0];  // [10][16][128]
    for (int i = tid; i < 896; i += 256) {
        int slot = i >> 7, d = i & 127;
        float v;
        if (slot == 0) v = H[0 * 2048 + b * 128 + d];
        else if (slot == 1) v = H[1 * 2048 + b * 128 + d] + H[5 * 2048 + b * 128 + d];
        else if (slot == 2) v = H[2 * 2048 + b * 128 + d] + H[6 * 2048 + b * 128 + d];
        else if (slot == 3) v = H[3 * 2048 + b * 128 + d] + H[7 * 2048 + b * 128 + d];
        else if (slot == 4) v = H[4 * 2048 + b * 128 + d];
        else if (slot == 5) v = H[8 * 2048 + b * 128 + d];
        else v = H[9 * 2048 + b * 128 + d];
        pe[i] = fmaxf(v, 0.f);
    }
    __syncthreads();
    for (int oi = wp; oi < 60; oi += 8) {
        int o = og0 + oi;
        u64 acc = 0ull;
#pragma unroll
        for (int i = 0; i < 7; i++) {
            int k4 = lane + 32 * i;
            float4 wv = __ldg((const float4*)(fW + o * 896) + k4);
            float4 xv = ((const float4*)pe)[k4];
            u64 a01, a23, w01, w23;
            asm("mov.b64 %0, {%1, %2};" : "=l"(a01) : "f"(xv.x), "f"(xv.y));
            asm("mov.b64 %0, {%1, %2};" : "=l"(a23) : "f"(xv.z), "f"(xv.w));
            asm("mov.b64 %0, {%1, %2};" : "=l"(w01) : "f"(wv.x), "f"(wv.y));
            asm("mov.b64 %0, {%1, %2};" : "=l"(w23) : "f"(wv.z), "f"(wv.w));
            fma2(acc, a01, w01);
            fma2(acc, a23, w23);
        }
        float v = sum2(acc);
#pragma unroll
        for (int m = 16; m > 0; m >>= 1) v += __shfl_xor_sync(0xffffffffu, v, m);
        if (lane == 0) out[b * 600 + o] = v + fb[o];
    }
}

// ---------------- launch ----------------
extern "C" void kernel_launch(void* const* d_in, const int* in_sizes, int n_in,
                              void* d_out, int out_size) {
    const int* cc = (const int*)d_in[0];
    const int* cp = (const int*)d_in[1];
    const int* cd = (const int*)d_in[2];
    const int* cli = (const int*)d_in[3];
    const int* clv = (const int*)d_in[4];
    const int* cii = (const int*)d_in[5];
    const int* civ = (const int*)d_in[6];
    const float* wgt = (const float*)d_in[7];
    const float* age = (const float*)d_in[8];
    const float* ec = (const float*)d_in[9];
    const float* ep = (const float*)d_in[10];
    const float* ed = (const float*)d_in[11];
    const float* eli = (const float*)d_in[12];
    const float* elv = (const float*)d_in[13];
    const float* eii = (const float*)d_in[14];
    const float* eiv = (const float*)d_in[15];
    const float* mWih = (const float*)d_in[16];
    const float* mWhh = (const float*)d_in[17];
    const float* mbih = (const float*)d_in[18];
    const float* mbhh = (const float*)d_in[19];
    const float* vWih = (const float*)d_in[20];
    const float* vWhh = (const float*)d_in[21];
    const float* vbih = (const float*)d_in[22];
    const float* vbhh = (const float*)d_in[23];
    const float* gWs = (const float*)d_in[24];
    const float* gWm = (const float*)d_in[25];
    const float* fwW = (const float*)d_in[26];
    const float* fwb = (const float*)d_in[27];
    const float* faW = (const float*)d_in[28];
    const float* fab = (const float*)d_in[29];
    const float* fpW = (const float*)d_in[30];
    const float* fpb = (const float*)d_in[31];
    float* out = (float*)d_out;

    cudaFuncSetAttribute(k_gemm, cudaFuncAttributeMaxDynamicSharedMemorySize, GSM_BYTES);
    cudaFuncSetAttribute((const void*)k_rec<16, 32, true>, cudaFuncAttributeMaxDynamicSharedMemorySize, 229376);
    cudaFuncSetAttribute((const void*)k_rec<4, 16, false>, cudaFuncAttributeMaxDynamicSharedMemorySize, 204800);

    k_pre<<<21634, 128>>>(cc, cp, cd, ec, ep, ed, cli, clv, cii, civ, eli, elv, eii, eiv,
                          gWs, gWm, mWih, vWih, wgt, age, fwW, fwb, faW, fab);
    k_bias<<<64, 128>>>(gWs, gWm);
    k_gemm<<<dim3(64, 4, 2), 256, GSM_BYTES>>>(1, mbih, vbih);
    k_gemm<<<dim3(64, 3, 8), 256, GSM_BYTES>>>(2, mbih, vbih);
    k_rec<16, 32, true><<<128, 384, 229376>>>(mWhh, mbhh);
    k_gemm<<<dim3(20, 3, 1), 256, GSM_BYTES>>>(3, mbih, vbih);
    k_rec<4, 16, false><<<40, 384, 204800>>>(vWhh, vbhh);
    k_head<<<160, 256>>>(fpW, fpb, out);
}

// round 10
// speedup vs baseline: 1.7033x; 1.0420x over previous
#include <cuda_runtime.h>

typedef unsigned long long u64;

#define B_  16
#define V_  16
#define C_  64
#define M_  32
#define CM_ 16
#define D_  128
#define OUT_ 600
#define BV  256
#define BVM 8192

// ---------------- scratch ----------------
__device__ __align__(16) float g_vis[3][BV][D_];
__device__ __align__(16) float g_mon[2][BVM][D_];
__device__ __align__(16) float g_wch[2][512 * D_];       // gnn combined weights tf32-hi [n][k]
__device__ __align__(16) float g_wcl[2][512 * D_];       // gnn combined weights tf32-lo
__device__ __align__(16) float g_mih_h[5 * 384 * D_];    // mgru Wih tf32-hi
__device__ __align__(16) float g_mih_l[5 * 384 * D_];
__device__ __align__(16) float g_vih_h[4 * 384 * D_];    // vgru Wih tf32-hi
__device__ __align__(16) float g_vih_l[4 * 384 * D_];
__device__ __align__(16) float g_bias[2][BV][512];       // visit-level gnn bias
__device__ __align__(16) float g_outs[2][BVM][512];      // gnn outputs (relu)
__device__ __align__(16) float g_gi[8][BVM][384];        // monitor gi
__device__ __align__(16) float g_seq[10][BV][D_];        // visit-level sequences
__device__ __align__(16) float g_vgi[10][BV][384];       // visit gi
__device__ __align__(16) float g_hbuf[10][B_][D_];       // final hidden per run

// ---------------- helpers ----------------
__device__ __forceinline__ void fma2(u64& c, u64 a, u64 b) {
    asm("fma.rn.f32x2 %0, %1, %2, %0;" : "+l"(c) : "l"(a), "l"(b));
}
__device__ __forceinline__ float sum2(u64 v) {
    float x, y; asm("mov.b64 {%0, %1}, %2;" : "=f"(x), "=f"(y) : "l"(v)); return x + y;
}
__device__ __forceinline__ float tanh_fast(float x) {
    float r; asm("tanh.approx.f32 %0, %1;" : "=f"(r) : "f"(x)); return r;
}
__device__ __forceinline__ float sigm_(float x) { return fmaf(0.5f, tanh_fast(0.5f * x), 0.5f); }

__device__ __forceinline__ unsigned tf32r(float x) {
    unsigned r; asm("cvt.rna.tf32.f32 %0, %1;" : "=r"(r) : "f"(x)); return r;
}

#define MMA_TF32(c, a, b) \
    asm("mma.sync.aligned.m16n8k8.row.col.f32.tf32.tf32.f32 " \
        "{%0,%1,%2,%3},{%4,%5,%6,%7},{%8,%9},{%0,%1,%2,%3};" \
        : "+f"((c)[0]), "+f"((c)[1]), "+f"((c)[2]), "+f"((c)[3]) \
        : "r"((a)[0]), "r"((a)[1]), "r"((a)[2]), "r"((a)[3]), "r"((b)[0]), "r"((b)[1]))

// ---------------- K_pre: gathers + weight prep (incl. tf32 hi/lo) + scalar feats ----------------
__global__ __launch_bounds__(128) void k_pre(
    const int* __restrict__ cc, const int* __restrict__ cp, const int* __restrict__ cd,
    const float* __restrict__ ec, const float* __restrict__ ep, const float* __restrict__ ed,
    const int* __restrict__ li, const int* __restrict__ lv,
    const int* __restrict__ ii, const int* __restrict__ iv,
    const float* __restrict__ eli, const float* __restrict__ elv,
    const float* __restrict__ eii, const float* __restrict__ eiv,
    const float* __restrict__ Ws, const float* __restrict__ Wm,
    const float* __restrict__ mWih, const float* __restrict__ vWih,
    const float* __restrict__ w, const float* __restrict__ a,
    const float* __restrict__ fwW, const float* __restrict__ fwb,
    const float* __restrict__ faW, const float* __restrict__ fab) {
    int bx = blockIdx.x, tid = threadIdx.x;
    if (bx < 768) {
        int bv = bx & 255, ty = bx >> 8, d = tid;
        const int* codes = ((ty == 0) ? cc : ((ty == 1) ? cp : cd)) + bv * C_;
        const float* emb = (ty == 0) ? ec : ((ty == 1) ? ep : ed);
        float s = 0.f;
#pragma unroll 8
        for (int c = 0; c < C_; c++) s += emb[codes[c] * D_ + d];
        g_vis[ty][bv][d] = s;
    } else if (bx < 17152) {
        int i = bx - 768, p = i >> 13, row = i & 8191, d = tid;
        const int* ci = ((p == 0) ? li : ii) + row * CM_;
        const int* cv = ((p == 0) ? lv : iv) + row * CM_;
        const float* ei = (p == 0) ? eli : eii;
        const float* ev = (p == 0) ? elv : eiv;
        float s = 0.f;
#pragma unroll
        for (int c = 0; c < CM_; c++) s += ei[ci[c] * D_ + d] * ev[cv[c] * D_ + d];
        g_mon[p][row][d] = s;
    } else if (bx < 18176) {
        int i = (bx - 17152) * 128 + tid;
        int p = i >> 16, d = (i >> 9) & 127, j5 = i & 511;
        int t = j5 >> 7, j = j5 & 127;
        float v = (t == 0) ? Ws[(p * 4) * 16384 + d * 128 + j]
                           : Wm[(p * 4 + t) * 16384 + d * 128 + j] * (1.f / 3.f);
        float h = __uint_as_float(tf32r(v));
        g_wch[p][j5 * 128 + d] = h;
        g_wcl[p][j5 * 128 + d] = __uint_as_float(tf32r(v - h));
    } else if (bx < 20096) {
        int idx = (bx - 18176) * 128 + tid;   // < 245760
        float v = mWih[idx];
        float h = __uint_as_float(tf32r(v));
        g_mih_h[idx] = h;
        g_mih_l[idx] = __uint_as_float(tf32r(v - h));
    } else if (bx < 21632) {
        int idx = (bx - 20096) * 128 + tid;   // < 196608
        float v = vWih[idx];
        float h = __uint_as_float(tf32r(v));
        g_vih_h[idx] = h;
        g_vih_l[idx] = __uint_as_float(tf32r(v - h));
    } else {
        int i = bx - 21632;
        const float* Wp = (i == 0) ? fwW : faW;
        const float* bp = (i == 0) ? fwb : fab;
        const float* xp = (i == 0) ? w : a;
        for (int idx = tid; idx < 32768; idx += 128) {
            int bv = idx >> 7, d = idx & 127;
            float x = xp[bv];
            g_seq[8 + i][bv][d] = (x != 0.f) ? (x * Wp[d] + bp[d]) : 0.f;
        }
    }
}

// ---------------- K_bias: visit-level gnn bias ----------------
__global__ __launch_bounds__(128) void k_bias(const float* __restrict__ Ws, const float* __restrict__ Wm) {
    __shared__ float sv[3][32][128];
    int blk = blockIdx.x, tid = threadIdx.x;
    int pt = blk >> 3, p = pt >> 2, t = pt & 3;
    int bv0 = (blk & 7) * 32;
    for (int i = tid; i < 3 * 32 * 128; i += 128) {
        int ty = i >> 12, c = (i >> 7) & 31, d = i & 127;
        sv[ty][c][d] = g_vis[ty][bv0 + c][d];
    }
    __syncthreads();
    int j = tid;
    const float* Wsp = Ws + (p * 4 + t) * 16384;
    const float* Wmp = Wm + (p * 4 + t) * 16384;
    float acc[32];
#pragma unroll
    for (int c = 0; c < 32; c++) acc[c] = 0.f;
    for (int d = 0; d < 128; d++) {
        float w2 = Wmp[d * 128 + j] * (1.f / 3.f);
        float w1 = (t == 0) ? 0.f : (Wsp[d * 128 + j] - w2);
#pragma unroll
        for (int c = 0; c < 32; c++) {
            float v0 = sv[0][c][d], v1 = sv[1][c][d], v2 = sv[2][c][d];
            float vs = v0 + v1 + v2;
            float vt = (t == 1) ? v0 : ((t == 2) ? v1 : ((t == 3) ? v2 : 0.f));
            acc[c] = fmaf(w2, vs, fmaf(w1, vt, acc[c]));
        }
    }
    for (int c = 0; c < 32; c++) g_bias[p][bv0 + c][t * 128 + j] = acc[c];
}

// ---------------- Tensor-core GEMM (3xTF32): 128x128 block tile, K-chunk 32 ----------------
// smem 72KB, <=128 regs (launch_bounds 256,2) -> 2 CTAs/SM.
#define GSM_BYTES (4 * 128 * 36 * 4)
__global__ __launch_bounds__(256, 2) void k_gemm(int mode,
                                                 const float* __restrict__ bih_all, const float* __restrict__ vbih_all) {
    extern __shared__ float sm[];
    float* Ah = sm;                 // [128][36]
    float* Al = Ah + 128 * 36;
    float* Wh = Al + 128 * 36;      // [128][36]  (n rows, k cols)
    float* Wl = Wh + 128 * 36;

    const float *A, *Whp, *Wlp, *bias; float* out;
    int lda, K, bshift, relu;
    int n0 = blockIdx.x * 128, j0 = blockIdx.y * 128;
    if (mode == 1) {
        int p = blockIdx.z;
        A = &g_mon[p][0][0]; lda = 128;
        Whp = g_wch[p]; Wlp = g_wcl[p];
        bias = &g_bias[p][0][0]; bshift = 5; K = 512; relu = 1;
        out = &g_outs[p][0][0];
    } else if (mode == 2) {
        int z = blockIdx.z, p = z >> 2, t = z & 3, g = (t == 0) ? p : (t + 1);
        A = &g_outs[p][0][0] + t * 128; lda = 512;
        Whp = g_mih_h + g * 49152; Wlp = g_mih_l + g * 49152;
        bias = bih_all + g * 384; bshift = 30; K = 384; relu = 0;
        out = &g_gi[z][0][0];
    } else {
        int run = n0 >> 8;
        int vi = (run < 8) ? (run >> 2) : (run - 6);
        A = &g_seq[0][0][0]; lda = 128;
        Whp = g_vih_h + vi * 49152; Wlp = g_vih_l + vi * 49152;
        bias = vbih_all + vi * 384; bshift = 30; K = 384; relu = 0;
        out = &g_vgi[0][0][0];
    }

    int tid = threadIdx.x;
    int lane = tid & 31, wid = tid >> 5;
    int gid = lane >> 2, tig = lane & 3;
    int m0w = (wid & 1) * 64, n0w = (wid >> 1) * 32;

    float C[4][4][4];
#pragma unroll
    for (int mt = 0; mt < 4; mt++)
#pragma unroll
        for (int nt = 0; nt < 4; nt++)
#pragma unroll
            for (int q = 0; q < 4; q++) C[mt][nt][q] = 0.f;

    for (int kc = 0; kc < 4; kc++) {
        // load A tile [128][32] -> hi/lo on the fly
#pragma unroll
        for (int it = 0; it < 4; it++) {
            int f4 = tid + 256 * it;
            int r = f4 >> 3, c4 = f4 & 7;
            float4 v = *(const float4*)(A + (n0 + r) * lda + kc * 32 + c4 * 4);
            float h0 = __uint_as_float(tf32r(v.x)), h1 = __uint_as_float(tf32r(v.y));
            float h2 = __uint_as_float(tf32r(v.z)), h3 = __uint_as_float(tf32r(v.w));
            *(float4*)(Ah + r * 36 + c4 * 4) = make_float4(h0, h1, h2, h3);
            *(float4*)(Al + r * 36 + c4 * 4) =
                make_float4(__uint_as_float(tf32r(v.x - h0)), __uint_as_float(tf32r(v.y - h1)),
                            __uint_as_float(tf32r(v.z - h2)), __uint_as_float(tf32r(v.w - h3)));
        }
        // load W tile [128 n][32 k] hi/lo (precomputed)
#pragma unroll
        for (int it = 0; it < 4; it++) {
            int f4 = tid + 256 * it;
            int n = f4 >> 3, k4 = f4 & 7;
            *(float4*)(Wh + n * 36 + k4 * 4) = *(const float4*)(Whp + (j0 + n) * 128 + kc * 32 + k4 * 4);
            *(float4*)(Wl + n * 36 + k4 * 4) = *(const float4*)(Wlp + (j0 + n) * 128 + kc * 32 + k4 * 4);
        }
        __syncthreads();

#pragma unroll
        for (int ks = 0; ks < 4; ks++) {
            int kk = ks * 8;
            unsigned ah[4][4], al[4][4], bh[4][2], bl[4][2];
#pragma unroll
            for (int mt = 0; mt < 4; mt++) {
                const float* ap = Ah + (m0w + 16 * mt + gid) * 36 + kk + tig;
                const float* lp = Al + (m0w + 16 * mt + gid) * 36 + kk + tig;
                ah[mt][0] = __float_as_uint(ap[0]);
                ah[mt][1] = __float_as_uint(ap[8 * 36]);
                ah[mt][2] = __float_as_uint(ap[4]);
                ah[mt][3] = __float_as_uint(ap[8 * 36 + 4]);
                al[mt][0] = __float_as_uint(lp[0]);
                al[mt][1] = __float_as_uint(lp[8 * 36]);
                al[mt][2] = __float_as_uint(lp[4]);
                al[mt][3] = __float_as_uint(lp[8 * 36 + 4]);
            }
#pragma unroll
            for (int nt = 0; nt < 4; nt++) {
                const float* bp = Wh + (n0w + 8 * nt + gid) * 36 + kk + tig;
                const float* lp = Wl + (n0w + 8 * nt + gid) * 36 + kk + tig;
                bh[nt][0] = __float_as_uint(bp[0]);
                bh[nt][1] = __float_as_uint(bp[4]);
                bl[nt][0] = __float_as_uint(lp[0]);
                bl[nt][1] = __float_as_uint(lp[4]);
            }
#pragma unroll
            for (int mt = 0; mt < 4; mt++)
#pragma unroll
                for (int nt = 0; nt < 4; nt++) {
                    MMA_TF32(C[mt][nt], ah[mt], bh[nt]);
                    MMA_TF32(C[mt][nt], ah[mt], bl[nt]);
                    MMA_TF32(C[mt][nt], al[mt], bh[nt]);
                }
        }
        __syncthreads();
    }

#pragma unroll
    for (int mt = 0; mt < 4; mt++) {
        int mrow = n0 + m0w + 16 * mt + gid;
        int bgrp = (mrow >> bshift) * K;
        int bgrp2 = ((mrow + 8) >> bshift) * K;
#pragma unroll
        for (int nt = 0; nt < 4; nt++) {
            int col = j0 + n0w + 8 * nt + 2 * tig;
            float v0 = C[mt][nt][0] + bias[bgrp + col];
            float v1 = C[mt][nt][1] + bias[bgrp + col + 1];
            float v2 = C[mt][nt][2] + bias[bgrp2 + col];
            float v3 = C[mt][nt][3] + bias[bgrp2 + col + 1];
            if (relu) {
                v0 = fmaxf(v0, 0.f); v1 = fmaxf(v1, 0.f);
                v2 = fmaxf(v2, 0.f); v3 = fmaxf(v3, 0.f);
            }
            *(float2*)(out + mrow * K + col) = make_float2(v0, v1);
            *(float2*)(out + (mrow + 8) * K + col) = make_float2(v2, v3);
        }
    }
}

// ---------------- GRU recurrence (templated on seqs/block) ----------------
// Weight staging padded to 385 u64 per d2-row (64 rows): 24640 u64 = 49280 floats.
// Store bank for wsf[(d>>1)*770 + 2j + (d&1)]: (770*(d>>1) + 2j + (d&1)) mod 32
// -> consecutive-thread-conflict-free (j strides 2 within a warp half).
template <int NSEQ, int T, bool MON>
__global__ __launch_bounds__(384, 1) void k_rec(const float* __restrict__ Whh_all,
                                                const float* __restrict__ bhh_all) {
    extern __shared__ float sm[];
    float* wsf = sm;                     // 49280 floats
    float* hs = sm + 49280;              // [NSEQ][128]
    float* gsm = hs + NSEQ * 128;        // [NSEQ][384]
    const u64* ws2 = (const u64*)sm;
    int tid = threadIdx.x, bx = blockIdx.x;

    const float *Whh, *bhh, *gip; float* outp;
    int s0;
    if (MON) {
        int chan = bx >> 4, sgrp = bx & 15;
        int p = chan >> 2, t = chan & 3, g = (t == 0) ? p : (t + 1);
        Whh = Whh_all + g * 49152; bhh = bhh_all + g * 384;
        gip = &g_gi[chan][0][0]; outp = &g_seq[chan][0][0];
        s0 = sgrp * NSEQ;
    } else {
        int run = bx >> 2, sgrp = bx & 3;
        int vi = (run < 8) ? (run >> 2) : (run - 6);
        Whh = Whh_all + vi * 49152; bhh = bhh_all + vi * 384;
        gip = &g_vgi[run][0][0]; outp = &g_hbuf[run][0][0];
        s0 = sgrp * NSEQ;
    }
    for (int i = tid; i < 49152; i += 384) {
        int j = i >> 7, d = i & 127;
        wsf[(d >> 1) * 770 + 2 * j + (d & 1)] = Whh[i];
    }
    for (int i = tid; i < NSEQ * 128; i += 384) hs[i] = 0.f;
    __syncthreads();

    int j = tid;
    float bj = bhh[j];
    constexpr int KP = (NSEQ * 128 + 383) / 384;

    for (int t = 0; t < T; t++) {
        float pr[KP], pz[KP], pn[KP];
#pragma unroll
        for (int k = 0; k < KP; k++) {
            int idx = tid + k * 384;
            if (idx < NSEQ * 128) {
                int s = idx >> 7, d = idx & 127;
                const float* gr = gip + ((s0 + s) * T + t) * 384;
                pr[k] = gr[d]; pz[k] = gr[128 + d]; pn[k] = gr[256 + d];
            }
        }
        u64 acc[NSEQ];
#pragma unroll
        for (int s = 0; s < NSEQ; s++) acc[s] = 0ull;
#pragma unroll 2
        for (int d4 = 0; d4 < 32; d4++) {
            u64 wA = ws2[(2 * d4) * 385 + j];
            u64 wB = ws2[(2 * d4 + 1) * 385 + j];
#pragma unroll
            for (int s = 0; s < NSEQ; s++) {
                double2 hd = ((const double2*)(hs + s * 128))[d4];
                fma2(acc[s], __double_as_longlong(hd.x), wA);
                fma2(acc[s], __double_as_longlong(hd.y), wB);
            }
        }
#pragma unroll
        for (int s = 0; s < NSEQ; s++) gsm[s * 384 + j] = sum2(acc[s]) + bj;
        __syncthreads();
#pragma unroll
        for (int k = 0; k < KP; k++) {
            int idx = tid + k * 384;
            if (idx < NSEQ * 128) {
                int s = idx >> 7, d = idx & 127;
                float rg = sigm_(pr[k] + gsm[s * 384 + d]);
                float zg = sigm_(pz[k] + gsm[s * 384 + 128 + d]);
                float nn = tanh_fast(fmaf(rg, gsm[s * 384 + 256 + d], pn[k]));
                hs[idx] = (1.f - zg) * nn + zg * hs[idx];
            }
        }
        __syncthreads();
    }
    for (int idx = tid; idx < NSEQ * 128; idx += 384) {
        int s = idx >> 7, d = idx & 127;
        outp[(s0 + s) * 128 + d] = hs[idx];
    }
}

// ---------------- head: out = relu(pe) @ W.T + b ----------------
__global__ void k_head(const float* __restrict__ fW, const float* __restrict__ fb,
                       float* __restrict__ out) {
    __shared__ float pe[896];
    int b = blockIdx.x / 10, og0 = (blockIdx.x % 10) * 60;
    int tid = threadIdx.x, lane = tid & 31, wp = tid >> 5;
    const float* H = &g_hbuf[0][0][0];  // [10][16][128]
    for (int i = tid; i < 896; i += 256) {
        int slot = i >> 7, d = i & 127;
        float v;
        if (slot == 0) v = H[0 * 2048 + b * 128 + d];
        else if (slot == 1) v = H[1 * 2048 + b * 128 + d] + H[5 * 2048 + b * 128 + d];
        else if (slot == 2) v = H[2 * 2048 + b * 128 + d] + H[6 * 2048 + b * 128 + d];
        else if (slot == 3) v = H[3 * 2048 + b * 128 + d] + H[7 * 2048 + b * 128 + d];
        else if (slot == 4) v = H[4 * 2048 + b * 128 + d];
        else if (slot == 5) v = H[8 * 2048 + b * 128 + d];
        else v = H[9 * 2048 + b * 128 + d];
        pe[i] = fmaxf(v, 0.f);
    }
    __syncthreads();
    for (int oi = wp; oi < 60; oi += 8) {
        int o = og0 + oi;
        u64 acc = 0ull;
#pragma unroll
        for (int i = 0; i < 7; i++) {
            int k4 = lane + 32 * i;
            float4 wv = __ldg((const float4*)(fW + o * 896) + k4);
            float4 xv = ((const float4*)pe)[k4];
            u64 a01, a23, w01, w23;
            asm("mov.b64 %0, {%1, %2};" : "=l"(a01) : "f"(xv.x), "f"(xv.y));
            asm("mov.b64 %0, {%1, %2};" : "=l"(a23) : "f"(xv.z), "f"(xv.w));
            asm("mov.b64 %0, {%1, %2};" : "=l"(w01) : "f"(wv.x), "f"(wv.y));
            asm("mov.b64 %0, {%1, %2};" : "=l"(w23) : "f"(wv.z), "f"(wv.w));
            fma2(acc, a01, w01);
            fma2(acc, a23, w23);
        }
        float v = sum2(acc);
#pragma unroll
        for (int m = 16; m > 0; m >>= 1) v += __shfl_xor_sync(0xffffffffu, v, m);
        if (lane == 0) out[b * 600 + o] = v + fb[o];
    }
}

// ---------------- launch ----------------
extern "C" void kernel_launch(void* const* d_in, const int* in_sizes, int n_in,
                              void* d_out, int out_size) {
    const int* cc = (const int*)d_in[0];
    const int* cp = (const int*)d_in[1];
    const int* cd = (const int*)d_in[2];
    const int* cli = (const int*)d_in[3];
    const int* clv = (const int*)d_in[4];
    const int* cii = (const int*)d_in[5];
    const int* civ = (const int*)d_in[6];
    const float* wgt = (const float*)d_in[7];
    const float* age = (const float*)d_in[8];
    const float* ec = (const float*)d_in[9];
    const float* ep = (const float*)d_in[10];
    const float* ed = (const float*)d_in[11];
    const float* eli = (const float*)d_in[12];
    const float* elv = (const float*)d_in[13];
    const float* eii = (const float*)d_in[14];
    const float* eiv = (const float*)d_in[15];
    const float* mWih = (const float*)d_in[16];
    const float* mWhh = (const float*)d_in[17];
    const float* mbih = (const float*)d_in[18];
    const float* mbhh = (const float*)d_in[19];
    const float* vWih = (const float*)d_in[20];
    const float* vWhh = (const float*)d_in[21];
    const float* vbih = (const float*)d_in[22];
    const float* vbhh = (const float*)d_in[23];
    const float* gWs = (const float*)d_in[24];
    const float* gWm = (const float*)d_in[25];
    const float* fwW = (const float*)d_in[26];
    const float* fwb = (const float*)d_in[27];
    const float* faW = (const float*)d_in[28];
    const float* fab = (const float*)d_in[29];
    const float* fpW = (const float*)d_in[30];
    const float* fpb = (const float*)d_in[31];
    float* out = (float*)d_out;

    // dyn smem (floats->bytes): mon = (49280 + 2048 + 6144)*4 = 229888; visit = (49280 + 512 + 1536)*4 = 205312
    cudaFuncSetAttribute(k_gemm, cudaFuncAttributeMaxDynamicSharedMemorySize, GSM_BYTES);
    cudaFuncSetAttribute((const void*)k_rec<16, 32, true>, cudaFuncAttributeMaxDynamicSharedMemorySize, 229888);
    cudaFuncSetAttribute((const void*)k_rec<4, 16, false>, cudaFuncAttributeMaxDynamicSharedMemorySize, 205312);

    k_pre<<<21634, 128>>>(cc, cp, cd, ec, ep, ed, cli, clv, cii, civ, eli, elv, eii, eiv,
                          gWs, gWm, mWih, vWih, wgt, age, fwW, fwb, faW, fab);
    k_bias<<<64, 128>>>(gWs, gWm);
    k_gemm<<<dim3(64, 4, 2), 256, GSM_BYTES>>>(1, mbih, vbih);
    k_gemm<<<dim3(64, 3, 8), 256, GSM_BYTES>>>(2, mbih, vbih);
    k_rec<16, 32, true><<<128, 384, 229888>>>(mWhh, mbhh);
    k_gemm<<<dim3(20, 3, 1), 256, GSM_BYTES>>>(3, mbih, vbih);
    k_rec<4, 16, false><<<40, 384, 205312>>>(vWhh, vbhh);
    k_head<<<160, 256>>>(fpW, fpb, out);
}

// round 11
// speedup vs baseline: 1.8564x; 1.0899x over previous
#include <cuda_runtime.h>

typedef unsigned long long u64;

#define B_  16
#define V_  16
#define C_  64
#define M_  32
#define CM_ 16
#define D_  128
#define OUT_ 600
#define BV  256
#define BVM 8192

// ---------------- scratch ----------------
__device__ __align__(16) float g_vis[3][BV][D_];
__device__ __align__(16) float g_mon[2][BVM][D_];
__device__ __align__(16) unsigned g_wbh[2][512 * 64];    // gnn combined W bf16x2-hi [n][k/2]
__device__ __align__(16) unsigned g_wbl[2][512 * 64];    // bf16x2-lo
__device__ __align__(16) unsigned g_mbh[5 * 384 * 64];   // mgru Wih bf16x2-hi [g*384+j][k/2]
__device__ __align__(16) unsigned g_mbl[5 * 384 * 64];
__device__ __align__(16) unsigned g_vbh[4 * 384 * 64];   // vgru Wih bf16x2-hi
__device__ __align__(16) unsigned g_vbl[4 * 384 * 64];
__device__ __align__(16) float g_bias[2][BV][512];       // visit-level gnn bias
__device__ __align__(16) float g_outs[2][BVM][512];      // gnn outputs (relu)
__device__ __align__(16) float g_gi[8][BVM][384];        // monitor gi
__device__ __align__(16) float g_seq[10][BV][D_];        // visit-level sequences
__device__ __align__(16) float g_vgi[10][BV][384];       // visit gi
__device__ __align__(16) float g_hbuf[10][B_][D_];       // final hidden per run

// ---------------- helpers ----------------
__device__ __forceinline__ void fma2(u64& c, u64 a, u64 b) {
    asm("fma.rn.f32x2 %0, %1, %2, %0;" : "+l"(c) : "l"(a), "l"(b));
}
__device__ __forceinline__ float sum2(u64 v) {
    float x, y; asm("mov.b64 {%0, %1}, %2;" : "=f"(x), "=f"(y) : "l"(v)); return x + y;
}
__device__ __forceinline__ float tanh_fast(float x) {
    float r; asm("tanh.approx.f32 %0, %1;" : "=f"(r) : "f"(x)); return r;
}
__device__ __forceinline__ float sigm_(float x) { return fmaf(0.5f, tanh_fast(0.5f * x), 0.5f); }

// pack (lo, hi) floats into bf16x2: low half = lo
__device__ __forceinline__ unsigned bfpair(float lo, float hi) {
    unsigned r; asm("cvt.rn.bf16x2.f32 %0, %1, %2;" : "=r"(r) : "f"(hi), "f"(lo)); return r;
}
__device__ __forceinline__ float bflo(unsigned p) { return __uint_as_float(p << 16); }
__device__ __forceinline__ float bfhi(unsigned p) { return __uint_as_float(p & 0xffff0000u); }

#define MMA_BF16(c, a, b) \
    asm("mma.sync.aligned.m16n8k16.row.col.f32.bf16.bf16.f32 " \
        "{%0,%1,%2,%3},{%4,%5,%6,%7},{%8,%9},{%0,%1,%2,%3};" \
        : "+f"((c)[0]), "+f"((c)[1]), "+f"((c)[2]), "+f"((c)[3]) \
        : "r"((a)[0]), "r"((a)[1]), "r"((a)[2]), "r"((a)[3]), "r"((b)[0]), "r"((b)[1]))

// ---------------- K_pre: gathers + bf16 weight prep + scalar feats ----------------
__global__ __launch_bounds__(128) void k_pre(
    const int* __restrict__ cc, const int* __restrict__ cp, const int* __restrict__ cd,
    const float* __restrict__ ec, const float* __restrict__ ep, const float* __restrict__ ed,
    const int* __restrict__ li, const int* __restrict__ lv,
    const int* __restrict__ ii, const int* __restrict__ iv,
    const float* __restrict__ eli, const float* __restrict__ elv,
    const float* __restrict__ eii, const float* __restrict__ eiv,
    const float* __restrict__ Ws, const float* __restrict__ Wm,
    const float* __restrict__ mWih, const float* __restrict__ vWih,
    const float* __restrict__ w, const float* __restrict__ a,
    const float* __restrict__ fwW, const float* __restrict__ fwb,
    const float* __restrict__ faW, const float* __restrict__ fab) {
    int bx = blockIdx.x, tid = threadIdx.x;
    if (bx < 768) {
        int bv = bx & 255, ty = bx >> 8, d = tid;
        const int* codes = ((ty == 0) ? cc : ((ty == 1) ? cp : cd)) + bv * C_;
        const float* emb = (ty == 0) ? ec : ((ty == 1) ? ep : ed);
        float s = 0.f;
#pragma unroll 8
        for (int c = 0; c < C_; c++) s += emb[codes[c] * D_ + d];
        g_vis[ty][bv][d] = s;
    } else if (bx < 17152) {
        int i = bx - 768, p = i >> 13, row = i & 8191, d = tid;
        const int* ci = ((p == 0) ? li : ii) + row * CM_;
        const int* cv = ((p == 0) ? lv : iv) + row * CM_;
        const float* ei = (p == 0) ? eli : eii;
        const float* ev = (p == 0) ? elv : eiv;
        float s = 0.f;
#pragma unroll
        for (int c = 0; c < CM_; c++) s += ei[ci[c] * D_ + d] * ev[cv[c] * D_ + d];
        g_mon[p][row][d] = s;
    } else if (bx < 17664) {
        // gnn combined weights -> packed bf16x2 hi/lo, [n=512][k2=64]
        int i = (bx - 17152) * 128 + tid;        // < 65536
        int p = i >> 15, rem = i & 32767;
        int k2 = rem >> 9, j5 = rem & 511;
        int t = j5 >> 7, j = j5 & 127;
        const float* src = (t == 0) ? (Ws + (p * 4) * 16384) : (Wm + (p * 4 + t) * 16384);
        float sc = (t == 0) ? 1.f : (1.f / 3.f);
        float v0 = src[(2 * k2) * 128 + j] * sc;
        float v1 = src[(2 * k2 + 1) * 128 + j] * sc;
        unsigned h = bfpair(v0, v1);
        g_wbh[p][j5 * 64 + k2] = h;
        g_wbl[p][j5 * 64 + k2] = bfpair(v0 - bflo(h), v1 - bfhi(h));
    } else if (bx < 18624) {
        int o = (bx - 17664) * 128 + tid;        // < 122880
        float2 v = *(const float2*)(mWih + 2 * o);
        unsigned h = bfpair(v.x, v.y);
        g_mbh[o] = h;
        g_mbl[o] = bfpair(v.x - bflo(h), v.y - bfhi(h));
    } else if (bx < 19392) {
        int o = (bx - 18624) * 128 + tid;        // < 98304
        float2 v = *(const float2*)(vWih + 2 * o);
        unsigned h = bfpair(v.x, v.y);
        g_vbh[o] = h;
        g_vbl[o] = bfpair(v.x - bflo(h), v.y - bfhi(h));
    } else {
        int i = bx - 19392;
        const float* Wp = (i == 0) ? fwW : faW;
        const float* bp = (i == 0) ? fwb : fab;
        const float* xp = (i == 0) ? w : a;
        for (int idx = tid; idx < 32768; idx += 128) {
            int bv = idx >> 7, d = idx & 127;
            float x = xp[bv];
            g_seq[8 + i][bv][d] = (x != 0.f) ? (x * Wp[d] + bp[d]) : 0.f;
        }
    }
}

// ---------------- K_bias: visit-level gnn bias ----------------
__global__ __launch_bounds__(128) void k_bias(const float* __restrict__ Ws, const float* __restrict__ Wm) {
    __shared__ float sv[3][32][128];
    int blk = blockIdx.x, tid = threadIdx.x;
    int pt = blk >> 3, p = pt >> 2, t = pt & 3;
    int bv0 = (blk & 7) * 32;
    for (int i = tid; i < 3 * 32 * 128; i += 128) {
        int ty = i >> 12, c = (i >> 7) & 31, d = i & 127;
        sv[ty][c][d] = g_vis[ty][bv0 + c][d];
    }
    __syncthreads();
    int j = tid;
    const float* Wsp = Ws + (p * 4 + t) * 16384;
    const float* Wmp = Wm + (p * 4 + t) * 16384;
    float acc[32];
#pragma unroll
    for (int c = 0; c < 32; c++) acc[c] = 0.f;
    for (int d = 0; d < 128; d++) {
        float w2 = Wmp[d * 128 + j] * (1.f / 3.f);
        float w1 = (t == 0) ? 0.f : (Wsp[d * 128 + j] - w2);
#pragma unroll
        for (int c = 0; c < 32; c++) {
            float v0 = sv[0][c][d], v1 = sv[1][c][d], v2 = sv[2][c][d];
            float vs = v0 + v1 + v2;
            float vt = (t == 1) ? v0 : ((t == 2) ? v1 : ((t == 3) ? v2 : 0.f));
            acc[c] = fmaf(w2, vs, fmaf(w1, vt, acc[c]));
        }
    }
    for (int c = 0; c < 32; c++) g_bias[p][bv0 + c][t * 128 + j] = acc[c];
}

// ---------------- Tensor-core GEMM (3xBF16 m16n8k16): 128x128 block tile, K-chunk 64 ----------------
// smem 72KB, <=128 regs (launch_bounds 256,2) -> 2 CTAs/SM.
#define GSM_BYTES (4 * 128 * 36 * 4)
__global__ __launch_bounds__(256, 2) void k_gemm(int mode,
                                                 const float* __restrict__ bih_all, const float* __restrict__ vbih_all) {
    extern __shared__ unsigned smu[];
    unsigned* Ah = smu;                 // [128][36] u32 (bf16x2)
    unsigned* Al = Ah + 128 * 36;
    unsigned* Wh = Al + 128 * 36;       // [128 n][36] u32
    unsigned* Wl = Wh + 128 * 36;

    const float *A, *bias; float* out;
    const unsigned *Whp, *Wlp;
    int lda, K, bshift, relu;
    int n0 = blockIdx.x * 128, j0 = blockIdx.y * 128;
    if (mode == 1) {
        int p = blockIdx.z;
        A = &g_mon[p][0][0]; lda = 128;
        Whp = g_wbh[p]; Wlp = g_wbl[p];
        bias = &g_bias[p][0][0]; bshift = 5; K = 512; relu = 1;
        out = &g_outs[p][0][0];
    } else if (mode == 2) {
        int z = blockIdx.z, p = z >> 2, t = z & 3, g = (t == 0) ? p : (t + 1);
        A = &g_outs[p][0][0] + t * 128; lda = 512;
        Whp = g_mbh + g * 24576; Wlp = g_mbl + g * 24576;
        bias = bih_all + g * 384; bshift = 30; K = 384; relu = 0;
        out = &g_gi[z][0][0];
    } else {
        int run = n0 >> 8;
        int vi = (run < 8) ? (run >> 2) : (run - 6);
        A = &g_seq[0][0][0]; lda = 128;
        Whp = g_vbh + vi * 24576; Wlp = g_vbl + vi * 24576;
        bias = vbih_all + vi * 384; bshift = 30; K = 384; relu = 0;
        out = &g_vgi[0][0][0];
    }

    int tid = threadIdx.x;
    int lane = tid & 31, wid = tid >> 5;
    int gid = lane >> 2, tig = lane & 3;
    int m0w = (wid & 1) * 64, n0w = (wid >> 1) * 32;

    float C[4][4][4];
#pragma unroll
    for (int mt = 0; mt < 4; mt++)
#pragma unroll
        for (int nt = 0; nt < 4; nt++)
#pragma unroll
            for (int q = 0; q < 4; q++) C[mt][nt][q] = 0.f;

    for (int kc = 0; kc < 2; kc++) {
        // A tile [128 rows][64 f32] -> bf16x2 hi/lo, on-the-fly split
#pragma unroll
        for (int it = 0; it < 8; it++) {
            int f4 = tid + 256 * it;           // 0..2047
            int r = f4 >> 4, c4 = f4 & 15;     // 16 float4 per row-chunk
            float4 v = *(const float4*)(A + (n0 + r) * lda + kc * 64 + c4 * 4);
            unsigned h01 = bfpair(v.x, v.y), h23 = bfpair(v.z, v.w);
            unsigned l01 = bfpair(v.x - bflo(h01), v.y - bfhi(h01));
            unsigned l23 = bfpair(v.z - bflo(h23), v.w - bfhi(h23));
            *(u64*)(Ah + r * 36 + c4 * 2) = (u64)h01 | ((u64)h23 << 32);
            *(u64*)(Al + r * 36 + c4 * 2) = (u64)l01 | ((u64)l23 << 32);
        }
        // W tile [128 n][32 u32] hi/lo (pre-packed)
#pragma unroll
        for (int it = 0; it < 8; it++) {
            int u2 = tid + 256 * it;           // 0..2047
            int n = u2 >> 4, c2 = u2 & 15;
            uint2 sh = *(const uint2*)(Whp + (j0 + n) * 64 + kc * 32 + c2 * 2);
            uint2 sl = *(const uint2*)(Wlp + (j0 + n) * 64 + kc * 32 + c2 * 2);
            *(u64*)(Wh + n * 36 + c2 * 2) = (u64)sh.x | ((u64)sh.y << 32);
            *(u64*)(Wl + n * 36 + c2 * 2) = (u64)sl.x | ((u64)sl.y << 32);
        }
        __syncthreads();

#pragma unroll
        for (int ks = 0; ks < 4; ks++) {
            int kk = ks * 8;   // 8 u32 words = k16
            unsigned ah[4][4], al[4][4], bh[4][2], bl[4][2];
#pragma unroll
            for (int mt = 0; mt < 4; mt++) {
                const unsigned* ap = Ah + (m0w + 16 * mt + gid) * 36 + kk + tig;
                const unsigned* lp = Al + (m0w + 16 * mt + gid) * 36 + kk + tig;
                ah[mt][0] = ap[0];
                ah[mt][1] = ap[8 * 36];
                ah[mt][2] = ap[4];
                ah[mt][3] = ap[8 * 36 + 4];
                al[mt][0] = lp[0];
                al[mt][1] = lp[8 * 36];
                al[mt][2] = lp[4];
                al[mt][3] = lp[8 * 36 + 4];
            }
#pragma unroll
            for (int nt = 0; nt < 4; nt++) {
                const unsigned* bp = Wh + (n0w + 8 * nt + gid) * 36 + kk + tig;
                const unsigned* lp = Wl + (n0w + 8 * nt + gid) * 36 + kk + tig;
                bh[nt][0] = bp[0];
                bh[nt][1] = bp[4];
                bl[nt][0] = lp[0];
                bl[nt][1] = lp[4];
            }
#pragma unroll
            for (int mt = 0; mt < 4; mt++)
#pragma unroll
                for (int nt = 0; nt < 4; nt++) {
                    MMA_BF16(C[mt][nt], ah[mt], bh[nt]);
                    MMA_BF16(C[mt][nt], ah[mt], bl[nt]);
                    MMA_BF16(C[mt][nt], al[mt], bh[nt]);
                }
        }
        __syncthreads();
    }

#pragma unroll
    for (int mt = 0; mt < 4; mt++) {
        int mrow = n0 + m0w + 16 * mt + gid;
        int bgrp = (mrow >> bshift) * K;
        int bgrp2 = ((mrow + 8) >> bshift) * K;
#pragma unroll
        for (int nt = 0; nt < 4; nt++) {
            int col = j0 + n0w + 8 * nt + 2 * tig;
            float v0 = C[mt][nt][0] + bias[bgrp + col];
            float v1 = C[mt][nt][1] + bias[bgrp + col + 1];
            float v2 = C[mt][nt][2] + bias[bgrp2 + col];
            float v3 = C[mt][nt][3] + bias[bgrp2 + col + 1];
            if (relu) {
                v0 = fmaxf(v0, 0.f); v1 = fmaxf(v1, 0.f);
                v2 = fmaxf(v2, 0.f); v3 = fmaxf(v3, 0.f);
            }
            *(float2*)(out + mrow * K + col) = make_float2(v0, v1);
            *(float2*)(out + (mrow + 8) * K + col) = make_float2(v2, v3);
        }
    }
}

// ---------------- GRU recurrence (templated on seqs/block) ----------------
// Weight staging padded to 385 u64 per d2-row (64 rows): 24640 u64 = 49280 floats.
template <int NSEQ, int T, bool MON>
__global__ __launch_bounds__(384, 1) void k_rec(const float* __restrict__ Whh_all,
                                                const float* __restrict__ bhh_all) {
    extern __shared__ float sm[];
    float* wsf = sm;                     // 49280 floats
    float* hs = sm + 49280;              // [NSEQ][128]
    float* gsm = hs + NSEQ * 128;        // [NSEQ][384]
    const u64* ws2 = (const u64*)sm;
    int tid = threadIdx.x, bx = blockIdx.x;

    const float *Whh, *bhh, *gip; float* outp;
    int s0;
    if (MON) {
        int chan = bx >> 4, sgrp = bx & 15;
        int p = chan >> 2, t = chan & 3, g = (t == 0) ? p : (t + 1);
        Whh = Whh_all + g * 49152; bhh = bhh_all + g * 384;
        gip = &g_gi[chan][0][0]; outp = &g_seq[chan][0][0];
        s0 = sgrp * NSEQ;
    } else {
        int run = bx >> 2, sgrp = bx & 3;
        int vi = (run < 8) ? (run >> 2) : (run - 6);
        Whh = Whh_all + vi * 49152; bhh = bhh_all + vi * 384;
        gip = &g_vgi[run][0][0]; outp = &g_hbuf[run][0][0];
        s0 = sgrp * NSEQ;
    }
    for (int i = tid; i < 49152; i += 384) {
        int j = i >> 7, d = i & 127;
        wsf[(d >> 1) * 770 + 2 * j + (d & 1)] = Whh[i];
    }
    for (int i = tid; i < NSEQ * 128; i += 384) hs[i] = 0.f;
    __syncthreads();

    int j = tid;
    float bj = bhh[j];
    constexpr int KP = (NSEQ * 128 + 383) / 384;

    for (int t = 0; t < T; t++) {
        float pr[KP], pz[KP], pn[KP];
#pragma unroll
        for (int k = 0; k < KP; k++) {
            int idx = tid + k * 384;
            if (idx < NSEQ * 128) {
                int s = idx >> 7, d = idx & 127;
                const float* gr = gip + ((s0 + s) * T + t) * 384;
                pr[k] = gr[d]; pz[k] = gr[128 + d]; pn[k] = gr[256 + d];
            }
        }
        u64 acc[NSEQ];
#pragma unroll
        for (int s = 0; s < NSEQ; s++) acc[s] = 0ull;
#pragma unroll 2
        for (int d4 = 0; d4 < 32; d4++) {
            u64 wA = ws2[(2 * d4) * 385 + j];
            u64 wB = ws2[(2 * d4 + 1) * 385 + j];
#pragma unroll
            for (int s = 0; s < NSEQ; s++) {
                double2 hd = ((const double2*)(hs + s * 128))[d4];
                fma2(acc[s], __double_as_longlong(hd.x), wA);
                fma2(acc[s], __double_as_longlong(hd.y), wB);
            }
        }
#pragma unroll
        for (int s = 0; s < NSEQ; s++) gsm[s * 384 + j] = sum2(acc[s]) + bj;
        __syncthreads();
#pragma unroll
        for (int k = 0; k < KP; k++) {
            int idx = tid + k * 384;
            if (idx < NSEQ * 128) {
                int s = idx >> 7, d = idx & 127;
                float rg = sigm_(pr[k] + gsm[s * 384 + d]);
                float zg = sigm_(pz[k] + gsm[s * 384 + 128 + d]);
                float nn = tanh_fast(fmaf(rg, gsm[s * 384 + 256 + d], pn[k]));
                hs[idx] = (1.f - zg) * nn + zg * hs[idx];
            }
        }
        __syncthreads();
    }
    for (int idx = tid; idx < NSEQ * 128; idx += 384) {
        int s = idx >> 7, d = idx & 127;
        outp[(s0 + s) * 128 + d] = hs[idx];
    }
}

// ---------------- head: out = relu(pe) @ W.T + b ----------------
__global__ void k_head(const float* __restrict__ fW, const float* __restrict__ fb,
                       float* __restrict__ out) {
    __shared__ float pe[896];
    int b = blockIdx.x / 10, og0 = (blockIdx.x % 10) * 60;
    int tid = threadIdx.x, lane = tid & 31, wp = tid >> 5;
    const float* H = &g_hbuf[0][0][0];  // [10][16][128]
    for (int i = tid; i < 896; i += 256) {
        int slot = i >> 7, d = i & 127;
        float v;
        if (slot == 0) v = H[0 * 2048 + b * 128 + d];
        else if (slot == 1) v = H[1 * 2048 + b * 128 + d] + H[5 * 2048 + b * 128 + d];
        else if (slot == 2) v = H[2 * 2048 + b * 128 + d] + H[6 * 2048 + b * 128 + d];
        else if (slot == 3) v = H[3 * 2048 + b * 128 + d] + H[7 * 2048 + b * 128 + d];
        else if (slot == 4) v = H[4 * 2048 + b * 128 + d];
        else if (slot == 5) v = H[8 * 2048 + b * 128 + d];
        else v = H[9 * 2048 + b * 128 + d];
        pe[i] = fmaxf(v, 0.f);
    }
    __syncthreads();
    for (int oi = wp; oi < 60; oi += 8) {
        int o = og0 + oi;
        u64 acc = 0ull;
#pragma unroll
        for (int i = 0; i < 7; i++) {
            int k4 = lane + 32 * i;
            float4 wv = __ldg((const float4*)(fW + o * 896) + k4);
            float4 xv = ((const float4*)pe)[k4];
            u64 a01, a23, w01, w23;
            asm("mov.b64 %0, {%1, %2};" : "=l"(a01) : "f"(xv.x), "f"(xv.y));
            asm("mov.b64 %0, {%1, %2};" : "=l"(a23) : "f"(xv.z), "f"(xv.w));
            asm("mov.b64 %0, {%1, %2};" : "=l"(w01) : "f"(wv.x), "f"(wv.y));
            asm("mov.b64 %0, {%1, %2};" : "=l"(w23) : "f"(wv.z), "f"(wv.w));
            fma2(acc, a01, w01);
            fma2(acc, a23, w23);
        }
        float v = sum2(acc);
#pragma unroll
        for (int m = 16; m > 0; m >>= 1) v += __shfl_xor_sync(0xffffffffu, v, m);
        if (lane == 0) out[b * 600 + o] = v + fb[o];
    }
}

// ---------------- launch ----------------
extern "C" void kernel_launch(void* const* d_in, const int* in_sizes, int n_in,
                              void* d_out, int out_size) {
    const int* cc = (const int*)d_in[0];
    const int* cp = (const int*)d_in[1];
    const int* cd = (const int*)d_in[2];
    const int* cli = (const int*)d_in[3];
    const int* clv = (const int*)d_in[4];
    const int* cii = (const int*)d_in[5];
    const int* civ = (const int*)d_in[6];
    const float* wgt = (const float*)d_in[7];
    const float* age = (const float*)d_in[8];
    const float* ec = (const float*)d_in[9];
    const float* ep = (const float*)d_in[10];
    const float* ed = (const float*)d_in[11];
    const float* eli = (const float*)d_in[12];
    const float* elv = (const float*)d_in[13];
    const float* eii = (const float*)d_in[14];
    const float* eiv = (const float*)d_in[15];
    const float* mWih = (const float*)d_in[16];
    const float* mWhh = (const float*)d_in[17];
    const float* mbih = (const float*)d_in[18];
    const float* mbhh = (const float*)d_in[19];
    const float* vWih = (const float*)d_in[20];
    const float* vWhh = (const float*)d_in[21];
    const float* vbih = (const float*)d_in[22];
    const float* vbhh = (const float*)d_in[23];
    const float* gWs = (const float*)d_in[24];
    const float* gWm = (const float*)d_in[25];
    const float* fwW = (const float*)d_in[26];
    const float* fwb = (const float*)d_in[27];
    const float* faW = (const float*)d_in[28];
    const float* fab = (const float*)d_in[29];
    const float* fpW = (const float*)d_in[30];
    const float* fpb = (const float*)d_in[31];
    float* out = (float*)d_out;

    cudaFuncSetAttribute(k_gemm, cudaFuncAttributeMaxDynamicSharedMemorySize, GSM_BYTES);
    cudaFuncSetAttribute((const void*)k_rec<16, 32, true>, cudaFuncAttributeMaxDynamicSharedMemorySize, 229888);
    cudaFuncSetAttribute((const void*)k_rec<4, 16, false>, cudaFuncAttributeMaxDynamicSharedMemorySize, 205312);

    k_pre<<<19394, 128>>>(cc, cp, cd, ec, ep, ed, cli, clv, cii, civ, eli, elv, eii, eiv,
                          gWs, gWm, mWih, vWih, wgt, age, fwW, fwb, faW, fab);
    k_bias<<<64, 128>>>(gWs, gWm);
    k_gemm<<<dim3(64, 4, 2), 256, GSM_BYTES>>>(1, mbih, vbih);
    k_gemm<<<dim3(64, 3, 8), 256, GSM_BYTES>>>(2, mbih, vbih);
    k_rec<16, 32, true><<<128, 384, 229888>>>(mWhh, mbhh);
    k_gemm<<<dim3(20, 3, 1), 256, GSM_BYTES>>>(3, mbih, vbih);
    k_rec<4, 16, false><<<40, 384, 205312>>>(vWhh, vbhh);
    k_head<<<160, 256>>>(fpW, fpb, out);
}

// round 13
// speedup vs baseline: 2.5460x; 1.3715x over previous
#include <cuda_runtime.h>

typedef unsigned long long u64;

#define B_  16
#define V_  16
#define C_  64
#define M_  32
#define CM_ 16
#define D_  128
#define OUT_ 600
#define BV  256
#define BVM 8192

// ---------------- scratch ----------------
__device__ __align__(16) float g_vis[3][BV][D_];
__device__ __align__(16) float g_mon[2][BVM][D_];
__device__ __align__(16) unsigned g_wbh[2][512 * 64];    // gnn combined W bf16x2-hi [n][k/2]
__device__ __align__(16) unsigned g_wbl[2][512 * 64];    // bf16x2-lo
__device__ __align__(16) unsigned g_mbh[5 * 384 * 64];   // mgru Wih bf16x2-hi
__device__ __align__(16) unsigned g_mbl[5 * 384 * 64];
__device__ __align__(16) unsigned g_vbh[4 * 384 * 64];   // vgru Wih bf16x2-hi
__device__ __align__(16) unsigned g_vbl[4 * 384 * 64];
__device__ __align__(16) unsigned g_hhh[5 * 384 * 64];   // mgru Whh bf16x2-hi
__device__ __align__(16) unsigned g_hhl[5 * 384 * 64];   // mgru Whh bf16x2-lo
__device__ __align__(16) float g_bias[2][BV][512];       // visit-level gnn bias
__device__ __align__(16) float g_outs[2][BVM][512];      // gnn outputs (relu)
__device__ __align__(16) float g_gi[8][BVM][384];        // monitor gi
__device__ __align__(16) float g_seq[10][BV][D_];        // visit-level sequences
__device__ __align__(16) float g_vgi[10][BV][384];       // visit gi
__device__ __align__(16) float g_hbuf[10][B_][D_];       // final hidden per run

// ---------------- helpers ----------------
__device__ __forceinline__ void fma2(u64& c, u64 a, u64 b) {
    asm("fma.rn.f32x2 %0, %1, %2, %0;" : "+l"(c) : "l"(a), "l"(b));
}
__device__ __forceinline__ float sum2(u64 v) {
    float x, y; asm("mov.b64 {%0, %1}, %2;" : "=f"(x), "=f"(y) : "l"(v)); return x + y;
}
__device__ __forceinline__ float tanh_fast(float x) {
    float r; asm("tanh.approx.f32 %0, %1;" : "=f"(r) : "f"(x)); return r;
}
__device__ __forceinline__ float sigm_(float x) { return fmaf(0.5f, tanh_fast(0.5f * x), 0.5f); }

// pack (lo, hi) floats into bf16x2: low half = first arg
__device__ __forceinline__ unsigned bfpair(float lo, float hi) {
    unsigned r; asm("cvt.rn.bf16x2.f32 %0, %1, %2;" : "=r"(r) : "f"(hi), "f"(lo)); return r;
}
__device__ __forceinline__ float bflo(unsigned p) { return __uint_as_float(p << 16); }
__device__ __forceinline__ float bfhi(unsigned p) { return __uint_as_float(p & 0xffff0000u); }

#define MMA_BF16(c, a, b) \
    asm("mma.sync.aligned.m16n8k16.row.col.f32.bf16.bf16.f32 " \
        "{%0,%1,%2,%3},{%4,%5,%6,%7},{%8,%9},{%0,%1,%2,%3};" \
        : "+f"((c)[0]), "+f"((c)[1]), "+f"((c)[2]), "+f"((c)[3]) \
        : "r"((a)[0]), "r"((a)[1]), "r"((a)[2]), "r"((a)[3]), "r"((b)[0]), "r"((b)[1]))

// ---------------- K_pre: gathers + bf16 weight prep + scalar feats ----------------
__global__ __launch_bounds__(128) void k_pre(
    const int* __restrict__ cc, const int* __restrict__ cp, const int* __restrict__ cd,
    const float* __restrict__ ec, const float* __restrict__ ep, const float* __restrict__ ed,
    const int* __restrict__ li, const int* __restrict__ lv,
    const int* __restrict__ ii, const int* __restrict__ iv,
    const float* __restrict__ eli, const float* __restrict__ elv,
    const float* __restrict__ eii, const float* __restrict__ eiv,
    const float* __restrict__ Ws, const float* __restrict__ Wm,
    const float* __restrict__ mWih, const float* __restrict__ vWih,
    const float* __restrict__ mWhh,
    const float* __restrict__ w, const float* __restrict__ a,
    const float* __restrict__ fwW, const float* __restrict__ fwb,
    const float* __restrict__ faW, const float* __restrict__ fab) {
    int bx = blockIdx.x, tid = threadIdx.x;
    if (bx < 768) {
        int bv = bx & 255, ty = bx >> 8, d = tid;
        const int* codes = ((ty == 0) ? cc : ((ty == 1) ? cp : cd)) + bv * C_;
        const float* emb = (ty == 0) ? ec : ((ty == 1) ? ep : ed);
        float s = 0.f;
#pragma unroll 8
        for (int c = 0; c < C_; c++) s += emb[codes[c] * D_ + d];
        g_vis[ty][bv][d] = s;
    } else if (bx < 17152) {
        int i = bx - 768, p = i >> 13, row = i & 8191, d = tid;
        const int* ci = ((p == 0) ? li : ii) + row * CM_;
        const int* cv = ((p == 0) ? lv : iv) + row * CM_;
        const float* ei = (p == 0) ? eli : eii;
        const float* ev = (p == 0) ? elv : eiv;
        float s = 0.f;
#pragma unroll
        for (int c = 0; c < CM_; c++) s += ei[ci[c] * D_ + d] * ev[cv[c] * D_ + d];
        g_mon[p][row][d] = s;
    } else if (bx < 17664) {
        // gnn combined weights -> packed bf16x2 hi/lo, [n=512][k2=64]
        int i = (bx - 17152) * 128 + tid;        // < 65536
        int p = i >> 15, rem = i & 32767;
        int k2 = rem >> 9, j5 = rem & 511;
        int t = j5 >> 7, j = j5 & 127;
        const float* src = (t == 0) ? (Ws + (p * 4) * 16384) : (Wm + (p * 4 + t) * 16384);
        float sc = (t == 0) ? 1.f : (1.f / 3.f);
        float v0 = src[(2 * k2) * 128 + j] * sc;
        float v1 = src[(2 * k2 + 1) * 128 + j] * sc;
        unsigned h = bfpair(v0, v1);
        g_wbh[p][j5 * 64 + k2] = h;
        g_wbl[p][j5 * 64 + k2] = bfpair(v0 - bflo(h), v1 - bfhi(h));
    } else if (bx < 18624) {
        int o = (bx - 17664) * 128 + tid;        // < 122880
        float2 v = *(const float2*)(mWih + 2 * o);
        unsigned h = bfpair(v.x, v.y);
        g_mbh[o] = h;
        g_mbl[o] = bfpair(v.x - bflo(h), v.y - bfhi(h));
    } else if (bx < 19392) {
        int o = (bx - 18624) * 128 + tid;        // < 98304
        float2 v = *(const float2*)(vWih + 2 * o);
        unsigned h = bfpair(v.x, v.y);
        g_vbh[o] = h;
        g_vbl[o] = bfpair(v.x - bflo(h), v.y - bfhi(h));
    } else if (bx < 20352) {
        int o = (bx - 19392) * 128 + tid;        // < 122880
        float2 v = *(const float2*)(mWhh + 2 * o);
        unsigned h = bfpair(v.x, v.y);
        g_hhh[o] = h;
        g_hhl[o] = bfpair(v.x - bflo(h), v.y - bfhi(h));
    } else {
        int i = bx - 20352;
        const float* Wp = (i == 0) ? fwW : faW;
        const float* bp = (i == 0) ? fwb : fab;
        const float* xp = (i == 0) ? w : a;
        for (int idx = tid; idx < 32768; idx += 128) {
            int bv = idx >> 7, d = idx & 127;
            float x = xp[bv];
            g_seq[8 + i][bv][d] = (x != 0.f) ? (x * Wp[d] + bp[d]) : 0.f;
        }
    }
}

// ---------------- K_bias: visit-level gnn bias ----------------
__global__ __launch_bounds__(128) void k_bias(const float* __restrict__ Ws, const float* __restrict__ Wm) {
    __shared__ float sv[3][32][128];
    int blk = blockIdx.x, tid = threadIdx.x;
    int pt = blk >> 3, p = pt >> 2, t = pt & 3;
    int bv0 = (blk & 7) * 32;
    for (int i = tid; i < 3 * 32 * 128; i += 128) {
        int ty = i >> 12, c = (i >> 7) & 31, d = i & 127;
        sv[ty][c][d] = g_vis[ty][bv0 + c][d];
    }
    __syncthreads();
    int j = tid;
    const float* Wsp = Ws + (p * 4 + t) * 16384;
    const float* Wmp = Wm + (p * 4 + t) * 16384;
    float acc[32];
#pragma unroll
    for (int c = 0; c < 32; c++) acc[c] = 0.f;
    for (int d = 0; d < 128; d++) {
        float w2 = Wmp[d * 128 + j] * (1.f / 3.f);
        float w1 = (t == 0) ? 0.f : (Wsp[d * 128 + j] - w2);
#pragma unroll
        for (int c = 0; c < 32; c++) {
            float v0 = sv[0][c][d], v1 = sv[1][c][d], v2 = sv[2][c][d];
            float vs = v0 + v1 + v2;
            float vt = (t == 1) ? v0 : ((t == 2) ? v1 : ((t == 3) ? v2 : 0.f));
            acc[c] = fmaf(w2, vs, fmaf(w1, vt, acc[c]));
        }
    }
    for (int c = 0; c < 32; c++) g_bias[p][bv0 + c][t * 128 + j] = acc[c];
}

// ---------------- Tensor-core GEMM (3xBF16 m16n8k16): 128x128 block tile ----------------
#define GSM_BYTES (4 * 128 * 36 * 4)
__global__ __launch_bounds__(256, 2) void k_gemm(int mode,
                                                 const float* __restrict__ bih_all, const float* __restrict__ vbih_all) {
    extern __shared__ unsigned smu[];
    unsigned* Ah = smu;                 // [128][36] u32 (bf16x2)
    unsigned* Al = Ah + 128 * 36;
    unsigned* Wh = Al + 128 * 36;       // [128 n][36] u32
    unsigned* Wl = Wh + 128 * 36;

    const float *A, *bias; float* out;
    const unsigned *Whp, *Wlp;
    int lda, K, bshift, relu;
    int n0 = blockIdx.x * 128, j0 = blockIdx.y * 128;
    if (mode == 1) {
        int p = blockIdx.z;
        A = &g_mon[p][0][0]; lda = 128;
        Whp = g_wbh[p]; Wlp = g_wbl[p];
        bias = &g_bias[p][0][0]; bshift = 5; K = 512; relu = 1;
        out = &g_outs[p][0][0];
    } else if (mode == 2) {
        int z = blockIdx.z, p = z >> 2, t = z & 3, g = (t == 0) ? p : (t + 1);
        A = &g_outs[p][0][0] + t * 128; lda = 512;
        Whp = g_mbh + g * 24576; Wlp = g_mbl + g * 24576;
        bias = bih_all + g * 384; bshift = 30; K = 384; relu = 0;
        out = &g_gi[z][0][0];
    } else {
        int run = n0 >> 8;
        int vi = (run < 8) ? (run >> 2) : (run - 6);
        A = &g_seq[0][0][0]; lda = 128;
        Whp = g_vbh + vi * 24576; Wlp = g_vbl + vi * 24576;
        bias = vbih_all + vi * 384; bshift = 30; K = 384; relu = 0;
        out = &g_vgi[0][0][0];
    }

    int tid = threadIdx.x;
    int lane = tid & 31, wid = tid >> 5;
    int gid = lane >> 2, tig = lane & 3;
    int m0w = (wid & 1) * 64, n0w = (wid >> 1) * 32;

    float C[4][4][4];
#pragma unroll
    for (int mt = 0; mt < 4; mt++)
#pragma unroll
        for (int nt = 0; nt < 4; nt++)
#pragma unroll
            for (int q = 0; q < 4; q++) C[mt][nt][q] = 0.f;

    for (int kc = 0; kc < 2; kc++) {
#pragma unroll
        for (int it = 0; it < 8; it++) {
            int f4 = tid + 256 * it;
            int r = f4 >> 4, c4 = f4 & 15;
            float4 v = *(const float4*)(A + (n0 + r) * lda + kc * 64 + c4 * 4);
            unsigned h01 = bfpair(v.x, v.y), h23 = bfpair(v.z, v.w);
            unsigned l01 = bfpair(v.x - bflo(h01), v.y - bfhi(h01));
            unsigned l23 = bfpair(v.z - bflo(h23), v.w - bfhi(h23));
            *(u64*)(Ah + r * 36 + c4 * 2) = (u64)h01 | ((u64)h23 << 32);
            *(u64*)(Al + r * 36 + c4 * 2) = (u64)l01 | ((u64)l23 << 32);
        }
#pragma unroll
        for (int it = 0; it < 8; it++) {
            int u2 = tid + 256 * it;
            int n = u2 >> 4, c2 = u2 & 15;
            uint2 sh = *(const uint2*)(Whp + (j0 + n) * 64 + kc * 32 + c2 * 2);
            uint2 sl = *(const uint2*)(Wlp + (j0 + n) * 64 + kc * 32 + c2 * 2);
            *(u64*)(Wh + n * 36 + c2 * 2) = (u64)sh.x | ((u64)sh.y << 32);
            *(u64*)(Wl + n * 36 + c2 * 2) = (u64)sl.x | ((u64)sl.y << 32);
        }
        __syncthreads();

#pragma unroll
        for (int ks = 0; ks < 4; ks++) {
            int kk = ks * 8;
            unsigned ah[4][4], al[4][4], bh[4][2], bl[4][2];
#pragma unroll
            for (int mt = 0; mt < 4; mt++) {
                const unsigned* ap = Ah + (m0w + 16 * mt + gid) * 36 + kk + tig;
                const unsigned* lp = Al + (m0w + 16 * mt + gid) * 36 + kk + tig;
                ah[mt][0] = ap[0];
                ah[mt][1] = ap[8 * 36];
                ah[mt][2] = ap[4];
                ah[mt][3] = ap[8 * 36 + 4];
                al[mt][0] = lp[0];
                al[mt][1] = lp[8 * 36];
                al[mt][2] = lp[4];
                al[mt][3] = lp[8 * 36 + 4];
            }
#pragma unroll
            for (int nt = 0; nt < 4; nt++) {
                const unsigned* bp = Wh + (n0w + 8 * nt + gid) * 36 + kk + tig;
                const unsigned* lp = Wl + (n0w + 8 * nt + gid) * 36 + kk + tig;
                bh[nt][0] = bp[0];
                bh[nt][1] = bp[4];
                bl[nt][0] = lp[0];
                bl[nt][1] = lp[4];
            }
#pragma unroll
            for (int mt = 0; mt < 4; mt++)
#pragma unroll
                for (int nt = 0; nt < 4; nt++) {
                    MMA_BF16(C[mt][nt], ah[mt], bh[nt]);
                    MMA_BF16(C[mt][nt], ah[mt], bl[nt]);
                    MMA_BF16(C[mt][nt], al[mt], bh[nt]);
                }
        }
        __syncthreads();
    }

#pragma unroll
    for (int mt = 0; mt < 4; mt++) {
        int mrow = n0 + m0w + 16 * mt + gid;
        int bgrp = (mrow >> bshift) * K;
        int bgrp2 = ((mrow + 8) >> bshift) * K;
#pragma unroll
        for (int nt = 0; nt < 4; nt++) {
            int col = j0 + n0w + 8 * nt + 2 * tig;
            float v0 = C[mt][nt][0] + bias[bgrp + col];
            float v1 = C[mt][nt][1] + bias[bgrp + col + 1];
            float v2 = C[mt][nt][2] + bias[bgrp2 + col];
            float v3 = C[mt][nt][3] + bias[bgrp2 + col + 1];
            if (relu) {
                v0 = fmaxf(v0, 0.f); v1 = fmaxf(v1, 0.f);
                v2 = fmaxf(v2, 0.f); v3 = fmaxf(v3, 0.f);
            }
            *(float2*)(out + mrow * K + col) = make_float2(v0, v1);
            *(float2*)(out + (mrow + 8) * K + col) = make_float2(v2, v3);
        }
    }
}

// ---------------- monitor GRU recurrence on tensor cores (3xBF16) ----------------
// Per CTA: 16 seqs; per step gates[16][384] = h[16][128] @ Whh^T via m16n8k16.
// Whh-hi in smem [384][68] u32; Whh-lo fragments in 64 regs/thread.
#define RSM_BYTES 146176
__global__ __launch_bounds__(384, 1) void k_rec_mma(const float* __restrict__ bhh_all) {
    extern __shared__ unsigned smu[];
    unsigned* Bh = smu;                    // [384][68] u32
    unsigned* Ah = smu + 26112;            // [16][68]
    unsigned* Al = Ah + 1088;              // [16][68]
    float* hs = (float*)(smu + 28288);     // [16][128]
    float* gsm = hs + 2048;                // [16][388]
    int tid = threadIdx.x, bx = blockIdx.x;
    int chan = bx >> 4, sgrp = bx & 15;
    int p = chan >> 2, tt = chan & 3, g = (tt == 0) ? p : (tt + 1);
    const float* bhh = bhh_all + g * 384;
    const float* gip = &g_gi[chan][0][0];
    float* outp = &g_seq[chan][0][0];
    int s0 = sgrp * 16;

    for (int i = tid; i < 24576; i += 384) Bh[(i >> 6) * 68 + (i & 63)] = g_hhh[g * 24576 + i];
    for (int i = tid; i < 2048; i += 384) hs[i] = 0.f;

    int lane = tid & 31, wid = tid >> 5;
    int gid = lane >> 2, tig = lane & 3;
    int n0w = wid * 32;

    unsigned blr[4][8][2];
#pragma unroll
    for (int nt = 0; nt < 4; nt++) {
        int col = n0w + 8 * nt + gid;
#pragma unroll
        for (int kk = 0; kk < 8; kk++) {
            blr[nt][kk][0] = g_hhl[g * 24576 + col * 64 + kk * 8 + tig];
            blr[nt][kk][1] = g_hhl[g * 24576 + col * 64 + kk * 8 + tig + 4];
        }
    }
    float bia[4][2];
#pragma unroll
    for (int nt = 0; nt < 4; nt++) {
        bia[nt][0] = bhh[n0w + 8 * nt + 2 * tig];
        bia[nt][1] = bhh[n0w + 8 * nt + 2 * tig + 1];
    }
    __syncthreads();

    for (int t = 0; t < 32; t++) {
        // prefetch gi (gmem) for the gate phase
        float pr[6], pz[6], pn[6];
#pragma unroll
        for (int k = 0; k < 6; k++) {
            int idx = tid + k * 384;
            if (idx < 2048) {
                int s = idx >> 7, d = idx & 127;
                const float* gr = gip + ((s0 + s) * 32 + t) * 384;
                pr[k] = gr[d]; pz[k] = gr[128 + d]; pn[k] = gr[256 + d];
            }
        }
        // h -> bf16 hi/lo
        for (int i = tid; i < 1024; i += 384) {
            int s = i >> 6, k2 = i & 63;
            float2 hv = *(const float2*)(hs + s * 128 + 2 * k2);
            unsigned h = bfpair(hv.x, hv.y);
            Ah[s * 68 + k2] = h;
            Al[s * 68 + k2] = bfpair(hv.x - bflo(h), hv.y - bfhi(h));
        }
        __syncthreads();
        // MMA: gates = h @ Whh^T
        float C[4][4];
#pragma unroll
        for (int nt = 0; nt < 4; nt++)
#pragma unroll
            for (int q = 0; q < 4; q++) C[nt][q] = 0.f;
#pragma unroll
        for (int kk = 0; kk < 8; kk++) {
            unsigned ah[4], al[4];
            ah[0] = Ah[gid * 68 + kk * 8 + tig];
            ah[1] = Ah[(gid + 8) * 68 + kk * 8 + tig];
            ah[2] = Ah[gid * 68 + kk * 8 + tig + 4];
            ah[3] = Ah[(gid + 8) * 68 + kk * 8 + tig + 4];
            al[0] = Al[gid * 68 + kk * 8 + tig];
            al[1] = Al[(gid + 8) * 68 + kk * 8 + tig];
            al[2] = Al[gid * 68 + kk * 8 + tig + 4];
            al[3] = Al[(gid + 8) * 68 + kk * 8 + tig + 4];
#pragma unroll
            for (int nt = 0; nt < 4; nt++) {
                unsigned bh[2];
                int col = n0w + 8 * nt + gid;
                bh[0] = Bh[col * 68 + kk * 8 + tig];
                bh[1] = Bh[col * 68 + kk * 8 + tig + 4];
                MMA_BF16(C[nt], ah, bh);
                MMA_BF16(C[nt], al, bh);
                MMA_BF16(C[nt], ah, blr[nt][kk]);
            }
        }
        // store gate pre-activations (+bhh)
#pragma unroll
        for (int nt = 0; nt < 4; nt++) {
            int col = n0w + 8 * nt + 2 * tig;
            *(float2*)(gsm + gid * 388 + col) = make_float2(C[nt][0] + bia[nt][0], C[nt][1] + bia[nt][1]);
            *(float2*)(gsm + (gid + 8) * 388 + col) = make_float2(C[nt][2] + bia[nt][0], C[nt][3] + bia[nt][1]);
        }
        __syncthreads();
        // gate update
#pragma unroll
        for (int k = 0; k < 6; k++) {
            int idx = tid + k * 384;
            if (idx < 2048) {
                int s = idx >> 7, d = idx & 127;
                float rg = sigm_(pr[k] + gsm[s * 388 + d]);
                float zg = sigm_(pz[k] + gsm[s * 388 + 128 + d]);
                float nn = tanh_fast(fmaf(rg, gsm[s * 388 + 256 + d], pn[k]));
                hs[idx] = (1.f - zg) * nn + zg * hs[idx];
            }
        }
        __syncthreads();
    }
    for (int idx = tid; idx < 2048; idx += 384) {
        int s = idx >> 7, d = idx & 127;
        outp[(s0 + s) * 128 + d] = hs[idx];
    }
}

// ---------------- visit GRU recurrence (scalar path, small) ----------------
template <int NSEQ, int T>
__global__ __launch_bounds__(384, 1) void k_rec(const float* __restrict__ Whh_all,
                                                const float* __restrict__ bhh_all) {
    extern __shared__ float sm[];
    float* wsf = sm;                     // 49280 floats
    float* hs = sm + 49280;              // [NSEQ][128]
    float* gsm = hs + NSEQ * 128;        // [NSEQ][384]
    const u64* ws2 = (const u64*)sm;
    int tid = threadIdx.x, bx = blockIdx.x;

    int run = bx >> 2, sgrp = bx & 3;
    int vi = (run < 8) ? (run >> 2) : (run - 6);
    const float* Whh = Whh_all + vi * 49152;
    const float* bhh = bhh_all + vi * 384;
    const float* gip = &g_vgi[run][0][0];
    float* outp = &g_hbuf[run][0][0];
    int s0 = sgrp * NSEQ;

    for (int i = tid; i < 49152; i += 384) {
        int j = i >> 7, d = i & 127;
        wsf[(d >> 1) * 770 + 2 * j + (d & 1)] = Whh[i];
    }
    for (int i = tid; i < NSEQ * 128; i += 384) hs[i] = 0.f;
    __syncthreads();

    int j = tid;
    float bj = bhh[j];
    constexpr int KP = (NSEQ * 128 + 383) / 384;

    for (int t = 0; t < T; t++) {
        float pr[KP], pz[KP], pn[KP];
#pragma unroll
        for (int k = 0; k < KP; k++) {
            int idx = tid + k * 384;
            if (idx < NSEQ * 128) {
                int s = idx >> 7, d = idx & 127;
                const float* gr = gip + ((s0 + s) * T + t) * 384;
                pr[k] = gr[d]; pz[k] = gr[128 + d]; pn[k] = gr[256 + d];
            }
        }
        u64 acc[NSEQ];
#pragma unroll
        for (int s = 0; s < NSEQ; s++) acc[s] = 0ull;
#pragma unroll 2
        for (int d4 = 0; d4 < 32; d4++) {
            u64 wA = ws2[(2 * d4) * 385 + j];
            u64 wB = ws2[(2 * d4 + 1) * 385 + j];
#pragma unroll
            for (int s = 0; s < NSEQ; s++) {
                double2 hd = ((const double2*)(hs + s * 128))[d4];
                fma2(acc[s], __double_as_longlong(hd.x), wA);
                fma2(acc[s], __double_as_longlong(hd.y), wB);
            }
        }
#pragma unroll
        for (int s = 0; s < NSEQ; s++) gsm[s * 384 + j] = sum2(acc[s]) + bj;
        __syncthreads();
#pragma unroll
        for (int k = 0; k < KP; k++) {
            int idx = tid + k * 384;
            if (idx < NSEQ * 128) {
                int s = idx >> 7, d = idx & 127;
                float rg = sigm_(pr[k] + gsm[s * 384 + d]);
                float zg = sigm_(pz[k] + gsm[s * 384 + 128 + d]);
                float nn = tanh_fast(fmaf(rg, gsm[s * 384 + 256 + d], pn[k]));
                hs[idx] = (1.f - zg) * nn + zg * hs[idx];
            }
        }
        __syncthreads();
    }
    for (int idx = tid; idx < NSEQ * 128; idx += 384) {
        int s = idx >> 7, d = idx & 127;
        outp[(s0 + s) * 128 + d] = hs[idx];
    }
}

// ---------------- head: out = relu(pe) @ W.T + b ----------------
__global__ void k_head(const float* __restrict__ fW, const float* __restrict__ fb,
                       float* __restrict__ out) {
    __shared__ float pe[896];
    int b = blockIdx.x / 10, og0 = (blockIdx.x % 10) * 60;
    int tid = threadIdx.x, lane = tid & 31, wp = tid >> 5;
    const float* H = &g_hbuf[0][0][0];  // [10][16][128]
    for (int i = tid; i < 896; i += 256) {
        int slot = i >> 7, d = i & 127;
        float v;
        if (slot == 0) v = H[0 * 2048 + b * 128 + d];
        else if (slot == 1) v = H[1 * 2048 + b * 128 + d] + H[5 * 2048 + b * 128 + d];
        else if (slot == 2) v = H[2 * 2048 + b * 128 + d] + H[6 * 2048 + b * 128 + d];
        else if (slot == 3) v = H[3 * 2048 + b * 128 + d] + H[7 * 2048 + b * 128 + d];
        else if (slot == 4) v = H[4 * 2048 + b * 128 + d];
        else if (slot == 5) v = H[8 * 2048 + b * 128 + d];
        else v = H[9 * 2048 + b * 128 + d];
        pe[i] = fmaxf(v, 0.f);
    }
    __syncthreads();
    for (int oi = wp; oi < 60; oi += 8) {
        int o = og0 + oi;
        u64 acc = 0ull;
#pragma unroll
        for (int i = 0; i < 7; i++) {
            int k4 = lane + 32 * i;
            float4 wv = __ldg((const float4*)(fW + o * 896) + k4);
            float4 xv = ((const float4*)pe)[k4];
            u64 a01, a23, w01, w23;
            asm("mov.b64 %0, {%1, %2};" : "=l"(a01) : "f"(xv.x), "f"(xv.y));
            asm("mov.b64 %0, {%1, %2};" : "=l"(a23) : "f"(xv.z), "f"(xv.w));
            asm("mov.b64 %0, {%1, %2};" : "=l"(w01) : "f"(wv.x), "f"(wv.y));
            asm("mov.b64 %0, {%1, %2};" : "=l"(w23) : "f"(wv.z), "f"(wv.w));
            fma2(acc, a01, w01);
            fma2(acc, a23, w23);
        }
        float v = sum2(acc);
#pragma unroll
        for (int m = 16; m > 0; m >>= 1) v += __shfl_xor_sync(0xffffffffu, v, m);
        if (lane == 0) out[b * 600 + o] = v + fb[o];
    }
}

// ---------------- launch ----------------
extern "C" void kernel_launch(void* const* d_in, const int* in_sizes, int n_in,
                              void* d_out, int out_size) {
    const int* cc = (const int*)d_in[0];
    const int* cp = (const int*)d_in[1];
    const int* cd = (const int*)d_in[2];
    const int* cli = (const int*)d_in[3];
    const int* clv = (const int*)d_in[4];
    const int* cii = (const int*)d_in[5];
    const int* civ = (const int*)d_in[6];
    const float* wgt = (const float*)d_in[7];
    const float* age = (const float*)d_in[8];
    const float* ec = (const float*)d_in[9];
    const float* ep = (const float*)d_in[10];
    const float* ed = (const float*)d_in[11];
    const float* eli = (const float*)d_in[12];
    const float* elv = (const float*)d_in[13];
    const float* eii = (const float*)d_in[14];
    const float* eiv = (const float*)d_in[15];
    const float* mWih = (const float*)d_in[16];
    const float* mWhh = (const float*)d_in[17];
    const float* mbih = (const float*)d_in[18];
    const float* mbhh = (const float*)d_in[19];
    const float* vWih = (const float*)d_in[20];
    const float* vWhh = (const float*)d_in[21];
    const float* vbih = (const float*)d_in[22];
    const float* vbhh = (const float*)d_in[23];
    const float* gWs = (const float*)d_in[24];
    const float* gWm = (const float*)d_in[25];
    const float* fwW = (const float*)d_in[26];
    const float* fwb = (const float*)d_in[27];
    const float* faW = (const float*)d_in[28];
    const float* fab = (const float*)d_in[29];
    const float* fpW = (const float*)d_in[30];
    const float* fpb = (const float*)d_in[31];
    float* out = (float*)d_out;

    cudaFuncSetAttribute(k_gemm, cudaFuncAttributeMaxDynamicSharedMemorySize, GSM_BYTES);
    cudaFuncSetAttribute(k_rec_mma, cudaFuncAttributeMaxDynamicSharedMemorySize, RSM_BYTES);
    cudaFuncSetAttribute((const void*)k_rec<4, 16>, cudaFuncAttributeMaxDynamicSharedMemorySize, 205312);

    k_pre<<<20354, 128>>>(cc, cp, cd, ec, ep, ed, cli, clv, cii, civ, eli, elv, eii, eiv,
                          gWs, gWm, mWih, vWih, mWhh, wgt, age, fwW, fwb, faW, fab);
    k_bias<<<64, 128>>>(gWs, gWm);
    k_gemm<<<dim3(64, 4, 2), 256, GSM_BYTES>>>(1, mbih, vbih);
    k_gemm<<<dim3(64, 3, 8), 256, GSM_BYTES>>>(2, mbih, vbih);
    k_rec_mma<<<128, 384, RSM_BYTES>>>(mbhh);
    k_gemm<<<dim3(20, 3, 1), 256, GSM_BYTES>>>(3, mbih, vbih);
    k_rec<4, 16><<<40, 384, 205312>>>(vWhh, vbhh);
    k_head<<<160, 256>>>(fpW, fpb, out);
}

// round 14
// speedup vs baseline: 2.6097x; 1.0250x over previous
#include <cuda_runtime.h>
#include <cuda_fp16.h>

typedef unsigned long long u64;

#define B_  16
#define V_  16
#define C_  64
#define M_  32
#define CM_ 16
#define D_  128
#define OUT_ 600
#define BV  256
#define BVM 8192

// ---------------- scratch ----------------
__device__ __align__(16) float g_vis[3][BV][D_];
__device__ __align__(16) float g_mon[2][BVM][D_];
__device__ __align__(16) unsigned g_wbh[2][512 * 64];    // gnn combined W bf16x2-hi [n][k/2]
__device__ __align__(16) unsigned g_wbl[2][512 * 64];    // bf16x2-lo
__device__ __align__(16) unsigned g_mbh[5 * 384 * 64];   // mgru Wih bf16x2-hi
__device__ __align__(16) unsigned g_mbl[5 * 384 * 64];
__device__ __align__(16) unsigned g_vbh[4 * 384 * 64];   // vgru Wih bf16x2-hi
__device__ __align__(16) unsigned g_vbl[4 * 384 * 64];
__device__ __align__(16) unsigned g_hhh[5 * 384 * 64];   // mgru Whh bf16x2-hi
__device__ __align__(16) unsigned g_hhl[5 * 384 * 64];   // mgru Whh bf16x2-lo
__device__ __align__(16) float g_bias[2][BV][512];       // visit-level gnn bias
__device__ __align__(16) float g_outs[2][BVM][512];      // gnn outputs (relu)
__device__ __align__(16) __half g_gi[8][BVM][384];       // monitor gi (fp16)
__device__ __align__(16) float g_seq[10][BV][D_];        // visit-level sequences
__device__ __align__(16) __half g_vgi[10][BV][384];      // visit gi (fp16)
__device__ __align__(16) float g_hbuf[10][B_][D_];       // final hidden per run

// ---------------- helpers ----------------
__device__ __forceinline__ void fma2(u64& c, u64 a, u64 b) {
    asm("fma.rn.f32x2 %0, %1, %2, %0;" : "+l"(c) : "l"(a), "l"(b));
}
__device__ __forceinline__ float sum2(u64 v) {
    float x, y; asm("mov.b64 {%0, %1}, %2;" : "=f"(x), "=f"(y) : "l"(v)); return x + y;
}
__device__ __forceinline__ float tanh_fast(float x) {
    float r; asm("tanh.approx.f32 %0, %1;" : "=f"(r) : "f"(x)); return r;
}
__device__ __forceinline__ float sigm_(float x) { return fmaf(0.5f, tanh_fast(0.5f * x), 0.5f); }

// pack (lo, hi) floats into bf16x2: low half = first arg
__device__ __forceinline__ unsigned bfpair(float lo, float hi) {
    unsigned r; asm("cvt.rn.bf16x2.f32 %0, %1, %2;" : "=r"(r) : "f"(hi), "f"(lo)); return r;
}
__device__ __forceinline__ float bflo(unsigned p) { return __uint_as_float(p << 16); }
__device__ __forceinline__ float bfhi(unsigned p) { return __uint_as_float(p & 0xffff0000u); }

#define MMA_BF16(c, a, b) \
    asm("mma.sync.aligned.m16n8k16.row.col.f32.bf16.bf16.f32 " \
        "{%0,%1,%2,%3},{%4,%5,%6,%7},{%8,%9},{%0,%1,%2,%3};" \
        : "+f"((c)[0]), "+f"((c)[1]), "+f"((c)[2]), "+f"((c)[3]) \
        : "r"((a)[0]), "r"((a)[1]), "r"((a)[2]), "r"((a)[3]), "r"((b)[0]), "r"((b)[1]))

// ---------------- K_pre: gathers + bf16 weight prep + scalar feats ----------------
__global__ __launch_bounds__(128) void k_pre(
    const int* __restrict__ cc, const int* __restrict__ cp, const int* __restrict__ cd,
    const float* __restrict__ ec, const float* __restrict__ ep, const float* __restrict__ ed,
    const int* __restrict__ li, const int* __restrict__ lv,
    const int* __restrict__ ii, const int* __restrict__ iv,
    const float* __restrict__ eli, const float* __restrict__ elv,
    const float* __restrict__ eii, const float* __restrict__ eiv,
    const float* __restrict__ Ws, const float* __restrict__ Wm,
    const float* __restrict__ mWih, const float* __restrict__ vWih,
    const float* __restrict__ mWhh,
    const float* __restrict__ w, const float* __restrict__ a,
    const float* __restrict__ fwW, const float* __restrict__ fwb,
    const float* __restrict__ faW, const float* __restrict__ fab) {
    int bx = blockIdx.x, tid = threadIdx.x;
    if (bx < 768) {
        int bv = bx & 255, ty = bx >> 8, d = tid;
        const int* codes = ((ty == 0) ? cc : ((ty == 1) ? cp : cd)) + bv * C_;
        const float* emb = (ty == 0) ? ec : ((ty == 1) ? ep : ed);
        float s = 0.f;
#pragma unroll 8
        for (int c = 0; c < C_; c++) s += emb[codes[c] * D_ + d];
        g_vis[ty][bv][d] = s;
    } else if (bx < 17152) {
        int i = bx - 768, p = i >> 13, row = i & 8191, d = tid;
        const int* ci = ((p == 0) ? li : ii) + row * CM_;
        const int* cv = ((p == 0) ? lv : iv) + row * CM_;
        const float* ei = (p == 0) ? eli : eii;
        const float* ev = (p == 0) ? elv : eiv;
        float s = 0.f;
#pragma unroll
        for (int c = 0; c < CM_; c++) s += ei[ci[c] * D_ + d] * ev[cv[c] * D_ + d];
        g_mon[p][row][d] = s;
    } else if (bx < 17664) {
        // gnn combined weights -> packed bf16x2 hi/lo, [n=512][k2=64]
        int i = (bx - 17152) * 128 + tid;        // < 65536
        int p = i >> 15, rem = i & 32767;
        int k2 = rem >> 9, j5 = rem & 511;
        int t = j5 >> 7, j = j5 & 127;
        const float* src = (t == 0) ? (Ws + (p * 4) * 16384) : (Wm + (p * 4 + t) * 16384);
        float sc = (t == 0) ? 1.f : (1.f / 3.f);
        float v0 = src[(2 * k2) * 128 + j] * sc;
        float v1 = src[(2 * k2 + 1) * 128 + j] * sc;
        unsigned h = bfpair(v0, v1);
        g_wbh[p][j5 * 64 + k2] = h;
        g_wbl[p][j5 * 64 + k2] = bfpair(v0 - bflo(h), v1 - bfhi(h));
    } else if (bx < 18624) {
        int o = (bx - 17664) * 128 + tid;        // < 122880
        float2 v = *(const float2*)(mWih + 2 * o);
        unsigned h = bfpair(v.x, v.y);
        g_mbh[o] = h;
        g_mbl[o] = bfpair(v.x - bflo(h), v.y - bfhi(h));
    } else if (bx < 19392) {
        int o = (bx - 18624) * 128 + tid;        // < 98304
        float2 v = *(const float2*)(vWih + 2 * o);
        unsigned h = bfpair(v.x, v.y);
        g_vbh[o] = h;
        g_vbl[o] = bfpair(v.x - bflo(h), v.y - bfhi(h));
    } else if (bx < 20352) {
        int o = (bx - 19392) * 128 + tid;        // < 122880
        float2 v = *(const float2*)(mWhh + 2 * o);
        unsigned h = bfpair(v.x, v.y);
        g_hhh[o] = h;
        g_hhl[o] = bfpair(v.x - bflo(h), v.y - bfhi(h));
    } else {
        int i = bx - 20352;
        const float* Wp = (i == 0) ? fwW : faW;
        const float* bp = (i == 0) ? fwb : fab;
        const float* xp = (i == 0) ? w : a;
        for (int idx = tid; idx < 32768; idx += 128) {
            int bv = idx >> 7, d = idx & 127;
            float x = xp[bv];
            g_seq[8 + i][bv][d] = (x != 0.f) ? (x * Wp[d] + bp[d]) : 0.f;
        }
    }
}

// ---------------- K_bias: visit-level gnn bias ----------------
__global__ __launch_bounds__(128) void k_bias(const float* __restrict__ Ws, const float* __restrict__ Wm) {
    __shared__ float sv[3][32][128];
    int blk = blockIdx.x, tid = threadIdx.x;
    int pt = blk >> 3, p = pt >> 2, t = pt & 3;
    int bv0 = (blk & 7) * 32;
    for (int i = tid; i < 3 * 32 * 128; i += 128) {
        int ty = i >> 12, c = (i >> 7) & 31, d = i & 127;
        sv[ty][c][d] = g_vis[ty][bv0 + c][d];
    }
    __syncthreads();
    int j = tid;
    const float* Wsp = Ws + (p * 4 + t) * 16384;
    const float* Wmp = Wm + (p * 4 + t) * 16384;
    float acc[32];
#pragma unroll
    for (int c = 0; c < 32; c++) acc[c] = 0.f;
    for (int d = 0; d < 128; d++) {
        float w2 = Wmp[d * 128 + j] * (1.f / 3.f);
        float w1 = (t == 0) ? 0.f : (Wsp[d * 128 + j] - w2);
#pragma unroll
        for (int c = 0; c < 32; c++) {
            float v0 = sv[0][c][d], v1 = sv[1][c][d], v2 = sv[2][c][d];
            float vs = v0 + v1 + v2;
            float vt = (t == 1) ? v0 : ((t == 2) ? v1 : ((t == 3) ? v2 : 0.f));
            acc[c] = fmaf(w2, vs, fmaf(w1, vt, acc[c]));
        }
    }
    for (int c = 0; c < 32; c++) g_bias[p][bv0 + c][t * 128 + j] = acc[c];
}

// ---------------- Tensor-core GEMM (3xBF16 m16n8k16): 128x128 block tile ----------------
// mode 1 writes fp32 (g_outs); modes 2/3 write fp16 (g_gi / g_vgi).
#define GSM_BYTES (4 * 128 * 36 * 4)
__global__ __launch_bounds__(256, 2) void k_gemm(int mode,
                                                 const float* __restrict__ bih_all, const float* __restrict__ vbih_all) {
    extern __shared__ unsigned smu[];
    unsigned* Ah = smu;                 // [128][36] u32 (bf16x2)
    unsigned* Al = Ah + 128 * 36;
    unsigned* Wh = Al + 128 * 36;       // [128 n][36] u32
    unsigned* Wl = Wh + 128 * 36;

    const float *A, *bias; float* out = 0; __half* outH = 0;
    const unsigned *Whp, *Wlp;
    int lda, K, bshift, relu;
    int n0 = blockIdx.x * 128, j0 = blockIdx.y * 128;
    if (mode == 1) {
        int p = blockIdx.z;
        A = &g_mon[p][0][0]; lda = 128;
        Whp = g_wbh[p]; Wlp = g_wbl[p];
        bias = &g_bias[p][0][0]; bshift = 5; K = 512; relu = 1;
        out = &g_outs[p][0][0];
    } else if (mode == 2) {
        int z = blockIdx.z, p = z >> 2, t = z & 3, g = (t == 0) ? p : (t + 1);
        A = &g_outs[p][0][0] + t * 128; lda = 512;
        Whp = g_mbh + g * 24576; Wlp = g_mbl + g * 24576;
        bias = bih_all + g * 384; bshift = 30; K = 384; relu = 0;
        outH = &g_gi[z][0][0];
    } else {
        int run = n0 >> 8;
        int vi = (run < 8) ? (run >> 2) : (run - 6);
        A = &g_seq[0][0][0]; lda = 128;
        Whp = g_vbh + vi * 24576; Wlp = g_vbl + vi * 24576;
        bias = vbih_all + vi * 384; bshift = 30; K = 384; relu = 0;
        outH = &g_vgi[0][0][0];
    }

    int tid = threadIdx.x;
    int lane = tid & 31, wid = tid >> 5;
    int gid = lane >> 2, tig = lane & 3;
    int m0w = (wid & 1) * 64, n0w = (wid >> 1) * 32;

    float C[4][4][4];
#pragma unroll
    for (int mt = 0; mt < 4; mt++)
#pragma unroll
        for (int nt = 0; nt < 4; nt++)
#pragma unroll
            for (int q = 0; q < 4; q++) C[mt][nt][q] = 0.f;

    for (int kc = 0; kc < 2; kc++) {
#pragma unroll
        for (int it = 0; it < 8; it++) {
            int f4 = tid + 256 * it;
            int r = f4 >> 4, c4 = f4 & 15;
            float4 v = *(const float4*)(A + (n0 + r) * lda + kc * 64 + c4 * 4);
            unsigned h01 = bfpair(v.x, v.y), h23 = bfpair(v.z, v.w);
            unsigned l01 = bfpair(v.x - bflo(h01), v.y - bfhi(h01));
            unsigned l23 = bfpair(v.z - bflo(h23), v.w - bfhi(h23));
            *(u64*)(Ah + r * 36 + c4 * 2) = (u64)h01 | ((u64)h23 << 32);
            *(u64*)(Al + r * 36 + c4 * 2) = (u64)l01 | ((u64)l23 << 32);
        }
#pragma unroll
        for (int it = 0; it < 8; it++) {
            int u2 = tid + 256 * it;
            int n = u2 >> 4, c2 = u2 & 15;
            uint2 sh = *(const uint2*)(Whp + (j0 + n) * 64 + kc * 32 + c2 * 2);
            uint2 sl = *(const uint2*)(Wlp + (j0 + n) * 64 + kc * 32 + c2 * 2);
            *(u64*)(Wh + n * 36 + c2 * 2) = (u64)sh.x | ((u64)sh.y << 32);
            *(u64*)(Wl + n * 36 + c2 * 2) = (u64)sl.x | ((u64)sl.y << 32);
        }
        __syncthreads();

#pragma unroll
        for (int ks = 0; ks < 4; ks++) {
            int kk = ks * 8;
            unsigned ah[4][4], al[4][4], bh[4][2], bl[4][2];
#pragma unroll
            for (int mt = 0; mt < 4; mt++) {
                const unsigned* ap = Ah + (m0w + 16 * mt + gid) * 36 + kk + tig;
                const unsigned* lp = Al + (m0w + 16 * mt + gid) * 36 + kk + tig;
                ah[mt][0] = ap[0];
                ah[mt][1] = ap[8 * 36];
                ah[mt][2] = ap[4];
                ah[mt][3] = ap[8 * 36 + 4];
                al[mt][0] = lp[0];
                al[mt][1] = lp[8 * 36];
                al[mt][2] = lp[4];
                al[mt][3] = lp[8 * 36 + 4];
            }
#pragma unroll
            for (int nt = 0; nt < 4; nt++) {
                const unsigned* bp = Wh + (n0w + 8 * nt + gid) * 36 + kk + tig;
                const unsigned* lp = Wl + (n0w + 8 * nt + gid) * 36 + kk + tig;
                bh[nt][0] = bp[0];
                bh[nt][1] = bp[4];
                bl[nt][0] = lp[0];
                bl[nt][1] = lp[4];
            }
#pragma unroll
            for (int mt = 0; mt < 4; mt++)
#pragma unroll
                for (int nt = 0; nt < 4; nt++) {
                    MMA_BF16(C[mt][nt], ah[mt], bh[nt]);
                    MMA_BF16(C[mt][nt], ah[mt], bl[nt]);
                    MMA_BF16(C[mt][nt], al[mt], bh[nt]);
                }
        }
        __syncthreads();
    }

#pragma unroll
    for (int mt = 0; mt < 4; mt++) {
        int mrow = n0 + m0w + 16 * mt + gid;
        int bgrp = (mrow >> bshift) * K;
        int bgrp2 = ((mrow + 8) >> bshift) * K;
#pragma unroll
        for (int nt = 0; nt < 4; nt++) {
            int col = j0 + n0w + 8 * nt + 2 * tig;
            float v0 = C[mt][nt][0] + bias[bgrp + col];
            float v1 = C[mt][nt][1] + bias[bgrp + col + 1];
            float v2 = C[mt][nt][2] + bias[bgrp2 + col];
            float v3 = C[mt][nt][3] + bias[bgrp2 + col + 1];
            if (relu) {
                v0 = fmaxf(v0, 0.f); v1 = fmaxf(v1, 0.f);
                v2 = fmaxf(v2, 0.f); v3 = fmaxf(v3, 0.f);
                *(float2*)(out + mrow * K + col) = make_float2(v0, v1);
                *(float2*)(out + (mrow + 8) * K + col) = make_float2(v2, v3);
            } else {
                *(__half2*)(outH + mrow * K + col) = __floats2half2_rn(v0, v1);
                *(__half2*)(outH + (mrow + 8) * K + col) = __floats2half2_rn(v2, v3);
            }
        }
    }
}

// ---------------- monitor GRU recurrence on tensor cores (3xBF16) ----------------
// Per CTA: 16 seqs; per step gates[16][384] = h[16][128] @ Whh^T via m16n8k16.
// Whh-hi in smem [384][68] u32; Whh-lo fragments in registers.
// Gate phase processes d-pairs and emits next-step Ah/Al directly (2 barriers/step).
#define RSM_BYTES 146176
__global__ __launch_bounds__(384, 1) void k_rec_mma(const float* __restrict__ bhh_all) {
    extern __shared__ unsigned smu[];
    unsigned* Bh = smu;                    // [384][68] u32
    unsigned* Ah = smu + 26112;            // [16][68]
    unsigned* Al = Ah + 1088;              // [16][68]
    float* hs = (float*)(smu + 28288);     // [16][128]
    float* gsm = hs + 2048;                // [16][388]
    int tid = threadIdx.x, bx = blockIdx.x;
    int chan = bx >> 4, sgrp = bx & 15;
    int p = chan >> 2, tt = chan & 3, g = (tt == 0) ? p : (tt + 1);
    const float* bhh = bhh_all + g * 384;
    const __half* gip = &g_gi[chan][0][0];
    float* outp = &g_seq[chan][0][0];
    int s0 = sgrp * 16;

    for (int i = tid; i < 24576; i += 384) Bh[(i >> 6) * 68 + (i & 63)] = g_hhh[g * 24576 + i];
    for (int i = tid; i < 2048; i += 384) hs[i] = 0.f;
    for (int i = tid; i < 1088; i += 384) { Ah[i] = 0u; Al[i] = 0u; }

    int lane = tid & 31, wid = tid >> 5;
    int gid = lane >> 2, tig = lane & 3;
    int n0w = wid * 32;

    unsigned blr[4][8][2];
#pragma unroll
    for (int nt = 0; nt < 4; nt++) {
        int col = n0w + 8 * nt + gid;
#pragma unroll
        for (int kk = 0; kk < 8; kk++) {
            blr[nt][kk][0] = g_hhl[g * 24576 + col * 64 + kk * 8 + tig];
            blr[nt][kk][1] = g_hhl[g * 24576 + col * 64 + kk * 8 + tig + 4];
        }
    }
    float bia[4][2];
#pragma unroll
    for (int nt = 0; nt < 4; nt++) {
        bia[nt][0] = bhh[n0w + 8 * nt + 2 * tig];
        bia[nt][1] = bhh[n0w + 8 * nt + 2 * tig + 1];
    }
    __syncthreads();

    for (int t = 0; t < 32; t++) {
        // prefetch gi (gmem, fp16 pairs) for the gate phase
        __half2 pr2[3], pz2[3], pn2[3];
#pragma unroll
        for (int k = 0; k < 3; k++) {
            int idx2 = tid + k * 384;
            if (idx2 < 1024) {
                int s = idx2 >> 6, k2 = idx2 & 63;
                const __half2* grow = (const __half2*)(gip + ((s0 + s) * 32 + t) * 384);
                pr2[k] = grow[k2]; pz2[k] = grow[64 + k2]; pn2[k] = grow[128 + k2];
            }
        }
        // MMA: gates = h @ Whh^T (Ah/Al produced by previous gate phase)
        float C[4][4];
#pragma unroll
        for (int nt = 0; nt < 4; nt++)
#pragma unroll
            for (int q = 0; q < 4; q++) C[nt][q] = 0.f;
#pragma unroll
        for (int kk = 0; kk < 8; kk++) {
            unsigned ah[4], al[4];
            ah[0] = Ah[gid * 68 + kk * 8 + tig];
            ah[1] = Ah[(gid + 8) * 68 + kk * 8 + tig];
            ah[2] = Ah[gid * 68 + kk * 8 + tig + 4];
            ah[3] = Ah[(gid + 8) * 68 + kk * 8 + tig + 4];
            al[0] = Al[gid * 68 + kk * 8 + tig];
            al[1] = Al[(gid + 8) * 68 + kk * 8 + tig];
            al[2] = Al[gid * 68 + kk * 8 + tig + 4];
            al[3] = Al[(gid + 8) * 68 + kk * 8 + tig + 4];
#pragma unroll
            for (int nt = 0; nt < 4; nt++) {
                unsigned bh[2];
                int col = n0w + 8 * nt + gid;
                bh[0] = Bh[col * 68 + kk * 8 + tig];
                bh[1] = Bh[col * 68 + kk * 8 + tig + 4];
                MMA_BF16(C[nt], ah, bh);
                MMA_BF16(C[nt], al, bh);
                MMA_BF16(C[nt], ah, blr[nt][kk]);
            }
        }
        // store gate pre-activations (+bhh)
#pragma unroll
        for (int nt = 0; nt < 4; nt++) {
            int col = n0w + 8 * nt + 2 * tig;
            *(float2*)(gsm + gid * 388 + col) = make_float2(C[nt][0] + bia[nt][0], C[nt][1] + bia[nt][1]);
            *(float2*)(gsm + (gid + 8) * 388 + col) = make_float2(C[nt][2] + bia[nt][0], C[nt][3] + bia[nt][1]);
        }
        __syncthreads();
        // gate update on d-pairs; writes hs + next-step Ah/Al
#pragma unroll
        for (int k = 0; k < 3; k++) {
            int idx2 = tid + k * 384;
            if (idx2 < 1024) {
                int s = idx2 >> 6, k2 = idx2 & 63;
                int d0 = 2 * k2;
                float2 gr = *(float2*)(gsm + s * 388 + d0);
                float2 gz = *(float2*)(gsm + s * 388 + 128 + d0);
                float2 gn = *(float2*)(gsm + s * 388 + 256 + d0);
                float2 pr = __half22float2(pr2[k]);
                float2 pz = __half22float2(pz2[k]);
                float2 pn = __half22float2(pn2[k]);
                float rg0 = sigm_(pr.x + gr.x), rg1 = sigm_(pr.y + gr.y);
                float zg0 = sigm_(pz.x + gz.x), zg1 = sigm_(pz.y + gz.y);
                float nn0 = tanh_fast(fmaf(rg0, gn.x, pn.x));
                float nn1 = tanh_fast(fmaf(rg1, gn.y, pn.y));
                float2 ho = *(float2*)(hs + s * 128 + d0);
                float h0 = (1.f - zg0) * nn0 + zg0 * ho.x;
                float h1 = (1.f - zg1) * nn1 + zg1 * ho.y;
                *(float2*)(hs + s * 128 + d0) = make_float2(h0, h1);
                unsigned hh = bfpair(h0, h1);
                Ah[s * 68 + k2] = hh;
                Al[s * 68 + k2] = bfpair(h0 - bflo(hh), h1 - bfhi(hh));
            }
        }
        __syncthreads();
    }
    for (int idx = tid; idx < 2048; idx += 384) {
        int s = idx >> 7, d = idx & 127;
        outp[(s0 + s) * 128 + d] = hs[idx];
    }
}

// ---------------- visit GRU recurrence (scalar path, small) ----------------
template <int NSEQ, int T>
__global__ __launch_bounds__(384, 1) void k_rec(const float* __restrict__ Whh_all,
                                                const float* __restrict__ bhh_all) {
    extern __shared__ float sm[];
    float* wsf = sm;                     // 49280 floats
    float* hs = sm + 49280;              // [NSEQ][128]
    float* gsm = hs + NSEQ * 128;        // [NSEQ][384]
    const u64* ws2 = (const u64*)sm;
    int tid = threadIdx.x, bx = blockIdx.x;

    int run = bx >> 2, sgrp = bx & 3;
    int vi = (run < 8) ? (run >> 2) : (run - 6);
    const float* Whh = Whh_all + vi * 49152;
    const float* bhh = bhh_all + vi * 384;
    const __half* gip = &g_vgi[run][0][0];
    float* outp = &g_hbuf[run][0][0];
    int s0 = sgrp * NSEQ;

    for (int i = tid; i < 49152; i += 384) {
        int j = i >> 7, d = i & 127;
        wsf[(d >> 1) * 770 + 2 * j + (d & 1)] = Whh[i];
    }
    for (int i = tid; i < NSEQ * 128; i += 384) hs[i] = 0.f;
    __syncthreads();

    int j = tid;
    float bj = bhh[j];
    constexpr int KP = (NSEQ * 128 + 383) / 384;

    for (int t = 0; t < T; t++) {
        float pr[KP], pz[KP], pn[KP];
#pragma unroll
        for (int k = 0; k < KP; k++) {
            int idx = tid + k * 384;
            if (idx < NSEQ * 128) {
                int s = idx >> 7, d = idx & 127;
                const __half* gr = gip + ((s0 + s) * T + t) * 384;
                pr[k] = __half2float(gr[d]);
                pz[k] = __half2float(gr[128 + d]);
                pn[k] = __half2float(gr[256 + d]);
            }
        }
        u64 acc[NSEQ];
#pragma unroll
        for (int s = 0; s < NSEQ; s++) acc[s] = 0ull;
#pragma unroll 2
        for (int d4 = 0; d4 < 32; d4++) {
            u64 wA = ws2[(2 * d4) * 385 + j];
            u64 wB = ws2[(2 * d4 + 1) * 385 + j];
#pragma unroll
            for (int s = 0; s < NSEQ; s++) {
                double2 hd = ((const double2*)(hs + s * 128))[d4];
                fma2(acc[s], __double_as_longlong(hd.x), wA);
                fma2(acc[s], __double_as_longlong(hd.y), wB);
            }
        }
#pragma unroll
        for (int s = 0; s < NSEQ; s++) gsm[s * 384 + j] = sum2(acc[s]) + bj;
        __syncthreads();
#pragma unroll
        for (int k = 0; k < KP; k++) {
            int idx = tid + k * 384;
            if (idx < NSEQ * 128) {
                int s = idx >> 7, d = idx & 127;
                float rg = sigm_(pr[k] + gsm[s * 384 + d]);
                float zg = sigm_(pz[k] + gsm[s * 384 + 128 + d]);
                float nn = tanh_fast(fmaf(rg, gsm[s * 384 + 256 + d], pn[k]));
                hs[idx] = (1.f - zg) * nn + zg * hs[idx];
            }
        }
        __syncthreads();
    }
    for (int idx = tid; idx < NSEQ * 128; idx += 384) {
        int s = idx >> 7, d = idx & 127;
        outp[(s0 + s) * 128 + d] = hs[idx];
    }
}

// ---------------- head: out = relu(pe) @ W.T + b ----------------
__global__ void k_head(const float* __restrict__ fW, const float* __restrict__ fb,
                       float* __restrict__ out) {
    __shared__ float pe[896];
    int b = blockIdx.x / 10, og0 = (blockIdx.x % 10) * 60;
    int tid = threadIdx.x, lane = tid & 31, wp = tid >> 5;
    const float* H = &g_hbuf[0][0][0];  // [10][16][128]
    for (int i = tid; i < 896; i += 256) {
        int slot = i >> 7, d = i & 127;
        float v;
        if (slot == 0) v = H[0 * 2048 + b * 128 + d];
        else if (slot == 1) v = H[1 * 2048 + b * 128 + d] + H[5 * 2048 + b * 128 + d];
        else if (slot == 2) v = H[2 * 2048 + b * 128 + d] + H[6 * 2048 + b * 128 + d];
        else if (slot == 3) v = H[3 * 2048 + b * 128 + d] + H[7 * 2048 + b * 128 + d];
        else if (slot == 4) v = H[4 * 2048 + b * 128 + d];
        else if (slot == 5) v = H[8 * 2048 + b * 128 + d];
        else v = H[9 * 2048 + b * 128 + d];
        pe[i] = fmaxf(v, 0.f);
    }
    __syncthreads();
    for (int oi = wp; oi < 60; oi += 8) {
        int o = og0 + oi;
        u64 acc = 0ull;
#pragma unroll
        for (int i = 0; i < 7; i++) {
            int k4 = lane + 32 * i;
            float4 wv = __ldg((const float4*)(fW + o * 896) + k4);
            float4 xv = ((const float4*)pe)[k4];
            u64 a01, a23, w01, w23;
            asm("mov.b64 %0, {%1, %2};" : "=l"(a01) : "f"(xv.x), "f"(xv.y));
            asm("mov.b64 %0, {%1, %2};" : "=l"(a23) : "f"(xv.z), "f"(xv.w));
            asm("mov.b64 %0, {%1, %2};" : "=l"(w01) : "f"(wv.x), "f"(wv.y));
            asm("mov.b64 %0, {%1, %2};" : "=l"(w23) : "f"(wv.z), "f"(wv.w));
            fma2(acc, a01, w01);
            fma2(acc, a23, w23);
        }
        float v = sum2(acc);
#pragma unroll
        for (int m = 16; m > 0; m >>= 1) v += __shfl_xor_sync(0xffffffffu, v, m);
        if (lane == 0) out[b * 600 + o] = v + fb[o];
    }
}

// ---------------- launch ----------------
extern "C" void kernel_launch(void* const* d_in, const int* in_sizes, int n_in,
                              void* d_out, int out_size) {
    const int* cc = (const int*)d_in[0];
    const int* cp = (const int*)d_in[1];
    const int* cd = (const int*)d_in[2];
    const int* cli = (const int*)d_in[3];
    const int* clv = (const int*)d_in[4];
    const int* cii = (const int*)d_in[5];
    const int* civ = (const int*)d_in[6];
    const float* wgt = (const float*)d_in[7];
    const float* age = (const float*)d_in[8];
    const float* ec = (const float*)d_in[9];
    const float* ep = (const float*)d_in[10];
    const float* ed = (const float*)d_in[11];
    const float* eli = (const float*)d_in[12];
    const float* elv = (const float*)d_in[13];
    const float* eii = (const float*)d_in[14];
    const float* eiv = (const float*)d_in[15];
    const float* mWih = (const float*)d_in[16];
    const float* mWhh = (const float*)d_in[17];
    const float* mbih = (const float*)d_in[18];
    const float* mbhh = (const float*)d_in[19];
    const float* vWih = (const float*)d_in[20];
    const float* vWhh = (const float*)d_in[21];
    const float* vbih = (const float*)d_in[22];
    const float* vbhh = (const float*)d_in[23];
    const float* gWs = (const float*)d_in[24];
    const float* gWm = (const float*)d_in[25];
    const float* fwW = (const float*)d_in[26];
    const float* fwb = (const float*)d_in[27];
    const float* faW = (const float*)d_in[28];
    const float* fab = (const float*)d_in[29];
    const float* fpW = (const float*)d_in[30];
    const float* fpb = (const float*)d_in[31];
    float* out = (float*)d_out;

    cudaFuncSetAttribute(k_gemm, cudaFuncAttributeMaxDynamicSharedMemorySize, GSM_BYTES);
    cudaFuncSetAttribute(k_rec_mma, cudaFuncAttributeMaxDynamicSharedMemorySize, RSM_BYTES);
    cudaFuncSetAttribute((const void*)k_rec<4, 16>, cudaFuncAttributeMaxDynamicSharedMemorySize, 205312);

    k_pre<<<20354, 128>>>(cc, cp, cd, ec, ep, ed, cli, clv, cii, civ, eli, elv, eii, eiv,
                          gWs, gWm, mWih, vWih, mWhh, wgt, age, fwW, fwb, faW, fab);
    k_bias<<<64, 128>>>(gWs, gWm);
    k_gemm<<<dim3(64, 4, 2), 256, GSM_BYTES>>>(1, mbih, vbih);
    k_gemm<<<dim3(64, 3, 8), 256, GSM_BYTES>>>(2, mbih, vbih);
    k_rec_mma<<<128, 384, RSM_BYTES>>>(mbhh);
    k_gemm<<<dim3(20, 3, 1), 256, GSM_BYTES>>>(3, mbih, vbih);
    k_rec<4, 16><<<40, 384, 205312>>>(vWhh, vbhh);
    k_head<<<160, 256>>>(fpW, fpb, out);
}

// round 16
// speedup vs baseline: 2.6122x; 1.0010x over previous
#include <cuda_runtime.h>
#include <cuda_fp16.h>

typedef unsigned long long u64;

#define B_  16
#define V_  16
#define C_  64
#define M_  32
#define CM_ 16
#define D_  128
#define OUT_ 600
#define BV  256
#define BVM 8192

// ---------------- scratch ----------------
__device__ __align__(16) float g_vis[3][BV][D_];
__device__ __align__(16) float g_mon[2][BVM][D_];
__device__ __align__(16) unsigned g_wbh[2][512 * 64];    // gnn combined W bf16x2-hi [n][k/2]
__device__ __align__(16) unsigned g_wbl[2][512 * 64];    // bf16x2-lo
__device__ __align__(16) unsigned g_mbh[5 * 384 * 64];   // mgru Wih bf16x2-hi
__device__ __align__(16) unsigned g_mbl[5 * 384 * 64];
__device__ __align__(16) unsigned g_vbh[4 * 384 * 64];   // vgru Wih bf16x2-hi
__device__ __align__(16) unsigned g_vbl[4 * 384 * 64];
__device__ __align__(16) unsigned g_hhh[5 * 384 * 64];   // mgru Whh bf16x2-hi
__device__ __align__(16) unsigned g_hhl[5 * 384 * 64];   // mgru Whh bf16x2-lo
__device__ __align__(16) float g_bias[2][BV][512];       // visit-level gnn bias
__device__ __align__(16) float g_outs[2][BVM][512];      // gnn outputs (relu)
__device__ __align__(16) __half g_gi[8][BVM][384];       // monitor gi (fp16)
__device__ __align__(16) float g_seq[10][BV][D_];        // visit-level sequences
__device__ __align__(16) __half g_vgi[10][BV][384];      // visit gi (fp16)
__device__ __align__(16) float g_hbuf[10][B_][D_];       // final hidden per run

// ---------------- helpers ----------------
__device__ __forceinline__ void fma2(u64& c, u64 a, u64 b) {
    asm("fma.rn.f32x2 %0, %1, %2, %0;" : "+l"(c) : "l"(a), "l"(b));
}
__device__ __forceinline__ float sum2(u64 v) {
    float x, y; asm("mov.b64 {%0, %1}, %2;" : "=f"(x), "=f"(y) : "l"(v)); return x + y;
}
__device__ __forceinline__ float tanh_fast(float x) {
    float r; asm("tanh.approx.f32 %0, %1;" : "=f"(r) : "f"(x)); return r;
}
__device__ __forceinline__ float sigm_(float x) { return fmaf(0.5f, tanh_fast(0.5f * x), 0.5f); }

// pack (lo, hi) floats into bf16x2: low half = first arg
__device__ __forceinline__ unsigned bfpair(float lo, float hi) {
    unsigned r; asm("cvt.rn.bf16x2.f32 %0, %1, %2;" : "=r"(r) : "f"(hi), "f"(lo)); return r;
}
__device__ __forceinline__ float bflo(unsigned p) { return __uint_as_float(p << 16); }
__device__ __forceinline__ float bfhi(unsigned p) { return __uint_as_float(p & 0xffff0000u); }

#define MMA_BF16(c, a, b) \
    asm("mma.sync.aligned.m16n8k16.row.col.f32.bf16.bf16.f32 " \
        "{%0,%1,%2,%3},{%4,%5,%6,%7},{%8,%9},{%0,%1,%2,%3};" \
        : "+f"((c)[0]), "+f"((c)[1]), "+f"((c)[2]), "+f"((c)[3]) \
        : "r"((a)[0]), "r"((a)[1]), "r"((a)[2]), "r"((a)[3]), "r"((b)[0]), "r"((b)[1]))

// ---------------- K_pre: gathers + bf16 weight prep + scalar feats ----------------
__global__ __launch_bounds__(128) void k_pre(
    const int* __restrict__ cc, const int* __restrict__ cp, const int* __restrict__ cd,
    const float* __restrict__ ec, const float* __restrict__ ep, const float* __restrict__ ed,
    const int* __restrict__ li, const int* __restrict__ lv,
    const int* __restrict__ ii, const int* __restrict__ iv,
    const float* __restrict__ eli, const float* __restrict__ elv,
    const float* __restrict__ eii, const float* __restrict__ eiv,
    const float* __restrict__ Ws, const float* __restrict__ Wm,
    const float* __restrict__ mWih, const float* __restrict__ vWih,
    const float* __restrict__ mWhh,
    const float* __restrict__ w, const float* __restrict__ a,
    const float* __restrict__ fwW, const float* __restrict__ fwb,
    const float* __restrict__ faW, const float* __restrict__ fab) {
    int bx = blockIdx.x, tid = threadIdx.x;
    if (bx < 768) {
        int bv = bx & 255, ty = bx >> 8, d = tid;
        const int* codes = ((ty == 0) ? cc : ((ty == 1) ? cp : cd)) + bv * C_;
        const float* emb = (ty == 0) ? ec : ((ty == 1) ? ep : ed);
        float s = 0.f;
#pragma unroll 8
        for (int c = 0; c < C_; c++) s += emb[codes[c] * D_ + d];
        g_vis[ty][bv][d] = s;
    } else if (bx < 17152) {
        int i = bx - 768, p = i >> 13, row = i & 8191, d = tid;
        const int* ci = ((p == 0) ? li : ii) + row * CM_;
        const int* cv = ((p == 0) ? lv : iv) + row * CM_;
        const float* ei = (p == 0) ? eli : eii;
        const float* ev = (p == 0) ? elv : eiv;
        float s = 0.f;
#pragma unroll
        for (int c = 0; c < CM_; c++) s += ei[ci[c] * D_ + d] * ev[cv[c] * D_ + d];
        g_mon[p][row][d] = s;
    } else if (bx < 17664) {
        // gnn combined weights -> packed bf16x2 hi/lo, [n=512][k2=64]
        int i = (bx - 17152) * 128 + tid;        // < 65536
        int p = i >> 15, rem = i & 32767;
        int k2 = rem >> 9, j5 = rem & 511;
        int t = j5 >> 7, j = j5 & 127;
        const float* src = (t == 0) ? (Ws + (p * 4) * 16384) : (Wm + (p * 4 + t) * 16384);
        float sc = (t == 0) ? 1.f : (1.f / 3.f);
        float v0 = src[(2 * k2) * 128 + j] * sc;
        float v1 = src[(2 * k2 + 1) * 128 + j] * sc;
        unsigned h = bfpair(v0, v1);
        g_wbh[p][j5 * 64 + k2] = h;
        g_wbl[p][j5 * 64 + k2] = bfpair(v0 - bflo(h), v1 - bfhi(h));
    } else if (bx < 18624) {
        int o = (bx - 17664) * 128 + tid;        // < 122880
        float2 v = *(const float2*)(mWih + 2 * o);
        unsigned h = bfpair(v.x, v.y);
        g_mbh[o] = h;
        g_mbl[o] = bfpair(v.x - bflo(h), v.y - bfhi(h));
    } else if (bx < 19392) {
        int o = (bx - 18624) * 128 + tid;        // < 98304
        float2 v = *(const float2*)(vWih + 2 * o);
        unsigned h = bfpair(v.x, v.y);
        g_vbh[o] = h;
        g_vbl[o] = bfpair(v.x - bflo(h), v.y - bfhi(h));
    } else if (bx < 20352) {
        int o = (bx - 19392) * 128 + tid;        // < 122880
        float2 v = *(const float2*)(mWhh + 2 * o);
        unsigned h = bfpair(v.x, v.y);
        g_hhh[o] = h;
        g_hhl[o] = bfpair(v.x - bflo(h), v.y - bfhi(h));
    } else {
        int i = bx - 20352;
        const float* Wp = (i == 0) ? fwW : faW;
        const float* bp = (i == 0) ? fwb : fab;
        const float* xp = (i == 0) ? w : a;
        for (int idx = tid; idx < 32768; idx += 128) {
            int bv = idx >> 7, d = idx & 127;
            float x = xp[bv];
            g_seq[8 + i][bv][d] = (x != 0.f) ? (x * Wp[d] + bp[d]) : 0.f;
        }
    }
}

// ---------------- K_bias: visit-level gnn bias ----------------
__global__ __launch_bounds__(128) void k_bias(const float* __restrict__ Ws, const float* __restrict__ Wm) {
    __shared__ float sv[3][32][128];
    int blk = blockIdx.x, tid = threadIdx.x;
    int pt = blk >> 3, p = pt >> 2, t = pt & 3;
    int bv0 = (blk & 7) * 32;
    for (int i = tid; i < 3 * 32 * 128; i += 128) {
        int ty = i >> 12, c = (i >> 7) & 31, d = i & 127;
        sv[ty][c][d] = g_vis[ty][bv0 + c][d];
    }
    __syncthreads();
    int j = tid;
    const float* Wsp = Ws + (p * 4 + t) * 16384;
    const float* Wmp = Wm + (p * 4 + t) * 16384;
    float acc[32];
#pragma unroll
    for (int c = 0; c < 32; c++) acc[c] = 0.f;
    for (int d = 0; d < 128; d++) {
        float w2 = Wmp[d * 128 + j] * (1.f / 3.f);
        float w1 = (t == 0) ? 0.f : (Wsp[d * 128 + j] - w2);
#pragma unroll
        for (int c = 0; c < 32; c++) {
            float v0 = sv[0][c][d], v1 = sv[1][c][d], v2 = sv[2][c][d];
            float vs = v0 + v1 + v2;
            float vt = (t == 1) ? v0 : ((t == 2) ? v1 : ((t == 3) ? v2 : 0.f));
            acc[c] = fmaf(w2, vs, fmaf(w1, vt, acc[c]));
        }
    }
    for (int c = 0; c < 32; c++) g_bias[p][bv0 + c][t * 128 + j] = acc[c];
}

// ---------------- Tensor-core GEMM (3xBF16 m16n8k16): 128x128 block tile ----------------
// mode 1 writes fp32 (g_outs); modes 2/3 write fp16 (g_gi / g_vgi).
#define GSM_BYTES (4 * 128 * 36 * 4)
__global__ __launch_bounds__(256, 2) void k_gemm(int mode,
                                                 const float* __restrict__ bih_all, const float* __restrict__ vbih_all) {
    extern __shared__ unsigned smu[];
    unsigned* Ah = smu;                 // [128][36] u32 (bf16x2)
    unsigned* Al = Ah + 128 * 36;
    unsigned* Wh = Al + 128 * 36;       // [128 n][36] u32
    unsigned* Wl = Wh + 128 * 36;

    const float *A, *bias; float* out = 0; __half* outH = 0;
    const unsigned *Whp, *Wlp;
    int lda, K, bshift, relu;
    int n0 = blockIdx.x * 128, j0 = blockIdx.y * 128;
    if (mode == 1) {
        int p = blockIdx.z;
        A = &g_mon[p][0][0]; lda = 128;
        Whp = g_wbh[p]; Wlp = g_wbl[p];
        bias = &g_bias[p][0][0]; bshift = 5; K = 512; relu = 1;
        out = &g_outs[p][0][0];
    } else if (mode == 2) {
        int z = blockIdx.z, p = z >> 2, t = z & 3, g = (t == 0) ? p : (t + 1);
        A = &g_outs[p][0][0] + t * 128; lda = 512;
        Whp = g_mbh + g * 24576; Wlp = g_mbl + g * 24576;
        bias = bih_all + g * 384; bshift = 30; K = 384; relu = 0;
        outH = &g_gi[z][0][0];
    } else {
        int run = n0 >> 8;
        int vi = (run < 8) ? (run >> 2) : (run - 6);
        A = &g_seq[0][0][0]; lda = 128;
        Whp = g_vbh + vi * 24576; Wlp = g_vbl + vi * 24576;
        bias = vbih_all + vi * 384; bshift = 30; K = 384; relu = 0;
        outH = &g_vgi[0][0][0];
    }

    int tid = threadIdx.x;
    int lane = tid & 31, wid = tid >> 5;
    int gid = lane >> 2, tig = lane & 3;
    int m0w = (wid & 1) * 64, n0w = (wid >> 1) * 32;

    float C[4][4][4];
#pragma unroll
    for (int mt = 0; mt < 4; mt++)
#pragma unroll
        for (int nt = 0; nt < 4; nt++)
#pragma unroll
            for (int q = 0; q < 4; q++) C[mt][nt][q] = 0.f;

    for (int kc = 0; kc < 2; kc++) {
#pragma unroll
        for (int it = 0; it < 8; it++) {
            int f4 = tid + 256 * it;
            int r = f4 >> 4, c4 = f4 & 15;
            float4 v = *(const float4*)(A + (n0 + r) * lda + kc * 64 + c4 * 4);
            unsigned h01 = bfpair(v.x, v.y), h23 = bfpair(v.z, v.w);
            unsigned l01 = bfpair(v.x - bflo(h01), v.y - bfhi(h01));
            unsigned l23 = bfpair(v.z - bflo(h23), v.w - bfhi(h23));
            *(u64*)(Ah + r * 36 + c4 * 2) = (u64)h01 | ((u64)h23 << 32);
            *(u64*)(Al + r * 36 + c4 * 2) = (u64)l01 | ((u64)l23 << 32);
        }
#pragma unroll
        for (int it = 0; it < 8; it++) {
            int u2 = tid + 256 * it;
            int n = u2 >> 4, c2 = u2 & 15;
            uint2 sh = *(const uint2*)(Whp + (j0 + n) * 64 + kc * 32 + c2 * 2);
            uint2 sl = *(const uint2*)(Wlp + (j0 + n) * 64 + kc * 32 + c2 * 2);
            *(u64*)(Wh + n * 36 + c2 * 2) = (u64)sh.x | ((u64)sh.y << 32);
            *(u64*)(Wl + n * 36 + c2 * 2) = (u64)sl.x | ((u64)sl.y << 32);
        }
        __syncthreads();

#pragma unroll
        for (int ks = 0; ks < 4; ks++) {
            int kk = ks * 8;
            unsigned ah[4][4], al[4][4], bh[4][2], bl[4][2];
#pragma unroll
            for (int mt = 0; mt < 4; mt++) {
                const unsigned* ap = Ah + (m0w + 16 * mt + gid) * 36 + kk + tig;
                const unsigned* lp = Al + (m0w + 16 * mt + gid) * 36 + kk + tig;
                ah[mt][0] = ap[0];
                ah[mt][1] = ap[8 * 36];
                ah[mt][2] = ap[4];
                ah[mt][3] = ap[8 * 36 + 4];
                al[mt][0] = lp[0];
                al[mt][1] = lp[8 * 36];
                al[mt][2] = lp[4];
                al[mt][3] = lp[8 * 36 + 4];
            }
#pragma unroll
            for (int nt = 0; nt < 4; nt++) {
                const unsigned* bp = Wh + (n0w + 8 * nt + gid) * 36 + kk + tig;
                const unsigned* lp = Wl + (n0w + 8 * nt + gid) * 36 + kk + tig;
                bh[nt][0] = bp[0];
                bh[nt][1] = bp[4];
                bl[nt][0] = lp[0];
                bl[nt][1] = lp[4];
            }
#pragma unroll
            for (int mt = 0; mt < 4; mt++)
#pragma unroll
                for (int nt = 0; nt < 4; nt++) {
                    MMA_BF16(C[mt][nt], ah[mt], bh[nt]);
                    MMA_BF16(C[mt][nt], ah[mt], bl[nt]);
                    MMA_BF16(C[mt][nt], al[mt], bh[nt]);
                }
        }
        __syncthreads();
    }

#pragma unroll
    for (int mt = 0; mt < 4; mt++) {
        int mrow = n0 + m0w + 16 * mt + gid;
        int bgrp = (mrow >> bshift) * K;
        int bgrp2 = ((mrow + 8) >> bshift) * K;
#pragma unroll
        for (int nt = 0; nt < 4; nt++) {
            int col = j0 + n0w + 8 * nt + 2 * tig;
            float v0 = C[mt][nt][0] + bias[bgrp + col];
            float v1 = C[mt][nt][1] + bias[bgrp + col + 1];
            float v2 = C[mt][nt][2] + bias[bgrp2 + col];
            float v3 = C[mt][nt][3] + bias[bgrp2 + col + 1];
            if (relu) {
                v0 = fmaxf(v0, 0.f); v1 = fmaxf(v1, 0.f);
                v2 = fmaxf(v2, 0.f); v3 = fmaxf(v3, 0.f);
                *(float2*)(out + mrow * K + col) = make_float2(v0, v1);
                *(float2*)(out + (mrow + 8) * K + col) = make_float2(v2, v3);
            } else {
                *(__half2*)(outH + mrow * K + col) = __floats2half2_rn(v0, v1);
                *(__half2*)(outH + (mrow + 8) * K + col) = __floats2half2_rn(v2, v3);
            }
        }
    }
}

// ---------------- monitor GRU recurrence on tensor cores (3xBF16), 512 threads ----------------
// Per CTA: 16 seqs; per step gates[16][384] = h[16][128] @ Whh^T via m16n8k16.
// 16 warps, 24 n-cols each (3 n-tiles). Whh-hi in smem; Whh-lo fragments in registers.
// Gate phase processes d-pairs and emits next-step Ah/Al directly (2 barriers/step).
#define RSM_BYTES 146176
__global__ __launch_bounds__(512, 1) void k_rec_mma(const float* __restrict__ bhh_all) {
    extern __shared__ unsigned smu[];
    unsigned* Bh = smu;                    // [384][68] u32
    unsigned* Ah = smu + 26112;            // [16][68]
    unsigned* Al = Ah + 1088;              // [16][68]
    float* hs = (float*)(smu + 28288);     // [16][128]
    float* gsm = hs + 2048;                // [16][388]
    int tid = threadIdx.x, bx = blockIdx.x;
    int chan = bx >> 4, sgrp = bx & 15;
    int p = chan >> 2, tt = chan & 3, g = (tt == 0) ? p : (tt + 1);
    const float* bhh = bhh_all + g * 384;
    const __half* gip = &g_gi[chan][0][0];
    float* outp = &g_seq[chan][0][0];
    int s0 = sgrp * 16;

    for (int i = tid; i < 24576; i += 512) Bh[(i >> 6) * 68 + (i & 63)] = g_hhh[g * 24576 + i];
    for (int i = tid; i < 2048; i += 512) hs[i] = 0.f;
    for (int i = tid; i < 1088; i += 512) { Ah[i] = 0u; Al[i] = 0u; }

    int lane = tid & 31, wid = tid >> 5;
    int gid = lane >> 2, tig = lane & 3;
    int n0w = wid * 24;   // 16 warps x 24 cols = 384

    unsigned blr[3][8][2];
#pragma unroll
    for (int nt = 0; nt < 3; nt++) {
        int col = n0w + 8 * nt + gid;
#pragma unroll
        for (int kk = 0; kk < 8; kk++) {
            blr[nt][kk][0] = g_hhl[g * 24576 + col * 64 + kk * 8 + tig];
            blr[nt][kk][1] = g_hhl[g * 24576 + col * 64 + kk * 8 + tig + 4];
        }
    }
    float bia[3][2];
#pragma unroll
    for (int nt = 0; nt < 3; nt++) {
        bia[nt][0] = bhh[n0w + 8 * nt + 2 * tig];
        bia[nt][1] = bhh[n0w + 8 * nt + 2 * tig + 1];
    }
    __syncthreads();

    for (int t = 0; t < 32; t++) {
        // prefetch gi (gmem, fp16 pairs) for the gate phase: 1024 pairs = 2 x 512
        __half2 pr2[2], pz2[2], pn2[2];
#pragma unroll
        for (int k = 0; k < 2; k++) {
            int idx2 = tid + k * 512;
            int s = idx2 >> 6, k2 = idx2 & 63;
            const __half2* grow = (const __half2*)(gip + ((s0 + s) * 32 + t) * 384);
            pr2[k] = grow[k2]; pz2[k] = grow[64 + k2]; pn2[k] = grow[128 + k2];
        }
        // MMA: gates = h @ Whh^T (Ah/Al produced by previous gate phase)
        float C[3][4];
#pragma unroll
        for (int nt = 0; nt < 3; nt++)
#pragma unroll
            for (int q = 0; q < 4; q++) C[nt][q] = 0.f;
#pragma unroll
        for (int kk = 0; kk < 8; kk++) {
            unsigned ah[4], al[4];
            ah[0] = Ah[gid * 68 + kk * 8 + tig];
            ah[1] = Ah[(gid + 8) * 68 + kk * 8 + tig];
            ah[2] = Ah[gid * 68 + kk * 8 + tig + 4];
            ah[3] = Ah[(gid + 8) * 68 + kk * 8 + tig + 4];
            al[0] = Al[gid * 68 + kk * 8 + tig];
            al[1] = Al[(gid + 8) * 68 + kk * 8 + tig];
            al[2] = Al[gid * 68 + kk * 8 + tig + 4];
            al[3] = Al[(gid + 8) * 68 + kk * 8 + tig + 4];
#pragma unroll
            for (int nt = 0; nt < 3; nt++) {
                unsigned bh[2];
                int col = n0w + 8 * nt + gid;
                bh[0] = Bh[col * 68 + kk * 8 + tig];
                bh[1] = Bh[col * 68 + kk * 8 + tig + 4];
                MMA_BF16(C[nt], ah, bh);
                MMA_BF16(C[nt], al, bh);
                MMA_BF16(C[nt], ah, blr[nt][kk]);
            }
        }
        // store gate pre-activations (+bhh)
#pragma unroll
        for (int nt = 0; nt < 3; nt++) {
            int col = n0w + 8 * nt + 2 * tig;
            *(float2*)(gsm + gid * 388 + col) = make_float2(C[nt][0] + bia[nt][0], C[nt][1] + bia[nt][1]);
            *(float2*)(gsm + (gid + 8) * 388 + col) = make_float2(C[nt][2] + bia[nt][0], C[nt][3] + bia[nt][1]);
        }
        __syncthreads();
        // gate update on d-pairs; writes hs + next-step Ah/Al
#pragma unroll
        for (int k = 0; k < 2; k++) {
            int idx2 = tid + k * 512;
            int s = idx2 >> 6, k2 = idx2 & 63;
            int d0 = 2 * k2;
            float2 gr = *(float2*)(gsm + s * 388 + d0);
            float2 gz = *(float2*)(gsm + s * 388 + 128 + d0);
            float2 gn = *(float2*)(gsm + s * 388 + 256 + d0);
            float2 pr = __half22float2(pr2[k]);
            float2 pz = __half22float2(pz2[k]);
            float2 pn = __half22float2(pn2[k]);
            float rg0 = sigm_(pr.x + gr.x), rg1 = sigm_(pr.y + gr.y);
            float zg0 = sigm_(pz.x + gz.x), zg1 = sigm_(pz.y + gz.y);
            float nn0 = tanh_fast(fmaf(rg0, gn.x, pn.x));
            float nn1 = tanh_fast(fmaf(rg1, gn.y, pn.y));
            float2 ho = *(float2*)(hs + s * 128 + d0);
            float h0 = (1.f - zg0) * nn0 + zg0 * ho.x;
            float h1 = (1.f - zg1) * nn1 + zg1 * ho.y;
            *(float2*)(hs + s * 128 + d0) = make_float2(h0, h1);
            unsigned hh = bfpair(h0, h1);
            Ah[s * 68 + k2] = hh;
            Al[s * 68 + k2] = bfpair(h0 - bflo(hh), h1 - bfhi(hh));
        }
        __syncthreads();
    }
    for (int idx = tid; idx < 2048; idx += 512) {
        int s = idx >> 7, d = idx & 127;
        outp[(s0 + s) * 128 + d] = hs[idx];
    }
}

// ---------------- visit GRU recurrence (scalar path, small) ----------------
template <int NSEQ, int T>
__global__ __launch_bounds__(384, 1) void k_rec(const float* __restrict__ Whh_all,
                                                const float* __restrict__ bhh_all) {
    extern __shared__ float sm[];
    float* wsf = sm;                     // 49280 floats
    float* hs = sm + 49280;              // [NSEQ][128]
    float* gsm = hs + NSEQ * 128;        // [NSEQ][384]
    const u64* ws2 = (const u64*)sm;
    int tid = threadIdx.x, bx = blockIdx.x;

    int run = bx >> 2, sgrp = bx & 3;
    int vi = (run < 8) ? (run >> 2) : (run - 6);
    const float* Whh = Whh_all + vi * 49152;
    const float* bhh = bhh_all + vi * 384;
    const __half* gip = &g_vgi[run][0][0];
    float* outp = &g_hbuf[run][0][0];
    int s0 = sgrp * NSEQ;

    for (int i = tid; i < 49152; i += 384) {
        int j = i >> 7, d = i & 127;
        wsf[(d >> 1) * 770 + 2 * j + (d & 1)] = Whh[i];
    }
    for (int i = tid; i < NSEQ * 128; i += 384) hs[i] = 0.f;
    __syncthreads();

    int j = tid;
    float bj = bhh[j];
    constexpr int KP = (NSEQ * 128 + 383) / 384;

    for (int t = 0; t < T; t++) {
        float pr[KP], pz[KP], pn[KP];
#pragma unroll
        for (int k = 0; k < KP; k++) {
            int idx = tid + k * 384;
            if (idx < NSEQ * 128) {
                int s = idx >> 7, d = idx & 127;
                const __half* gr = gip + ((s0 + s) * T + t) * 384;
                pr[k] = __half2float(gr[d]);
                pz[k] = __half2float(gr[128 + d]);
                pn[k] = __half2float(gr[256 + d]);
            }
        }
        u64 acc[NSEQ];
#pragma unroll
        for (int s = 0; s < NSEQ; s++) acc[s] = 0ull;
#pragma unroll 2
        for (int d4 = 0; d4 < 32; d4++) {
            u64 wA = ws2[(2 * d4) * 385 + j];
            u64 wB = ws2[(2 * d4 + 1) * 385 + j];
#pragma unroll
            for (int s = 0; s < NSEQ; s++) {
                double2 hd = ((const double2*)(hs + s * 128))[d4];
                fma2(acc[s], __double_as_longlong(hd.x), wA);
                fma2(acc[s], __double_as_longlong(hd.y), wB);
            }
        }
#pragma unroll
        for (int s = 0; s < NSEQ; s++) gsm[s * 384 + j] = sum2(acc[s]) + bj;
        __syncthreads();
#pragma unroll
        for (int k = 0; k < KP; k++) {
            int idx = tid + k * 384;
            if (idx < NSEQ * 128) {
                int s = idx >> 7, d = idx & 127;
                float rg = sigm_(pr[k] + gsm[s * 384 + d]);
                float zg = sigm_(pz[k] + gsm[s * 384 + 128 + d]);
                float nn = tanh_fast(fmaf(rg, gsm[s * 384 + 256 + d], pn[k]));
                hs[idx] = (1.f - zg) * nn + zg * hs[idx];
            }
        }
        __syncthreads();
    }
    for (int idx = tid; idx < NSEQ * 128; idx += 384) {
        int s = idx >> 7, d = idx & 127;
        outp[(s0 + s) * 128 + d] = hs[idx];
    }
}

// ---------------- head: out = relu(pe) @ W.T + b ----------------
__global__ void k_head(const float* __restrict__ fW, const float* __restrict__ fb,
                       float* __restrict__ out) {
    __shared__ float pe[896];
    int b = blockIdx.x / 10, og0 = (blockIdx.x % 10) * 60;
    int tid = threadIdx.x, lane = tid & 31, wp = tid >> 5;
    const float* H = &g_hbuf[0][0][0];  // [10][16][128]
    for (int i = tid; i < 896; i += 256) {
        int slot = i >> 7, d = i & 127;
        float v;
        if (slot == 0) v = H[0 * 2048 + b * 128 + d];
        else if (slot == 1) v = H[1 * 2048 + b * 128 + d] + H[5 * 2048 + b * 128 + d];
        else if (slot == 2) v = H[2 * 2048 + b * 128 + d] + H[6 * 2048 + b * 128 + d];
        else if (slot == 3) v = H[3 * 2048 + b * 128 + d] + H[7 * 2048 + b * 128 + d];
        else if (slot == 4) v = H[4 * 2048 + b * 128 + d];
        else if (slot == 5) v = H[8 * 2048 + b * 128 + d];
        else v = H[9 * 2048 + b * 128 + d];
        pe[i] = fmaxf(v, 0.f);
    }
    __syncthreads();
    for (int oi = wp; oi < 60; oi += 8) {
        int o = og0 + oi;
        u64 acc = 0ull;
#pragma unroll
        for (int i = 0; i < 7; i++) {
            int k4 = lane + 32 * i;
            float4 wv = __ldg((const float4*)(fW + o * 896) + k4);
            float4 xv = ((const float4*)pe)[k4];
            u64 a01, a23, w01, w23;
            asm("mov.b64 %0, {%1, %2};" : "=l"(a01) : "f"(xv.x), "f"(xv.y));
            asm("mov.b64 %0, {%1, %2};" : "=l"(a23) : "f"(xv.z), "f"(xv.w));
            asm("mov.b64 %0, {%1, %2};" : "=l"(w01) : "f"(wv.x), "f"(wv.y));
            asm("mov.b64 %0, {%1, %2};" : "=l"(w23) : "f"(wv.z), "f"(wv.w));
            fma2(acc, a01, w01);
            fma2(acc, a23, w23);
        }
        float v = sum2(acc);
#pragma unroll
        for (int m = 16; m > 0; m >>= 1) v += __shfl_xor_sync(0xffffffffu, v, m);
        if (lane == 0) out[b * 600 + o] = v + fb[o];
    }
}

// ---------------- launch ----------------
extern "C" void kernel_launch(void* const* d_in, const int* in_sizes, int n_in,
                              void* d_out, int out_size) {
    const int* cc = (const int*)d_in[0];
    const int* cp = (const int*)d_in[1];
    const int* cd = (const int*)d_in[2];
    const int* cli = (const int*)d_in[3];
    const int* clv = (const int*)d_in[4];
    const int* cii = (const int*)d_in[5];
    const int* civ = (const int*)d_in[6];
    const float* wgt = (const float*)d_in[7];
    const float* age = (const float*)d_in[8];
    const float* ec = (const float*)d_in[9];
    const float* ep = (const float*)d_in[10];
    const float* ed = (const float*)d_in[11];
    const float* eli = (const float*)d_in[12];
    const float* elv = (const float*)d_in[13];
    const float* eii = (const float*)d_in[14];
    const float* eiv = (const float*)d_in[15];
    const float* mWih = (const float*)d_in[16];
    const float* mWhh = (const float*)d_in[17];
    const float* mbih = (const float*)d_in[18];
    const float* mbhh = (const float*)d_in[19];
    const float* vWih = (const float*)d_in[20];
    const float* vWhh = (const float*)d_in[21];
    const float* vbih = (const float*)d_in[22];
    const float* vbhh = (const float*)d_in[23];
    const float* gWs = (const float*)d_in[24];
    const float* gWm = (const float*)d_in[25];
    const float* fwW = (const float*)d_in[26];
    const float* fwb = (const float*)d_in[27];
    const float* faW = (const float*)d_in[28];
    const float* fab = (const float*)d_in[29];
    const float* fpW = (const float*)d_in[30];
    const float* fpb = (const float*)d_in[31];
    float* out = (float*)d_out;

    cudaFuncSetAttribute(k_gemm, cudaFuncAttributeMaxDynamicSharedMemorySize, GSM_BYTES);
    cudaFuncSetAttribute(k_rec_mma, cudaFuncAttributeMaxDynamicSharedMemorySize, RSM_BYTES);
    cudaFuncSetAttribute((const void*)k_rec<4, 16>, cudaFuncAttributeMaxDynamicSharedMemorySize, 205312);

    k_pre<<<20354, 128>>>(cc, cp, cd, ec, ep, ed, cli, clv, cii, civ, eli, elv, eii, eiv,
                          gWs, gWm, mWih, vWih, mWhh, wgt, age, fwW, fwb, faW, fab);
    k_bias<<<64, 128>>>(gWs, gWm);
    k_gemm<<<dim3(64, 4, 2), 256, GSM_BYTES>>>(1, mbih, vbih);
    k_gemm<<<dim3(64, 3, 8), 256, GSM_BYTES>>>(2, mbih, vbih);
    k_rec_mma<<<128, 512, RSM_BYTES>>>(mbhh);
    k_gemm<<<dim3(20, 3, 1), 256, GSM_BYTES>>>(3, mbih, vbih);
    k_rec<4, 16><<<40, 384, 205312>>>(vWhh, vbhh);
    k_head<<<160, 256>>>(fpW, fpb, out);
}